// round 8
// baseline (speedup 1.0000x reference)
#include <cuda_runtime.h>
#include <cuda_fp16.h>
#include <math.h>
#include <stdint.h>

#define B_ 4
#define T_ 1024
#define C_ 1024
#define H_ 16
#define D_ 64
#define M_ (B_*T_)      /* 4096 rows */
#define NQKV 3072
#define NFC  4096

// ---------------- scratch (__device__ globals: no allocation allowed) -------
__device__ float g_x2 [M_*C_];                 // masked residual after proj
__device__ float g_imp[M_];
__device__ float g_msk[M_];
// fp16 operand buffers
__device__ __half g_q16[M_*C_];                      // (B,H,T,D)
__device__ __half g_k16[M_*C_];
__device__ __half g_v16[M_*C_];
__device__ __half g_h16[M_*C_];                      // LN out
__device__ __half g_y16[M_*C_];                      // attn out (B,T,C)
__device__ __half g_f16[(size_t)M_*NFC];             // gelu activations
__device__ __half g_wat[C_*NQKV];                    // weights transposed [N][K]
__device__ __half g_wpr[C_*C_];
__device__ __half g_wfc[(size_t)C_*NFC];
__device__ __half g_wf2[(size_t)NFC*C_];

// ---------------- helpers ---------------------------------------------------
__device__ __forceinline__ void mma_f16(float c[4], const uint32_t a[4], const uint32_t b[2]) {
    asm volatile(
        "mma.sync.aligned.m16n8k16.row.col.f32.f16.f16.f32 "
        "{%0,%1,%2,%3}, {%4,%5,%6,%7}, {%8,%9}, {%0,%1,%2,%3};"
        : "+f"(c[0]), "+f"(c[1]), "+f"(c[2]), "+f"(c[3])
        : "r"(a[0]), "r"(a[1]), "r"(a[2]), "r"(a[3]), "r"(b[0]), "r"(b[1]));
}
__device__ __forceinline__ void cp16(void* dst_smem, const void* src) {
    uint32_t d = (uint32_t)__cvta_generic_to_shared(dst_smem);
    asm volatile("cp.async.cg.shared.global [%0], [%1], 16;" :: "r"(d), "l"(src));
}
__device__ __forceinline__ void cp_commit() { asm volatile("cp.async.commit_group;"); }
template<int N_>
__device__ __forceinline__ void cp_wait() { asm volatile("cp.async.wait_group %0;" :: "n"(N_)); }
__device__ __forceinline__ uint32_t smem_u32(const void* p) {
    return (uint32_t)__cvta_generic_to_shared(p);
}
__device__ __forceinline__ void ldmx2t(uint32_t& r0, uint32_t& r1, uint32_t addr) {
    asm volatile("ldmatrix.sync.aligned.m8n8.x2.trans.shared.b16 {%0,%1}, [%2];"
                 : "=r"(r0), "=r"(r1) : "r"(addr));
}

// ---------------- small kernels --------------------------------------------
__global__ void zero_kernel(float* p, int n) {
    int i = blockIdx.x * 256 + threadIdx.x;
    if (i < n) p[i] = 0.f;
}

__global__ void mask_kernel(const float* __restrict__ imp,
                            const float* __restrict__ am,
                            const float* __restrict__ thr,
                            float* __restrict__ gmask,
                            float* __restrict__ outmask,
                            float* __restrict__ outloss) {
    int i = blockIdx.x * 256 + threadIdx.x;
    if (i < M_) {
        float pm = (imp[i] >= thr[0]) ? 1.f : 0.f;
        float cm = am[i] * pm;
        gmask[i]   = cm;
        outmask[i] = cm;
    }
    if (i == 0) outloss[0] = 0.f;
}

// ---------------- weight transpose -> fp16 [N][K] ---------------------------
__global__ void __launch_bounds__(256) wsplit_kernel(const float* __restrict__ W,
                                                     __half* __restrict__ Oh,
                                                     int K, int N) {
    __shared__ float tile[32][33];
    int n0 = blockIdx.x * 32, k0 = blockIdx.y * 32;
    int tx = threadIdx.x & 31, ty = threadIdx.x >> 5;   // 32 x 8
    #pragma unroll
    for (int i = 0; i < 4; i++)
        tile[ty + i * 8][tx] = W[(size_t)(k0 + ty + i * 8) * N + n0 + tx];
    __syncthreads();
    #pragma unroll
    for (int i = 0; i < 4; i++) {
        int n = n0 + ty + i * 8;
        Oh[(size_t)n * K + k0 + tx] = __float2half_rn(tile[tx][ty + i * 8]);
    }
}

// ---------------- layer norm -> fp16 ----------------------------------------
__global__ void __launch_bounds__(256) ln_kernel(const float* __restrict__ x,
                                                 const float* __restrict__ w,
                                                 const float* __restrict__ b,
                                                 __half* __restrict__ oh) {
    int row = blockIdx.x;
    int tid = threadIdx.x;
    __shared__ float buf[C_];
    __shared__ float red[8];
    const float* xr = x + (size_t)row * C_;
    float s = 0.f;
    #pragma unroll
    for (int j = tid; j < C_; j += 256) { float v = xr[j]; buf[j] = v; s += v; }
    #pragma unroll
    for (int o = 16; o; o >>= 1) s += __shfl_down_sync(~0u, s, o);
    if ((tid & 31) == 0) red[tid >> 5] = s;
    __syncthreads();
    if (tid < 8) {
        s = red[tid];
        #pragma unroll
        for (int o = 4; o; o >>= 1) s += __shfl_down_sync(0xff, s, o);
        if (tid == 0) red[0] = s;
    }
    __syncthreads();
    float mu = red[0] * (1.f / C_);
    __syncthreads();
    float ss = 0.f;
    #pragma unroll
    for (int j = tid; j < C_; j += 256) { float d = buf[j] - mu; ss += d * d; }
    #pragma unroll
    for (int o = 16; o; o >>= 1) ss += __shfl_down_sync(~0u, ss, o);
    if ((tid & 31) == 0) red[tid >> 5] = ss;
    __syncthreads();
    if (tid < 8) {
        ss = red[tid];
        #pragma unroll
        for (int o = 4; o; o >>= 1) ss += __shfl_down_sync(0xff, ss, o);
        if (tid == 0) red[0] = ss;
    }
    __syncthreads();
    float rstd = rsqrtf(red[0] * (1.f / C_) + 1e-5f);
    #pragma unroll
    for (int j = tid; j < C_; j += 256)
        oh[(size_t)row * C_ + j] = __float2half_rn((buf[j] - mu) * rstd * w[j] + b[j]);
}

// ---------------- fp16 GEMM: 128x128x32-per-stage, cp.async 4-stage ---------
#define STG  4
#define GEMM_SMEM (STG*2*5120*4)      /* 4 stages x (A+B) x 2560 u32 = 81920 B */

template<int EPI>
__global__ void __launch_bounds__(256, 2) tgemm_kernel(
    const __half* __restrict__ A, const __half* __restrict__ W,
    const float* __restrict__ bias, const float* __restrict__ res,
    const float* __restrict__ mask, float* __restrict__ Cout,
    int M, int N, int K)
{
    extern __shared__ uint32_t smu[];
    int tid  = threadIdx.x;
    int lane = tid & 31;
    int wid  = tid >> 5;
    int warpM = wid >> 2, warpN = wid & 3;
    int g  = lane >> 2, tg = lane & 3;
    int row0 = blockIdx.y * 128, col0 = blockIdx.x * 128;

    int r0s = tid >> 2, c0s = tid & 3;
    int r1s = r0s + 64;

    float acc[4][4][4] = {};
    int nk = K >> 5;

    auto load_stage = [&](int s, int buf) {
        uint32_t* Ad = smu + buf * 2 * 2560;
        uint32_t* Bd = Ad + 2560;
        size_t kb = (size_t)s * 32;
        const __half* Ag = A + (size_t)row0 * K + kb;
        const __half* Bg = W + (size_t)col0 * K + kb;
        cp16(Ad + r0s * 20 + c0s * 4, Ag + (size_t)r0s * K + c0s * 8);
        cp16(Ad + r1s * 20 + c0s * 4, Ag + (size_t)r1s * K + c0s * 8);
        cp16(Bd + r0s * 20 + c0s * 4, Bg + (size_t)r0s * K + c0s * 8);
        cp16(Bd + r1s * 20 + c0s * 4, Bg + (size_t)r1s * K + c0s * 8);
    };

    #pragma unroll
    for (int p = 0; p < STG - 1; p++) { load_stage(p, p); cp_commit(); }

    int mBase = warpM * 64;
    int nBase = warpN * 32;

    for (int kt = 0; kt < nk; kt++) {
        cp_wait<STG - 2>();
        __syncthreads();
        if (kt + STG - 1 < nk) load_stage(kt + STG - 1, (kt + STG - 1) & (STG - 1));
        cp_commit();

        int st = kt & (STG - 1);
        const uint32_t* Ast = smu + st * 2 * 2560;
        const uint32_t* Bst = Ast + 2560;
        #pragma unroll
        for (int kk2 = 0; kk2 < 2; kk2++) {
            int ko = kk2 * 8;
            uint32_t a[4][4], b[4][2];
            #pragma unroll
            for (int mi = 0; mi < 4; mi++) {
                int m = mBase + mi * 16 + g;
                a[mi][0] = Ast[(m    ) * 20 + ko + tg    ];
                a[mi][1] = Ast[(m + 8) * 20 + ko + tg    ];
                a[mi][2] = Ast[(m    ) * 20 + ko + tg + 4];
                a[mi][3] = Ast[(m + 8) * 20 + ko + tg + 4];
            }
            #pragma unroll
            for (int ni = 0; ni < 4; ni++) {
                int n = nBase + ni * 8 + g;
                b[ni][0] = Bst[n * 20 + ko + tg    ];
                b[ni][1] = Bst[n * 20 + ko + tg + 4];
            }
            #pragma unroll
            for (int mi = 0; mi < 4; mi++)
                #pragma unroll
                for (int ni = 0; ni < 4; ni++)
                    mma_f16(acc[mi][ni], a[mi], b[ni]);
        }
    }

    // ---- epilogue ----
    #pragma unroll
    for (int mi = 0; mi < 4; mi++) {
        #pragma unroll
        for (int half = 0; half < 2; half++) {
            int ig = row0 + mBase + mi * 16 + g + half * 8;
            #pragma unroll
            for (int ni = 0; ni < 4; ni++) {
                float v0 = acc[mi][ni][2 * half + 0];
                float v1 = acc[mi][ni][2 * half + 1];
                int jg = col0 + nBase + ni * 8 + tg * 2;
                if (EPI == 0) {        // QKV scatter -> fp16 q/k/v (B,H,T,D)
                    int bq = ig >> 10, t = ig & 1023;
                    int part = jg >> 10;
                    int c = jg & 1023;
                    int h = c >> 6, d = c & 63;
                    __half2 hv;
                    hv.x = __float2half_rn(v0 + bias[jg]);
                    hv.y = __float2half_rn(v1 + bias[jg + 1]);
                    __half* dst = (part == 0) ? g_q16 : (part == 1) ? g_k16 : g_v16;
                    *(__half2*)&dst[((size_t)(bq * H_ + h) * T_ + t) * D_ + d] = hv;
                } else if (EPI == 1) { // proj: (x + y@W + b) * mask[row]
                    float mrow = mask[ig];
                    Cout[(size_t)ig * N + jg]     = (res[(size_t)ig * N + jg]     + v0 + bias[jg])     * mrow;
                    Cout[(size_t)ig * N + jg + 1] = (res[(size_t)ig * N + jg + 1] + v1 + bias[jg + 1]) * mrow;
                } else if (EPI == 2) { // exact GELU -> fp16 activations
                    float a0 = v0 + bias[jg], a1 = v1 + bias[jg + 1];
                    float g0 = 0.5f * a0 * (1.f + erff(a0 * 0.70710678118654752f));
                    float g1 = 0.5f * a1 * (1.f + erff(a1 * 0.70710678118654752f));
                    __half2 hv; hv.x = __float2half_rn(g0); hv.y = __float2half_rn(g1);
                    *(__half2*)&g_f16[(size_t)ig * N + jg] = hv;
                } else {               // residual
                    Cout[(size_t)ig * N + jg]     = res[(size_t)ig * N + jg]     + v0 + bias[jg];
                    Cout[(size_t)ig * N + jg + 1] = res[(size_t)ig * N + jg + 1] + v1 + bias[jg + 1];
                }
            }
        }
    }
}

// ======================= FUSED FLASH ATTENTION (fp16) =======================
// One block = 32 query rows of one (b,h), 512 threads (16 warps).
// Phase 1: fp16 mma Q@K^T -> fp32 logit strip S.
// Phase 2: exact softmax; probs register-staged then stored as fp16 overlaid
//          in S (row mapping makes overwrites touch only consumed fp32 rows).
// Phase 3: fp16 mma S@V, V B-fragments via ldmatrix.trans.
#define QT 32
#define SSTR 1028                 /* fp32 logit row stride (floats) */
#define SHSTR 516                 /* half prob row stride in u32 (=1032 halves) */
#define QSTR 36                   /* u32 per Q row (72 halves) */
#define KVSTR 36                  /* u32 per K/V row (72 halves) */
#define SM_S    0
#define SM_Q    (QT*SSTR)                     /* floats */
#define SM_KV   (SM_Q + QT*QSTR)
#define SM_AM   (SM_KV + 128*KVSTR)
#define SM_TOTF (SM_AM + 1024)
#define FA_SMEM (SM_TOTF * 4)                 /* 158720 B */

__global__ void __launch_bounds__(512, 1) fattn_kernel(
    const __half* __restrict__ q, const __half* __restrict__ k,
    const __half* __restrict__ v, const float* __restrict__ am,
    __half* __restrict__ y16, float* __restrict__ imp)
{
    extern __shared__ float sm[];
    float*    S   = sm + SM_S;
    uint32_t* Shw = (uint32_t*)sm;            // half prob overlay (u32 view)
    __half*   Shh = (__half*)sm;
    uint32_t* Qs  = (uint32_t*)(sm + SM_Q);
    uint32_t* KVs = (uint32_t*)(sm + SM_KV);
    float*    amS = sm + SM_AM;

    int qt = gridDim.x - 1 - blockIdx.x;
    int bh = blockIdx.y;
    int b  = bh >> 4, h = bh & 15;
    int tid  = threadIdx.x;
    int lane = tid & 31;
    int wid  = tid >> 5;
    int g = lane >> 2, tg = lane & 3;

    int q0   = qt * QT;
    int kend = q0 + QT;
    int jmax = ((kend + 63) >> 6) << 6;

    const __half* qb = q + (size_t)bh * T_ * D_;
    const __half* kb = k + (size_t)bh * T_ * D_;
    const __half* vb = v + (size_t)bh * T_ * D_;

    // ---- load Q tile (32x64 half) + key mask ----
    if (tid < 256) {
        int row = tid >> 3, cs = tid & 7;
        uint4 val = *(const uint4*)(qb + (size_t)(q0 + row) * D_ + cs * 8);
        *(uint4*)&Qs[row * QSTR + cs * 4] = val;
    }
    for (int j = tid; j < T_; j += 512) amS[j] = am[b * T_ + j];
    __syncthreads();

    int warpRow = wid >> 3;        // 0/1
    int warpCol = wid & 7;         // 0..7
    int m0 = warpRow * 16;

    // register Q fragments: 4 ksteps(16) x 4 u32
    uint32_t aq[4][4];
    #pragma unroll
    for (int ks = 0; ks < 4; ks++) {
        aq[ks][0] = Qs[(m0 + g    ) * QSTR + ks * 8 + tg    ];
        aq[ks][1] = Qs[(m0 + g + 8) * QSTR + ks * 8 + tg    ];
        aq[ks][2] = Qs[(m0 + g    ) * QSTR + ks * 8 + 4 + tg];
        aq[ks][3] = Qs[(m0 + g + 8) * QSTR + ks * 8 + 4 + tg];
    }

    // ---- phase 1: logits ----
    for (int kc0 = 0; kc0 < jmax; kc0 += 128) {
        int rows_here = min(128, jmax - kc0);
        __syncthreads();
        for (int idx = tid; idx < rows_here * 8; idx += 512) {
            int r = idx >> 3, cs = idx & 7;
            uint4 val = *(const uint4*)(kb + (size_t)(kc0 + r) * D_ + cs * 8);
            *(uint4*)&KVs[r * KVSTR + cs * 4] = val;
        }
        __syncthreads();
        if (warpCol * 16 < rows_here) {
            float acc[2][4] = {};
            #pragma unroll
            for (int ks = 0; ks < 4; ks++) {
                #pragma unroll
                for (int f = 0; f < 2; f++) {
                    int n = warpCol * 16 + f * 8 + g;
                    uint32_t bb[2];
                    bb[0] = KVs[n * KVSTR + ks * 8 + tg    ];
                    bb[1] = KVs[n * KVSTR + ks * 8 + 4 + tg];
                    mma_f16(acc[f], aq[ks], bb);
                }
            }
            #pragma unroll
            for (int f = 0; f < 2; f++) {
                int n0 = kc0 + warpCol * 16 + f * 8 + tg * 2;
                int r0 = m0 + g;
                S[r0 * SSTR + n0]           = acc[f][0] * 0.125f;
                S[r0 * SSTR + n0 + 1]       = acc[f][1] * 0.125f;
                S[(r0 + 8) * SSTR + n0]     = acc[f][2] * 0.125f;
                S[(r0 + 8) * SSTR + n0 + 1] = acc[f][3] * 0.125f;
            }
        }
    }
    __syncthreads();

    // ---- phase 2: softmax; half probs overlaid into S ----
    // r2=0 -> rows 0..15 (half rows clobber only fp32 rows 0..8, already read)
    // r2=1 -> rows 16..31 (clobber fp32 rows 8..16, already consumed)
    #pragma unroll
    for (int r2 = 0; r2 < 2; r2++) {
        int row = wid + r2 * 16;
        int qg  = q0 + row;
        const float* srow = S + row * SSTR;
        float lm = -1e30f;
        for (int j = lane; j <= qg; j += 32)
            if (amS[j] != 0.f) lm = fmaxf(lm, srow[j]);
        #pragma unroll
        for (int o = 16; o; o >>= 1) lm = fmaxf(lm, __shfl_xor_sync(~0u, lm, o));
        float er[32];
        float ls = 0.f;
        #pragma unroll
        for (int i = 0; i < 32; i++) {
            int j = lane + 32 * i;
            bool valid = (j <= qg) && (amS[j] != 0.f);
            float e = valid ? __expf(srow[j] - lm) : 0.f;
            er[i] = e;
            ls += e;
        }
        #pragma unroll
        for (int o = 16; o; o >>= 1) ls += __shfl_xor_sync(~0u, ls, o);
        float inv = 1.f / ls;
        __syncthreads();             // all fp32 reads for this r2-group done
        #pragma unroll
        for (int i = 0; i < 32; i++) {
            int j = lane + 32 * i;
            if (j < jmax)
                Shh[row * (2 * SHSTR) + j] = __float2half_rn(er[i] * inv);
        }
    }
    __syncthreads();

    // ---- phase 2b: column sums -> importance atomics (2 cols per thread) ---
    if (2 * tid < kend) {
        float cs0 = 0.f, cs1 = 0.f;
        #pragma unroll
        for (int r = 0; r < QT; r++) {
            uint32_t pw = Shw[r * SHSTR + tid];
            __half2 ph = *(__half2*)&pw;
            cs0 += __half2float(ph.x);
            cs1 += __half2float(ph.y);
        }
        atomicAdd(&imp[b * T_ + 2 * tid],     cs0 * (1.f / (H_ * T_)));
        atomicAdd(&imp[b * T_ + 2 * tid + 1], cs1 * (1.f / (H_ * T_)));
    }

    // ---- phase 3: y = P @ V ----
    int col0 = warpCol * 8;            // output cols (halves)
    uint32_t kvbase = smem_u32(KVs);
    float acc[4] = {};
    for (int kc0 = 0; kc0 < jmax; kc0 += 128) {
        int rows_here = min(128, jmax - kc0);
        __syncthreads();
        for (int idx = tid; idx < rows_here * 8; idx += 512) {
            int r = idx >> 3, cs = idx & 7;
            uint4 val = *(const uint4*)(vb + (size_t)(kc0 + r) * D_ + cs * 8);
            *(uint4*)&KVs[r * KVSTR + cs * 4] = val;
        }
        __syncthreads();
        int ksteps = rows_here >> 4;
        for (int ks = 0; ks < ksteps; ks++) {
            int jc = kc0 + ks * 16;            // in halves
            uint32_t a[4], bb[2];
            a[0] = Shw[(m0 + g    ) * SHSTR + (jc >> 1) + tg    ];
            a[1] = Shw[(m0 + g + 8) * SHSTR + (jc >> 1) + tg    ];
            a[2] = Shw[(m0 + g    ) * SHSTR + (jc >> 1) + 4 + tg];
            a[3] = Shw[(m0 + g + 8) * SHSTR + (jc >> 1) + 4 + tg];
            uint32_t addr = kvbase + ((ks * 16 + (lane & 15)) * 72 + col0) * 2;
            ldmx2t(bb[0], bb[1], addr);
            mma_f16(acc, a, bb);
        }
    }
    #pragma unroll
    for (int half = 0; half < 2; half++) {
        int t = q0 + m0 + g + half * 8;
        int d = h * 64 + col0 + tg * 2;
        __half2 hv;
        hv.x = __float2half_rn(acc[2 * half]);
        hv.y = __float2half_rn(acc[2 * half + 1]);
        *(__half2*)&y16[(size_t)(b * T_ + t) * C_ + d] = hv;
    }
}

// ---------------- launch ----------------------------------------------------
extern "C" void kernel_launch(void* const* d_in, const int* in_sizes, int n_in,
                              void* d_out, int out_size) {
    const float* x     = (const float*)d_in[0];
    const float* am    = (const float*)d_in[1];
    const float* ln1w  = (const float*)d_in[2];
    const float* ln1b  = (const float*)d_in[3];
    const float* wattn = (const float*)d_in[4];
    const float* battn = (const float*)d_in[5];
    const float* wproj = (const float*)d_in[6];
    const float* bproj = (const float*)d_in[7];
    const float* thr   = (const float*)d_in[8];
    const float* ln2w  = (const float*)d_in[9];
    const float* ln2b  = (const float*)d_in[10];
    const float* wfc   = (const float*)d_in[11];
    const float* bfc   = (const float*)d_in[12];
    const float* wfc2  = (const float*)d_in[13];
    const float* bfc2  = (const float*)d_in[14];

    float* out      = (float*)d_out;
    float* out_x    = out;
    float* out_mask = out + out_size - 1 - M_;
    float* out_loss = out + out_size - 1;

    float *px2, *pimp, *pmsk;
    cudaGetSymbolAddress((void**)&px2,  g_x2);
    cudaGetSymbolAddress((void**)&pimp, g_imp);
    cudaGetSymbolAddress((void**)&pmsk, g_msk);
    __half *pq16, *pk16, *pv16, *ph16, *py16, *pf16, *pwat, *pwpr, *pwfc, *pwf2;
    cudaGetSymbolAddress((void**)&pq16, g_q16);
    cudaGetSymbolAddress((void**)&pk16, g_k16);
    cudaGetSymbolAddress((void**)&pv16, g_v16);
    cudaGetSymbolAddress((void**)&ph16, g_h16);
    cudaGetSymbolAddress((void**)&py16, g_y16);
    cudaGetSymbolAddress((void**)&pf16, g_f16);
    cudaGetSymbolAddress((void**)&pwat, g_wat);
    cudaGetSymbolAddress((void**)&pwpr, g_wpr);
    cudaGetSymbolAddress((void**)&pwfc, g_wfc);
    cudaGetSymbolAddress((void**)&pwf2, g_wf2);

    static int smem_set = 0;
    if (!smem_set) {
        cudaFuncSetAttribute(fattn_kernel,
                             cudaFuncAttributeMaxDynamicSharedMemorySize, FA_SMEM);
        cudaFuncSetAttribute(tgemm_kernel<0>,
                             cudaFuncAttributeMaxDynamicSharedMemorySize, GEMM_SMEM);
        cudaFuncSetAttribute(tgemm_kernel<1>,
                             cudaFuncAttributeMaxDynamicSharedMemorySize, GEMM_SMEM);
        cudaFuncSetAttribute(tgemm_kernel<2>,
                             cudaFuncAttributeMaxDynamicSharedMemorySize, GEMM_SMEM);
        cudaFuncSetAttribute(tgemm_kernel<3>,
                             cudaFuncAttributeMaxDynamicSharedMemorySize, GEMM_SMEM);
        smem_set = 1;
    }

    zero_kernel<<<16, 256>>>(pimp, M_);
    wsplit_kernel<<<dim3(NQKV/32, C_/32), 256>>>(wattn, pwat, C_, NQKV);
    wsplit_kernel<<<dim3(C_/32,   C_/32), 256>>>(wproj, pwpr, C_, C_);
    wsplit_kernel<<<dim3(NFC/32,  C_/32), 256>>>(wfc,   pwfc, C_, NFC);
    wsplit_kernel<<<dim3(C_/32,  NFC/32), 256>>>(wfc2,  pwf2, NFC, C_);

    ln_kernel<<<M_, 256>>>(x, ln1w, ln1b, ph16);
    tgemm_kernel<0><<<dim3(NQKV/128, M_/128), 256, GEMM_SMEM>>>(
        ph16, pwat, battn, nullptr, nullptr, nullptr, M_, NQKV, C_);
    fattn_kernel<<<dim3(T_/QT, B_*H_), 512, FA_SMEM>>>(pq16, pk16, pv16, am, py16, pimp);
    mask_kernel<<<16, 256>>>(pimp, am, thr, pmsk, out_mask, out_loss);
    tgemm_kernel<1><<<dim3(C_/128, M_/128), 256, GEMM_SMEM>>>(
        py16, pwpr, bproj, x, pmsk, px2, M_, C_, C_);
    ln_kernel<<<M_, 256>>>(px2, ln2w, ln2b, ph16);
    tgemm_kernel<2><<<dim3(NFC/128, M_/128), 256, GEMM_SMEM>>>(
        ph16, pwfc, bfc, nullptr, nullptr, nullptr, M_, NFC, C_);
    tgemm_kernel<3><<<dim3(C_/128, M_/128), 256, GEMM_SMEM>>>(
        pf16, pwf2, bfc2, px2, nullptr, out_x, M_, C_, NFC);
}

// round 9
// speedup vs baseline: 1.1055x; 1.1055x over previous
#include <cuda_runtime.h>
#include <cuda_fp16.h>
#include <math.h>
#include <stdint.h>

#define B_ 4
#define T_ 1024
#define C_ 1024
#define H_ 16
#define D_ 64
#define M_ (B_*T_)      /* 4096 rows */
#define NQKV 3072
#define NFC  4096

// ---------------- scratch (__device__ globals: no allocation allowed) -------
__device__ float g_x2 [M_*C_];                 // masked residual after proj
__device__ float g_imp[M_];
__device__ float g_msk[M_];
// fp16 operand buffers
__device__ __half g_q16[M_*C_];                      // (B,H,T,D)
__device__ __half g_k16[M_*C_];
__device__ __half g_v16[M_*C_];
__device__ __half g_h16[M_*C_];                      // LN out
__device__ __half g_y16[M_*C_];                      // attn out (B,T,C)
__device__ __half g_f16[(size_t)M_*NFC];             // gelu activations
__device__ __half g_wat[C_*NQKV];                    // weights transposed [N][K]
__device__ __half g_wpr[C_*C_];
__device__ __half g_wfc[(size_t)C_*NFC];
__device__ __half g_wf2[(size_t)NFC*C_];

// ---------------- helpers ---------------------------------------------------
__device__ __forceinline__ void mma_f16(float c[4], const uint32_t a[4], const uint32_t b[2]) {
    asm volatile(
        "mma.sync.aligned.m16n8k16.row.col.f32.f16.f16.f32 "
        "{%0,%1,%2,%3}, {%4,%5,%6,%7}, {%8,%9}, {%0,%1,%2,%3};"
        : "+f"(c[0]), "+f"(c[1]), "+f"(c[2]), "+f"(c[3])
        : "r"(a[0]), "r"(a[1]), "r"(a[2]), "r"(a[3]), "r"(b[0]), "r"(b[1]));
}
__device__ __forceinline__ void cp16(void* dst_smem, const void* src) {
    uint32_t d = (uint32_t)__cvta_generic_to_shared(dst_smem);
    asm volatile("cp.async.cg.shared.global [%0], [%1], 16;" :: "r"(d), "l"(src));
}
__device__ __forceinline__ void cp_commit() { asm volatile("cp.async.commit_group;"); }
template<int N_>
__device__ __forceinline__ void cp_wait() { asm volatile("cp.async.wait_group %0;" :: "n"(N_)); }
__device__ __forceinline__ uint32_t smem_u32(const void* p) {
    return (uint32_t)__cvta_generic_to_shared(p);
}
__device__ __forceinline__ void ldmx2t(uint32_t& r0, uint32_t& r1, uint32_t addr) {
    asm volatile("ldmatrix.sync.aligned.m8n8.x2.trans.shared.b16 {%0,%1}, [%2];"
                 : "=r"(r0), "=r"(r1) : "r"(addr));
}

// ---------------- small kernels --------------------------------------------
__global__ void zero_kernel(float* p, int n) {
    int i = blockIdx.x * 256 + threadIdx.x;
    if (i < n) p[i] = 0.f;
}

__global__ void mask_kernel(const float* __restrict__ imp,
                            const float* __restrict__ am,
                            const float* __restrict__ thr,
                            float* __restrict__ gmask,
                            float* __restrict__ outmask,
                            float* __restrict__ outloss) {
    int i = blockIdx.x * 256 + threadIdx.x;
    if (i < M_) {
        float pm = (imp[i] >= thr[0]) ? 1.f : 0.f;
        float cm = am[i] * pm;
        gmask[i]   = cm;
        outmask[i] = cm;
    }
    if (i == 0) outloss[0] = 0.f;
}

// ---------------- weight transpose -> fp16 [N][K] ---------------------------
__global__ void __launch_bounds__(256) wsplit_kernel(const float* __restrict__ W,
                                                     __half* __restrict__ Oh,
                                                     int K, int N) {
    __shared__ float tile[32][33];
    int n0 = blockIdx.x * 32, k0 = blockIdx.y * 32;
    int tx = threadIdx.x & 31, ty = threadIdx.x >> 5;   // 32 x 8
    #pragma unroll
    for (int i = 0; i < 4; i++)
        tile[ty + i * 8][tx] = W[(size_t)(k0 + ty + i * 8) * N + n0 + tx];
    __syncthreads();
    #pragma unroll
    for (int i = 0; i < 4; i++) {
        int n = n0 + ty + i * 8;
        Oh[(size_t)n * K + k0 + tx] = __float2half_rn(tile[tx][ty + i * 8]);
    }
}

// ---------------- layer norm -> fp16 ----------------------------------------
__global__ void __launch_bounds__(256) ln_kernel(const float* __restrict__ x,
                                                 const float* __restrict__ w,
                                                 const float* __restrict__ b,
                                                 __half* __restrict__ oh) {
    int row = blockIdx.x;
    int tid = threadIdx.x;
    __shared__ float buf[C_];
    __shared__ float red[8];
    const float* xr = x + (size_t)row * C_;
    float s = 0.f;
    #pragma unroll
    for (int j = tid; j < C_; j += 256) { float v = xr[j]; buf[j] = v; s += v; }
    #pragma unroll
    for (int o = 16; o; o >>= 1) s += __shfl_down_sync(~0u, s, o);
    if ((tid & 31) == 0) red[tid >> 5] = s;
    __syncthreads();
    if (tid < 8) {
        s = red[tid];
        #pragma unroll
        for (int o = 4; o; o >>= 1) s += __shfl_down_sync(0xff, s, o);
        if (tid == 0) red[0] = s;
    }
    __syncthreads();
    float mu = red[0] * (1.f / C_);
    __syncthreads();
    float ss = 0.f;
    #pragma unroll
    for (int j = tid; j < C_; j += 256) { float d = buf[j] - mu; ss += d * d; }
    #pragma unroll
    for (int o = 16; o; o >>= 1) ss += __shfl_down_sync(~0u, ss, o);
    if ((tid & 31) == 0) red[tid >> 5] = ss;
    __syncthreads();
    if (tid < 8) {
        ss = red[tid];
        #pragma unroll
        for (int o = 4; o; o >>= 1) ss += __shfl_down_sync(0xff, ss, o);
        if (tid == 0) red[0] = ss;
    }
    __syncthreads();
    float rstd = rsqrtf(red[0] * (1.f / C_) + 1e-5f);
    #pragma unroll
    for (int j = tid; j < C_; j += 256)
        oh[(size_t)row * C_ + j] = __float2half_rn((buf[j] - mu) * rstd * w[j] + b[j]);
}

// ---------------- fp16 GEMM: 128x128x32-per-stage, cp.async 4-stage ---------
#define STG  4
#define GEMM_SMEM (STG*2*5120*4)      /* 81920 B */

template<int EPI>
__global__ void __launch_bounds__(256, 2) tgemm_kernel(
    const __half* __restrict__ A, const __half* __restrict__ W,
    const float* __restrict__ bias, const float* __restrict__ res,
    const float* __restrict__ mask, float* __restrict__ Cout,
    int M, int N, int K)
{
    extern __shared__ uint32_t smu[];
    int tid  = threadIdx.x;
    int lane = tid & 31;
    int wid  = tid >> 5;
    int warpM = wid >> 2, warpN = wid & 3;
    int g  = lane >> 2, tg = lane & 3;
    int row0 = blockIdx.y * 128, col0 = blockIdx.x * 128;

    int r0s = tid >> 2, c0s = tid & 3;
    int r1s = r0s + 64;

    float acc[4][4][4] = {};
    int nk = K >> 5;

    auto load_stage = [&](int s, int buf) {
        uint32_t* Ad = smu + buf * 2 * 2560;
        uint32_t* Bd = Ad + 2560;
        size_t kb = (size_t)s * 32;
        const __half* Ag = A + (size_t)row0 * K + kb;
        const __half* Bg = W + (size_t)col0 * K + kb;
        cp16(Ad + r0s * 20 + c0s * 4, Ag + (size_t)r0s * K + c0s * 8);
        cp16(Ad + r1s * 20 + c0s * 4, Ag + (size_t)r1s * K + c0s * 8);
        cp16(Bd + r0s * 20 + c0s * 4, Bg + (size_t)r0s * K + c0s * 8);
        cp16(Bd + r1s * 20 + c0s * 4, Bg + (size_t)r1s * K + c0s * 8);
    };

    #pragma unroll
    for (int p = 0; p < STG - 1; p++) { load_stage(p, p); cp_commit(); }

    int mBase = warpM * 64;
    int nBase = warpN * 32;

    for (int kt = 0; kt < nk; kt++) {
        cp_wait<STG - 2>();
        __syncthreads();
        if (kt + STG - 1 < nk) load_stage(kt + STG - 1, (kt + STG - 1) & (STG - 1));
        cp_commit();

        int st = kt & (STG - 1);
        const uint32_t* Ast = smu + st * 2 * 2560;
        const uint32_t* Bst = Ast + 2560;
        #pragma unroll
        for (int kk2 = 0; kk2 < 2; kk2++) {
            int ko = kk2 * 8;
            uint32_t a[4][4], b[4][2];
            #pragma unroll
            for (int mi = 0; mi < 4; mi++) {
                int m = mBase + mi * 16 + g;
                a[mi][0] = Ast[(m    ) * 20 + ko + tg    ];
                a[mi][1] = Ast[(m + 8) * 20 + ko + tg    ];
                a[mi][2] = Ast[(m    ) * 20 + ko + tg + 4];
                a[mi][3] = Ast[(m + 8) * 20 + ko + tg + 4];
            }
            #pragma unroll
            for (int ni = 0; ni < 4; ni++) {
                int n = nBase + ni * 8 + g;
                b[ni][0] = Bst[n * 20 + ko + tg    ];
                b[ni][1] = Bst[n * 20 + ko + tg + 4];
            }
            #pragma unroll
            for (int mi = 0; mi < 4; mi++)
                #pragma unroll
                for (int ni = 0; ni < 4; ni++)
                    mma_f16(acc[mi][ni], a[mi], b[ni]);
        }
    }

    // ---- epilogue ----
    #pragma unroll
    for (int mi = 0; mi < 4; mi++) {
        #pragma unroll
        for (int half = 0; half < 2; half++) {
            int ig = row0 + mBase + mi * 16 + g + half * 8;
            #pragma unroll
            for (int ni = 0; ni < 4; ni++) {
                float v0 = acc[mi][ni][2 * half + 0];
                float v1 = acc[mi][ni][2 * half + 1];
                int jg = col0 + nBase + ni * 8 + tg * 2;
                if (EPI == 0) {        // QKV scatter -> fp16 q/k/v (B,H,T,D)
                    int bq = ig >> 10, t = ig & 1023;
                    int part = jg >> 10;
                    int c = jg & 1023;
                    int h = c >> 6, d = c & 63;
                    __half2 hv;
                    hv.x = __float2half_rn(v0 + bias[jg]);
                    hv.y = __float2half_rn(v1 + bias[jg + 1]);
                    __half* dst = (part == 0) ? g_q16 : (part == 1) ? g_k16 : g_v16;
                    *(__half2*)&dst[((size_t)(bq * H_ + h) * T_ + t) * D_ + d] = hv;
                } else if (EPI == 1) { // proj: (x + y@W + b) * mask[row]
                    float mrow = mask[ig];
                    Cout[(size_t)ig * N + jg]     = (res[(size_t)ig * N + jg]     + v0 + bias[jg])     * mrow;
                    Cout[(size_t)ig * N + jg + 1] = (res[(size_t)ig * N + jg + 1] + v1 + bias[jg + 1]) * mrow;
                } else if (EPI == 2) { // exact GELU -> fp16 activations
                    float a0 = v0 + bias[jg], a1 = v1 + bias[jg + 1];
                    float g0 = 0.5f * a0 * (1.f + erff(a0 * 0.70710678118654752f));
                    float g1 = 0.5f * a1 * (1.f + erff(a1 * 0.70710678118654752f));
                    __half2 hv; hv.x = __float2half_rn(g0); hv.y = __float2half_rn(g1);
                    *(__half2*)&g_f16[(size_t)ig * N + jg] = hv;
                } else {               // residual
                    Cout[(size_t)ig * N + jg]     = res[(size_t)ig * N + jg]     + v0 + bias[jg];
                    Cout[(size_t)ig * N + jg + 1] = res[(size_t)ig * N + jg + 1] + v1 + bias[jg + 1];
                }
            }
        }
    }
}

// ======================= FUSED FLASH ATTENTION (fp16, 2 CTA/SM) =============
// Logit/prob strip stored fp16 (94KB total smem -> 2 CTAs/SM).
// Probs kept UNNORMALIZED; 1/l folded into colsum + output scale.
#define QT 32
#define SHSTR 524                 /* u32 per strip row (1048 halves); 524%32=12 */
#define QSTR 36                   /* u32 per Q row */
#define KVSTR 36                  /* u32 per K/V row (72 halves) */
#define OFF_Q   67072
#define OFF_KV  71680
#define OFF_AM  90112
#define OFF_INV 94208
#define FA_SMEM 94336

__global__ void __launch_bounds__(512, 2) fattn_kernel(
    const __half* __restrict__ q, const __half* __restrict__ k,
    const __half* __restrict__ v, const float* __restrict__ am,
    __half* __restrict__ y16, float* __restrict__ imp)
{
    extern __shared__ char smc[];
    __half*   Shh = (__half*)smc;
    uint32_t* Shw = (uint32_t*)smc;
    uint32_t* Qs  = (uint32_t*)(smc + OFF_Q);
    uint32_t* KVs = (uint32_t*)(smc + OFF_KV);
    float*    amS = (float*)(smc + OFF_AM);
    float*    invlS = (float*)(smc + OFF_INV);

    int qt = gridDim.x - 1 - blockIdx.x;
    int bh = blockIdx.y;
    int b  = bh >> 4, h = bh & 15;
    int tid  = threadIdx.x;
    int lane = tid & 31;
    int wid  = tid >> 5;
    int g = lane >> 2, tg = lane & 3;

    int q0   = qt * QT;
    int kend = q0 + QT;
    int jmax = ((kend + 63) >> 6) << 6;

    const __half* qb = q + (size_t)bh * T_ * D_;
    const __half* kb = k + (size_t)bh * T_ * D_;
    const __half* vb = v + (size_t)bh * T_ * D_;

    // ---- load Q tile (32x64 half) + key mask ----
    if (tid < 256) {
        int row = tid >> 3, cs = tid & 7;
        uint4 val = *(const uint4*)(qb + (size_t)(q0 + row) * D_ + cs * 8);
        *(uint4*)&Qs[row * QSTR + cs * 4] = val;
    }
    for (int j = tid; j < T_; j += 512) amS[j] = am[b * T_ + j];
    __syncthreads();

    int warpRow = wid >> 3;        // 0/1
    int warpCol = wid & 7;         // 0..7
    int m0 = warpRow * 16;

    uint32_t aq[4][4];
    #pragma unroll
    for (int ks = 0; ks < 4; ks++) {
        aq[ks][0] = Qs[(m0 + g    ) * QSTR + ks * 8 + tg    ];
        aq[ks][1] = Qs[(m0 + g + 8) * QSTR + ks * 8 + tg    ];
        aq[ks][2] = Qs[(m0 + g    ) * QSTR + ks * 8 + 4 + tg];
        aq[ks][3] = Qs[(m0 + g + 8) * QSTR + ks * 8 + 4 + tg];
    }

    // ---- phase 1: logits (stored fp16) ----
    for (int kc0 = 0; kc0 < jmax; kc0 += 128) {
        int rows_here = min(128, jmax - kc0);
        __syncthreads();
        for (int idx = tid; idx < rows_here * 8; idx += 512) {
            int r = idx >> 3, cs = idx & 7;
            uint4 val = *(const uint4*)(kb + (size_t)(kc0 + r) * D_ + cs * 8);
            *(uint4*)&KVs[r * KVSTR + cs * 4] = val;
        }
        __syncthreads();
        if (warpCol * 16 < rows_here) {
            float acc[2][4] = {};
            #pragma unroll
            for (int ks = 0; ks < 4; ks++) {
                #pragma unroll
                for (int f = 0; f < 2; f++) {
                    int n = warpCol * 16 + f * 8 + g;
                    uint32_t bb[2];
                    bb[0] = KVs[n * KVSTR + ks * 8 + tg    ];
                    bb[1] = KVs[n * KVSTR + ks * 8 + 4 + tg];
                    mma_f16(acc[f], aq[ks], bb);
                }
            }
            #pragma unroll
            for (int f = 0; f < 2; f++) {
                int w0 = ((kc0 + warpCol * 16 + f * 8) >> 1) + tg;
                int r0 = m0 + g;
                __half2 p01 = __floats2half2_rn(acc[f][0] * 0.125f, acc[f][1] * 0.125f);
                __half2 p23 = __floats2half2_rn(acc[f][2] * 0.125f, acc[f][3] * 0.125f);
                Shw[r0 * SHSTR + w0]       = *(uint32_t*)&p01;
                Shw[(r0 + 8) * SHSTR + w0] = *(uint32_t*)&p23;
            }
        }
    }
    __syncthreads();

    // ---- phase 2: softmax (unnormalized probs in place, 1/l to smem) ----
    #pragma unroll
    for (int r2 = 0; r2 < 2; r2++) {
        int row = wid + r2 * 16;
        int qg  = q0 + row;
        __half* srow = Shh + row * (2 * SHSTR);
        float lm = -1e30f;
        for (int j = lane; j <= qg; j += 32)
            if (amS[j] != 0.f) lm = fmaxf(lm, __half2float(srow[j]));
        #pragma unroll
        for (int o = 16; o; o >>= 1) lm = fmaxf(lm, __shfl_xor_sync(~0u, lm, o));
        float ls = 0.f;
        for (int j = lane; j < jmax; j += 32) {
            bool valid = (j <= qg) && (amS[j] != 0.f);
            float e = valid ? __expf(__half2float(srow[j]) - lm) : 0.f;
            srow[j] = __float2half_rn(e);
            ls += e;
        }
        #pragma unroll
        for (int o = 16; o; o >>= 1) ls += __shfl_xor_sync(~0u, ls, o);
        if (lane == 0) invlS[row] = 1.f / ls;
    }
    __syncthreads();

    // ---- phase 2b: weighted column sums -> importance atomics ----
    if (2 * tid < kend) {
        float cs0 = 0.f, cs1 = 0.f;
        #pragma unroll
        for (int r = 0; r < QT; r++) {
            uint32_t pw = Shw[r * SHSTR + tid];
            __half2 ph = *(__half2*)&pw;
            float wgt = invlS[r];
            cs0 += __half2float(ph.x) * wgt;
            cs1 += __half2float(ph.y) * wgt;
        }
        atomicAdd(&imp[b * T_ + 2 * tid],     cs0 * (1.f / (H_ * T_)));
        atomicAdd(&imp[b * T_ + 2 * tid + 1], cs1 * (1.f / (H_ * T_)));
    }

    // ---- phase 3: y = (P @ V) * invl ----
    int col0 = warpCol * 8;
    uint32_t kvbase = smem_u32(KVs);
    float acc[4] = {};
    for (int kc0 = 0; kc0 < jmax; kc0 += 128) {
        int rows_here = min(128, jmax - kc0);
        __syncthreads();
        for (int idx = tid; idx < rows_here * 8; idx += 512) {
            int r = idx >> 3, cs = idx & 7;
            uint4 val = *(const uint4*)(vb + (size_t)(kc0 + r) * D_ + cs * 8);
            *(uint4*)&KVs[r * KVSTR + cs * 4] = val;
        }
        __syncthreads();
        int ksteps = rows_here >> 4;
        for (int ks = 0; ks < ksteps; ks++) {
            int wc = ((kc0 + ks * 16) >> 1);
            uint32_t a[4], bb[2];
            a[0] = Shw[(m0 + g    ) * SHSTR + wc + tg    ];
            a[1] = Shw[(m0 + g + 8) * SHSTR + wc + tg    ];
            a[2] = Shw[(m0 + g    ) * SHSTR + wc + 4 + tg];
            a[3] = Shw[(m0 + g + 8) * SHSTR + wc + 4 + tg];
            uint32_t addr = kvbase + ((ks * 16 + (lane & 15)) * 72 + col0) * 2;
            ldmx2t(bb[0], bb[1], addr);
            mma_f16(acc, a, bb);
        }
    }
    float sc0 = invlS[m0 + g], sc1 = invlS[m0 + g + 8];
    #pragma unroll
    for (int half = 0; half < 2; half++) {
        int t = q0 + m0 + g + half * 8;
        int d = h * 64 + col0 + tg * 2;
        float s = half ? sc1 : sc0;
        __half2 hv;
        hv.x = __float2half_rn(acc[2 * half] * s);
        hv.y = __float2half_rn(acc[2 * half + 1] * s);
        *(__half2*)&y16[(size_t)(b * T_ + t) * C_ + d] = hv;
    }
}

// ---------------- launch ----------------------------------------------------
extern "C" void kernel_launch(void* const* d_in, const int* in_sizes, int n_in,
                              void* d_out, int out_size) {
    const float* x     = (const float*)d_in[0];
    const float* am    = (const float*)d_in[1];
    const float* ln1w  = (const float*)d_in[2];
    const float* ln1b  = (const float*)d_in[3];
    const float* wattn = (const float*)d_in[4];
    const float* battn = (const float*)d_in[5];
    const float* wproj = (const float*)d_in[6];
    const float* bproj = (const float*)d_in[7];
    const float* thr   = (const float*)d_in[8];
    const float* ln2w  = (const float*)d_in[9];
    const float* ln2b  = (const float*)d_in[10];
    const float* wfc   = (const float*)d_in[11];
    const float* bfc   = (const float*)d_in[12];
    const float* wfc2  = (const float*)d_in[13];
    const float* bfc2  = (const float*)d_in[14];

    float* out      = (float*)d_out;
    float* out_x    = out;
    float* out_mask = out + out_size - 1 - M_;
    float* out_loss = out + out_size - 1;

    float *px2, *pimp, *pmsk;
    cudaGetSymbolAddress((void**)&px2,  g_x2);
    cudaGetSymbolAddress((void**)&pimp, g_imp);
    cudaGetSymbolAddress((void**)&pmsk, g_msk);
    __half *pq16, *pk16, *pv16, *ph16, *py16, *pf16, *pwat, *pwpr, *pwfc, *pwf2;
    cudaGetSymbolAddress((void**)&pq16, g_q16);
    cudaGetSymbolAddress((void**)&pk16, g_k16);
    cudaGetSymbolAddress((void**)&pv16, g_v16);
    cudaGetSymbolAddress((void**)&ph16, g_h16);
    cudaGetSymbolAddress((void**)&py16, g_y16);
    cudaGetSymbolAddress((void**)&pf16, g_f16);
    cudaGetSymbolAddress((void**)&pwat, g_wat);
    cudaGetSymbolAddress((void**)&pwpr, g_wpr);
    cudaGetSymbolAddress((void**)&pwfc, g_wfc);
    cudaGetSymbolAddress((void**)&pwf2, g_wf2);

    static int smem_set = 0;
    if (!smem_set) {
        cudaFuncSetAttribute(fattn_kernel,
                             cudaFuncAttributeMaxDynamicSharedMemorySize, FA_SMEM);
        cudaFuncSetAttribute(tgemm_kernel<0>,
                             cudaFuncAttributeMaxDynamicSharedMemorySize, GEMM_SMEM);
        cudaFuncSetAttribute(tgemm_kernel<1>,
                             cudaFuncAttributeMaxDynamicSharedMemorySize, GEMM_SMEM);
        cudaFuncSetAttribute(tgemm_kernel<2>,
                             cudaFuncAttributeMaxDynamicSharedMemorySize, GEMM_SMEM);
        cudaFuncSetAttribute(tgemm_kernel<3>,
                             cudaFuncAttributeMaxDynamicSharedMemorySize, GEMM_SMEM);
        smem_set = 1;
    }

    zero_kernel<<<16, 256>>>(pimp, M_);
    wsplit_kernel<<<dim3(NQKV/32, C_/32), 256>>>(wattn, pwat, C_, NQKV);
    wsplit_kernel<<<dim3(C_/32,   C_/32), 256>>>(wproj, pwpr, C_, C_);
    wsplit_kernel<<<dim3(NFC/32,  C_/32), 256>>>(wfc,   pwfc, C_, NFC);
    wsplit_kernel<<<dim3(C_/32,  NFC/32), 256>>>(wfc2,  pwf2, NFC, C_);

    ln_kernel<<<M_, 256>>>(x, ln1w, ln1b, ph16);
    tgemm_kernel<0><<<dim3(NQKV/128, M_/128), 256, GEMM_SMEM>>>(
        ph16, pwat, battn, nullptr, nullptr, nullptr, M_, NQKV, C_);
    fattn_kernel<<<dim3(T_/QT, B_*H_), 512, FA_SMEM>>>(pq16, pk16, pv16, am, py16, pimp);
    mask_kernel<<<16, 256>>>(pimp, am, thr, pmsk, out_mask, out_loss);
    tgemm_kernel<1><<<dim3(C_/128, M_/128), 256, GEMM_SMEM>>>(
        py16, pwpr, bproj, x, pmsk, px2, M_, C_, C_);
    ln_kernel<<<M_, 256>>>(px2, ln2w, ln2b, ph16);
    tgemm_kernel<2><<<dim3(NFC/128, M_/128), 256, GEMM_SMEM>>>(
        ph16, pwfc, bfc, nullptr, nullptr, nullptr, M_, NFC, C_);
    tgemm_kernel<3><<<dim3(C_/128, M_/128), 256, GEMM_SMEM>>>(
        pf16, pwf2, bfc2, px2, nullptr, out_x, M_, C_, NFC);
}

// round 10
// speedup vs baseline: 1.1510x; 1.0411x over previous
#include <cuda_runtime.h>
#include <cuda_fp16.h>
#include <math.h>
#include <stdint.h>

#define B_ 4
#define T_ 1024
#define C_ 1024
#define H_ 16
#define D_ 64
#define M_ (B_*T_)      /* 4096 rows */
#define NQKV 3072
#define NFC  4096

// ---------------- scratch (__device__ globals: no allocation allowed) -------
__device__ float g_x2 [M_*C_];                 // masked residual after proj
__device__ float g_imp[M_];
__device__ float g_msk[M_];
// fp16 operand buffers
__device__ __half g_q16[M_*C_];                      // (B,H,T,D)
__device__ __half g_k16[M_*C_];
__device__ __half g_v16[M_*C_];
__device__ __half g_h16[M_*C_];                      // LN out
__device__ __half g_y16[M_*C_];                      // attn out (B,T,C)
__device__ __half g_f16[(size_t)M_*NFC];             // gelu activations
__device__ __half g_wat[C_*NQKV];                    // weights transposed [N][K]
__device__ __half g_wpr[C_*C_];
__device__ __half g_wfc[(size_t)C_*NFC];
__device__ __half g_wf2[(size_t)NFC*C_];

// ---------------- helpers ---------------------------------------------------
__device__ __forceinline__ void mma_f16(float c[4], const uint32_t a[4], const uint32_t b[2]) {
    asm volatile(
        "mma.sync.aligned.m16n8k16.row.col.f32.f16.f16.f32 "
        "{%0,%1,%2,%3}, {%4,%5,%6,%7}, {%8,%9}, {%0,%1,%2,%3};"
        : "+f"(c[0]), "+f"(c[1]), "+f"(c[2]), "+f"(c[3])
        : "r"(a[0]), "r"(a[1]), "r"(a[2]), "r"(a[3]), "r"(b[0]), "r"(b[1]));
}
__device__ __forceinline__ void cp16(void* dst_smem, const void* src) {
    uint32_t d = (uint32_t)__cvta_generic_to_shared(dst_smem);
    asm volatile("cp.async.cg.shared.global [%0], [%1], 16;" :: "r"(d), "l"(src));
}
__device__ __forceinline__ void cp_commit() { asm volatile("cp.async.commit_group;"); }
template<int N_>
__device__ __forceinline__ void cp_wait() { asm volatile("cp.async.wait_group %0;" :: "n"(N_)); }
__device__ __forceinline__ uint32_t smem_u32(const void* p) {
    return (uint32_t)__cvta_generic_to_shared(p);
}
__device__ __forceinline__ void ldmx2t(uint32_t& r0, uint32_t& r1, uint32_t addr) {
    asm volatile("ldmatrix.sync.aligned.m8n8.x2.trans.shared.b16 {%0,%1}, [%2];"
                 : "=r"(r0), "=r"(r1) : "r"(addr));
}
// fast exp(x*0.125) on fma/alu pipes: x bounded (|logit*0.125| < ~40 safe)
__device__ __forceinline__ float fexp8(float x) {
    float t = x * 0.18033688011112042f;          // 0.125 * log2(e)
    float z = t + 12582912.0f;                   // round(t) in mantissa
    int   iz = __float_as_int(z);
    float fi = z - 12582912.0f;
    float f  = t - fi;                           // f in [-0.5, 0.5]
    float p = 0.0096181291f;
    p = p * f + 0.0555041087f;
    p = p * f + 0.2402265069f;
    p = p * f + 0.6931471806f;
    p = p * f + 1.0f;
    return __int_as_float(__float_as_int(p) + (iz << 23));
}

// ---------------- small kernels --------------------------------------------
__global__ void zero_kernel(float* p, int n) {
    int i = blockIdx.x * 256 + threadIdx.x;
    if (i < n) p[i] = 0.f;
}

__global__ void mask_kernel(const float* __restrict__ imp,
                            const float* __restrict__ am,
                            const float* __restrict__ thr,
                            float* __restrict__ gmask,
                            float* __restrict__ outmask,
                            float* __restrict__ outloss) {
    int i = blockIdx.x * 256 + threadIdx.x;
    if (i < M_) {
        float pm = (imp[i] >= thr[0]) ? 1.f : 0.f;
        float cm = am[i] * pm;
        gmask[i]   = cm;
        outmask[i] = cm;
    }
    if (i == 0) outloss[0] = 0.f;
}

// ---------------- weight transpose -> fp16 [N][K] ---------------------------
__global__ void __launch_bounds__(256) wsplit_kernel(const float* __restrict__ W,
                                                     __half* __restrict__ Oh,
                                                     int K, int N) {
    __shared__ float tile[32][33];
    int n0 = blockIdx.x * 32, k0 = blockIdx.y * 32;
    int tx = threadIdx.x & 31, ty = threadIdx.x >> 5;   // 32 x 8
    #pragma unroll
    for (int i = 0; i < 4; i++)
        tile[ty + i * 8][tx] = W[(size_t)(k0 + ty + i * 8) * N + n0 + tx];
    __syncthreads();
    #pragma unroll
    for (int i = 0; i < 4; i++) {
        int n = n0 + ty + i * 8;
        Oh[(size_t)n * K + k0 + tx] = __float2half_rn(tile[tx][ty + i * 8]);
    }
}

// ---------------- layer norm -> fp16 ----------------------------------------
__global__ void __launch_bounds__(256) ln_kernel(const float* __restrict__ x,
                                                 const float* __restrict__ w,
                                                 const float* __restrict__ b,
                                                 __half* __restrict__ oh) {
    int row = blockIdx.x;
    int tid = threadIdx.x;
    __shared__ float buf[C_];
    __shared__ float red[8];
    const float* xr = x + (size_t)row * C_;
    float s = 0.f;
    #pragma unroll
    for (int j = tid; j < C_; j += 256) { float v = xr[j]; buf[j] = v; s += v; }
    #pragma unroll
    for (int o = 16; o; o >>= 1) s += __shfl_down_sync(~0u, s, o);
    if ((tid & 31) == 0) red[tid >> 5] = s;
    __syncthreads();
    if (tid < 8) {
        s = red[tid];
        #pragma unroll
        for (int o = 4; o; o >>= 1) s += __shfl_down_sync(0xff, s, o);
        if (tid == 0) red[0] = s;
    }
    __syncthreads();
    float mu = red[0] * (1.f / C_);
    __syncthreads();
    float ss = 0.f;
    #pragma unroll
    for (int j = tid; j < C_; j += 256) { float d = buf[j] - mu; ss += d * d; }
    #pragma unroll
    for (int o = 16; o; o >>= 1) ss += __shfl_down_sync(~0u, ss, o);
    if ((tid & 31) == 0) red[tid >> 5] = ss;
    __syncthreads();
    if (tid < 8) {
        ss = red[tid];
        #pragma unroll
        for (int o = 4; o; o >>= 1) ss += __shfl_down_sync(0xff, ss, o);
        if (tid == 0) red[0] = ss;
    }
    __syncthreads();
    float rstd = rsqrtf(red[0] * (1.f / C_) + 1e-5f);
    #pragma unroll
    for (int j = tid; j < C_; j += 256)
        oh[(size_t)row * C_ + j] = __float2half_rn((buf[j] - mu) * rstd * w[j] + b[j]);
}

// ---------------- fp16 GEMM: 128x128x32-per-stage, cp.async 4-stage ---------
#define STG  4
#define GEMM_SMEM (STG*2*5120*4)      /* 81920 B */

template<int EPI>
__global__ void __launch_bounds__(256, 2) tgemm_kernel(
    const __half* __restrict__ A, const __half* __restrict__ W,
    const float* __restrict__ bias, const float* __restrict__ res,
    const float* __restrict__ mask, float* __restrict__ Cout,
    int M, int N, int K)
{
    extern __shared__ uint32_t smu[];
    int tid  = threadIdx.x;
    int lane = tid & 31;
    int wid  = tid >> 5;
    int warpM = wid >> 2, warpN = wid & 3;
    int g  = lane >> 2, tg = lane & 3;
    int row0 = blockIdx.y * 128, col0 = blockIdx.x * 128;

    int r0s = tid >> 2, c0s = tid & 3;
    int r1s = r0s + 64;

    float acc[4][4][4] = {};
    int nk = K >> 5;

    auto load_stage = [&](int s, int buf) {
        uint32_t* Ad = smu + buf * 2 * 2560;
        uint32_t* Bd = Ad + 2560;
        size_t kb = (size_t)s * 32;
        const __half* Ag = A + (size_t)row0 * K + kb;
        const __half* Bg = W + (size_t)col0 * K + kb;
        cp16(Ad + r0s * 20 + c0s * 4, Ag + (size_t)r0s * K + c0s * 8);
        cp16(Ad + r1s * 20 + c0s * 4, Ag + (size_t)r1s * K + c0s * 8);
        cp16(Bd + r0s * 20 + c0s * 4, Bg + (size_t)r0s * K + c0s * 8);
        cp16(Bd + r1s * 20 + c0s * 4, Bg + (size_t)r1s * K + c0s * 8);
    };

    #pragma unroll
    for (int p = 0; p < STG - 1; p++) { load_stage(p, p); cp_commit(); }

    int mBase = warpM * 64;
    int nBase = warpN * 32;

    for (int kt = 0; kt < nk; kt++) {
        cp_wait<STG - 2>();
        __syncthreads();
        if (kt + STG - 1 < nk) load_stage(kt + STG - 1, (kt + STG - 1) & (STG - 1));
        cp_commit();

        int st = kt & (STG - 1);
        const uint32_t* Ast = smu + st * 2 * 2560;
        const uint32_t* Bst = Ast + 2560;
        #pragma unroll
        for (int kk2 = 0; kk2 < 2; kk2++) {
            int ko = kk2 * 8;
            uint32_t a[4][4], b[4][2];
            #pragma unroll
            for (int mi = 0; mi < 4; mi++) {
                int m = mBase + mi * 16 + g;
                a[mi][0] = Ast[(m    ) * 20 + ko + tg    ];
                a[mi][1] = Ast[(m + 8) * 20 + ko + tg    ];
                a[mi][2] = Ast[(m    ) * 20 + ko + tg + 4];
                a[mi][3] = Ast[(m + 8) * 20 + ko + tg + 4];
            }
            #pragma unroll
            for (int ni = 0; ni < 4; ni++) {
                int n = nBase + ni * 8 + g;
                b[ni][0] = Bst[n * 20 + ko + tg    ];
                b[ni][1] = Bst[n * 20 + ko + tg + 4];
            }
            #pragma unroll
            for (int mi = 0; mi < 4; mi++)
                #pragma unroll
                for (int ni = 0; ni < 4; ni++)
                    mma_f16(acc[mi][ni], a[mi], b[ni]);
        }
    }

    // ---- epilogue ----
    #pragma unroll
    for (int mi = 0; mi < 4; mi++) {
        #pragma unroll
        for (int half = 0; half < 2; half++) {
            int ig = row0 + mBase + mi * 16 + g + half * 8;
            #pragma unroll
            for (int ni = 0; ni < 4; ni++) {
                float v0 = acc[mi][ni][2 * half + 0];
                float v1 = acc[mi][ni][2 * half + 1];
                int jg = col0 + nBase + ni * 8 + tg * 2;
                if (EPI == 0) {        // QKV scatter -> fp16 q/k/v (B,H,T,D)
                    int bq = ig >> 10, t = ig & 1023;
                    int part = jg >> 10;
                    int c = jg & 1023;
                    int h = c >> 6, d = c & 63;
                    __half2 hv;
                    hv.x = __float2half_rn(v0 + bias[jg]);
                    hv.y = __float2half_rn(v1 + bias[jg + 1]);
                    __half* dst = (part == 0) ? g_q16 : (part == 1) ? g_k16 : g_v16;
                    *(__half2*)&dst[((size_t)(bq * H_ + h) * T_ + t) * D_ + d] = hv;
                } else if (EPI == 1) { // proj: (x + y@W + b) * mask[row]
                    float mrow = mask[ig];
                    Cout[(size_t)ig * N + jg]     = (res[(size_t)ig * N + jg]     + v0 + bias[jg])     * mrow;
                    Cout[(size_t)ig * N + jg + 1] = (res[(size_t)ig * N + jg + 1] + v1 + bias[jg + 1]) * mrow;
                } else if (EPI == 2) { // exact GELU -> fp16 activations
                    float a0 = v0 + bias[jg], a1 = v1 + bias[jg + 1];
                    float g0 = 0.5f * a0 * (1.f + erff(a0 * 0.70710678118654752f));
                    float g1 = 0.5f * a1 * (1.f + erff(a1 * 0.70710678118654752f));
                    __half2 hv; hv.x = __float2half_rn(g0); hv.y = __float2half_rn(g1);
                    *(__half2*)&g_f16[(size_t)ig * N + jg] = hv;
                } else {               // residual
                    Cout[(size_t)ig * N + jg]     = res[(size_t)ig * N + jg]     + v0 + bias[jg];
                    Cout[(size_t)ig * N + jg + 1] = res[(size_t)ig * N + jg + 1] + v1 + bias[jg + 1];
                }
            }
        }
    }
}

// ======================= FUSED FLASH ATTENTION (fp16, 2 CTA/SM) =============
// No max-subtraction (logits bounded); exp fused into phase-1 epilogue via
// FMA-pipe fast exp2; row sums accumulated in registers + smem reduce.
#define QT 32
#define SHSTR 524                 /* u32 per strip row; 524%32=12 */
#define QSTR 36
#define KVSTR 36
#define OFF_Q    67072
#define OFF_KV   71680
#define OFF_AM   90112
#define OFF_INV  94208
#define OFF_PART 94336            /* float part[16][17] = 1088 B */
#define FA_SMEM  95424

__global__ void __launch_bounds__(512, 2) fattn_kernel(
    const __half* __restrict__ q, const __half* __restrict__ k,
    const __half* __restrict__ v, const float* __restrict__ am,
    __half* __restrict__ y16, float* __restrict__ imp)
{
    extern __shared__ char smc[];
    uint32_t* Shw = (uint32_t*)smc;
    uint32_t* Qs  = (uint32_t*)(smc + OFF_Q);
    uint32_t* KVs = (uint32_t*)(smc + OFF_KV);
    float*    amS = (float*)(smc + OFF_AM);
    float*    invlS = (float*)(smc + OFF_INV);
    float*    part  = (float*)(smc + OFF_PART);   // [16][17]

    int qt = gridDim.x - 1 - blockIdx.x;
    int bh = blockIdx.y;
    int b  = bh >> 4, h = bh & 15;
    int tid  = threadIdx.x;
    int lane = tid & 31;
    int wid  = tid >> 5;
    int g = lane >> 2, tg = lane & 3;

    int q0   = qt * QT;
    int kend = q0 + QT;
    int jmax = ((kend + 63) >> 6) << 6;

    const __half* qb = q + (size_t)bh * T_ * D_;
    const __half* kb = k + (size_t)bh * T_ * D_;
    const __half* vb = v + (size_t)bh * T_ * D_;

    // ---- load Q tile + key mask ----
    if (tid < 256) {
        int row = tid >> 3, cs = tid & 7;
        uint4 val = *(const uint4*)(qb + (size_t)(q0 + row) * D_ + cs * 8);
        *(uint4*)&Qs[row * QSTR + cs * 4] = val;
    }
    for (int j = tid; j < T_; j += 512) amS[j] = am[b * T_ + j];
    __syncthreads();

    int warpRow = wid >> 3;        // 0/1
    int warpCol = wid & 7;         // 0..7
    int m0 = warpRow * 16;

    uint32_t aq[4][4];
    #pragma unroll
    for (int ks = 0; ks < 4; ks++) {
        aq[ks][0] = Qs[(m0 + g    ) * QSTR + ks * 8 + tg    ];
        aq[ks][1] = Qs[(m0 + g + 8) * QSTR + ks * 8 + tg    ];
        aq[ks][2] = Qs[(m0 + g    ) * QSTR + ks * 8 + 4 + tg];
        aq[ks][3] = Qs[(m0 + g + 8) * QSTR + ks * 8 + 4 + tg];
    }

    int qg0 = q0 + m0 + g;
    int qg1 = qg0 + 8;
    float rs0 = 0.f, rs1 = 0.f;    // this warp's partial row sums

    // ---- phase 1: unnormalized probs = exp(logit), fused ----
    for (int kc0 = 0; kc0 < jmax; kc0 += 128) {
        int rows_here = min(128, jmax - kc0);
        __syncthreads();
        for (int idx = tid; idx < rows_here * 8; idx += 512) {
            int r = idx >> 3, cs = idx & 7;
            uint4 val = *(const uint4*)(kb + (size_t)(kc0 + r) * D_ + cs * 8);
            *(uint4*)&KVs[r * KVSTR + cs * 4] = val;
        }
        __syncthreads();
        if (warpCol * 16 < rows_here) {
            float acc[2][4] = {};
            #pragma unroll
            for (int ks = 0; ks < 4; ks++) {
                #pragma unroll
                for (int f = 0; f < 2; f++) {
                    int n = warpCol * 16 + f * 8 + g;
                    uint32_t bb[2];
                    bb[0] = KVs[n * KVSTR + ks * 8 + tg    ];
                    bb[1] = KVs[n * KVSTR + ks * 8 + 4 + tg];
                    mma_f16(acc[f], aq[ks], bb);
                }
            }
            #pragma unroll
            for (int f = 0; f < 2; f++) {
                int j0 = kc0 + warpCol * 16 + f * 8 + tg * 2;
                float m0v = amS[j0], m1v = amS[j0 + 1];
                float e00 = (j0     <= qg0 && m0v != 0.f) ? fexp8(acc[f][0]) : 0.f;
                float e01 = (j0 + 1 <= qg0 && m1v != 0.f) ? fexp8(acc[f][1]) : 0.f;
                float e10 = (j0     <= qg1 && m0v != 0.f) ? fexp8(acc[f][2]) : 0.f;
                float e11 = (j0 + 1 <= qg1 && m1v != 0.f) ? fexp8(acc[f][3]) : 0.f;
                rs0 += e00 + e01;
                rs1 += e10 + e11;
                __half2 p01 = __floats2half2_rn(e00, e01);
                __half2 p23 = __floats2half2_rn(e10, e11);
                int w0 = (j0 >> 1);
                int r0 = m0 + g;
                Shw[r0 * SHSTR + w0]       = *(uint32_t*)&p01;
                Shw[(r0 + 8) * SHSTR + w0] = *(uint32_t*)&p23;
            }
        }
    }
    // reduce partial row sums over the 4 tg lanes, stash per-warp partials
    rs0 += __shfl_xor_sync(~0u, rs0, 1); rs0 += __shfl_xor_sync(~0u, rs0, 2);
    rs1 += __shfl_xor_sync(~0u, rs1, 1); rs1 += __shfl_xor_sync(~0u, rs1, 2);
    if (tg == 0) {
        part[wid * 17 + g]     = rs0;
        part[wid * 17 + g + 8] = rs1;
    }
    __syncthreads();
    if (tid < 32) {
        int wr = tid >> 4, lr = tid & 15;
        float s = 0.f;
        #pragma unroll
        for (int w = 0; w < 8; w++) s += part[(wr * 8 + w) * 17 + lr];
        invlS[tid] = 1.f / s;
    }
    __syncthreads();

    // ---- phase 2b: weighted column sums -> importance atomics ----
    if (2 * tid < kend) {
        float cs0 = 0.f, cs1 = 0.f;
        #pragma unroll
        for (int r = 0; r < QT; r++) {
            uint32_t pw = Shw[r * SHSTR + tid];
            __half2 ph = *(__half2*)&pw;
            float wgt = invlS[r];
            cs0 += __half2float(ph.x) * wgt;
            cs1 += __half2float(ph.y) * wgt;
        }
        atomicAdd(&imp[b * T_ + 2 * tid],     cs0 * (1.f / (H_ * T_)));
        atomicAdd(&imp[b * T_ + 2 * tid + 1], cs1 * (1.f / (H_ * T_)));
    }

    // ---- phase 3: y = (P @ V) * invl ----
    int col0 = warpCol * 8;
    uint32_t kvbase = smem_u32(KVs);
    float acc[4] = {};
    for (int kc0 = 0; kc0 < jmax; kc0 += 128) {
        int rows_here = min(128, jmax - kc0);
        __syncthreads();
        for (int idx = tid; idx < rows_here * 8; idx += 512) {
            int r = idx >> 3, cs = idx & 7;
            uint4 val = *(const uint4*)(vb + (size_t)(kc0 + r) * D_ + cs * 8);
            *(uint4*)&KVs[r * KVSTR + cs * 4] = val;
        }
        __syncthreads();
        int ksteps = rows_here >> 4;
        for (int ks = 0; ks < ksteps; ks++) {
            int wc = ((kc0 + ks * 16) >> 1);
            uint32_t a[4], bb[2];
            a[0] = Shw[(m0 + g    ) * SHSTR + wc + tg    ];
            a[1] = Shw[(m0 + g + 8) * SHSTR + wc + tg    ];
            a[2] = Shw[(m0 + g    ) * SHSTR + wc + 4 + tg];
            a[3] = Shw[(m0 + g + 8) * SHSTR + wc + 4 + tg];
            uint32_t addr = kvbase + ((ks * 16 + (lane & 15)) * 72 + col0) * 2;
            ldmx2t(bb[0], bb[1], addr);
            mma_f16(acc, a, bb);
        }
    }
    float sc0 = invlS[m0 + g], sc1 = invlS[m0 + g + 8];
    #pragma unroll
    for (int half = 0; half < 2; half++) {
        int t = q0 + m0 + g + half * 8;
        int d = h * 64 + col0 + tg * 2;
        float s = half ? sc1 : sc0;
        __half2 hv;
        hv.x = __float2half_rn(acc[2 * half] * s);
        hv.y = __float2half_rn(acc[2 * half + 1] * s);
        *(__half2*)&y16[(size_t)(b * T_ + t) * C_ + d] = hv;
    }
}

// ---------------- launch ----------------------------------------------------
extern "C" void kernel_launch(void* const* d_in, const int* in_sizes, int n_in,
                              void* d_out, int out_size) {
    const float* x     = (const float*)d_in[0];
    const float* am    = (const float*)d_in[1];
    const float* ln1w  = (const float*)d_in[2];
    const float* ln1b  = (const float*)d_in[3];
    const float* wattn = (const float*)d_in[4];
    const float* battn = (const float*)d_in[5];
    const float* wproj = (const float*)d_in[6];
    const float* bproj = (const float*)d_in[7];
    const float* thr   = (const float*)d_in[8];
    const float* ln2w  = (const float*)d_in[9];
    const float* ln2b  = (const float*)d_in[10];
    const float* wfc   = (const float*)d_in[11];
    const float* bfc   = (const float*)d_in[12];
    const float* wfc2  = (const float*)d_in[13];
    const float* bfc2  = (const float*)d_in[14];

    float* out      = (float*)d_out;
    float* out_x    = out;
    float* out_mask = out + out_size - 1 - M_;
    float* out_loss = out + out_size - 1;

    float *px2, *pimp, *pmsk;
    cudaGetSymbolAddress((void**)&px2,  g_x2);
    cudaGetSymbolAddress((void**)&pimp, g_imp);
    cudaGetSymbolAddress((void**)&pmsk, g_msk);
    __half *pq16, *pk16, *pv16, *ph16, *py16, *pf16, *pwat, *pwpr, *pwfc, *pwf2;
    cudaGetSymbolAddress((void**)&pq16, g_q16);
    cudaGetSymbolAddress((void**)&pk16, g_k16);
    cudaGetSymbolAddress((void**)&pv16, g_v16);
    cudaGetSymbolAddress((void**)&ph16, g_h16);
    cudaGetSymbolAddress((void**)&py16, g_y16);
    cudaGetSymbolAddress((void**)&pf16, g_f16);
    cudaGetSymbolAddress((void**)&pwat, g_wat);
    cudaGetSymbolAddress((void**)&pwpr, g_wpr);
    cudaGetSymbolAddress((void**)&pwfc, g_wfc);
    cudaGetSymbolAddress((void**)&pwf2, g_wf2);

    static int smem_set = 0;
    if (!smem_set) {
        cudaFuncSetAttribute(fattn_kernel,
                             cudaFuncAttributeMaxDynamicSharedMemorySize, FA_SMEM);
        cudaFuncSetAttribute(tgemm_kernel<0>,
                             cudaFuncAttributeMaxDynamicSharedMemorySize, GEMM_SMEM);
        cudaFuncSetAttribute(tgemm_kernel<1>,
                             cudaFuncAttributeMaxDynamicSharedMemorySize, GEMM_SMEM);
        cudaFuncSetAttribute(tgemm_kernel<2>,
                             cudaFuncAttributeMaxDynamicSharedMemorySize, GEMM_SMEM);
        cudaFuncSetAttribute(tgemm_kernel<3>,
                             cudaFuncAttributeMaxDynamicSharedMemorySize, GEMM_SMEM);
        smem_set = 1;
    }

    zero_kernel<<<16, 256>>>(pimp, M_);
    wsplit_kernel<<<dim3(NQKV/32, C_/32), 256>>>(wattn, pwat, C_, NQKV);
    wsplit_kernel<<<dim3(C_/32,   C_/32), 256>>>(wproj, pwpr, C_, C_);
    wsplit_kernel<<<dim3(NFC/32,  C_/32), 256>>>(wfc,   pwfc, C_, NFC);
    wsplit_kernel<<<dim3(C_/32,  NFC/32), 256>>>(wfc2,  pwf2, NFC, C_);

    ln_kernel<<<M_, 256>>>(x, ln1w, ln1b, ph16);
    tgemm_kernel<0><<<dim3(NQKV/128, M_/128), 256, GEMM_SMEM>>>(
        ph16, pwat, battn, nullptr, nullptr, nullptr, M_, NQKV, C_);
    fattn_kernel<<<dim3(T_/QT, B_*H_), 512, FA_SMEM>>>(pq16, pk16, pv16, am, py16, pimp);
    mask_kernel<<<16, 256>>>(pimp, am, thr, pmsk, out_mask, out_loss);
    tgemm_kernel<1><<<dim3(C_/128, M_/128), 256, GEMM_SMEM>>>(
        py16, pwpr, bproj, x, pmsk, px2, M_, C_, C_);
    ln_kernel<<<M_, 256>>>(px2, ln2w, ln2b, ph16);
    tgemm_kernel<2><<<dim3(NFC/128, M_/128), 256, GEMM_SMEM>>>(
        ph16, pwfc, bfc, nullptr, nullptr, nullptr, M_, NFC, C_);
    tgemm_kernel<3><<<dim3(C_/128, M_/128), 256, GEMM_SMEM>>>(
        pf16, pwf2, bfc2, px2, nullptr, out_x, M_, C_, NFC);
}

// round 11
// speedup vs baseline: 1.1670x; 1.0139x over previous
#include <cuda_runtime.h>
#include <cuda_fp16.h>
#include <math.h>
#include <stdint.h>

#define B_ 4
#define T_ 1024
#define C_ 1024
#define H_ 16
#define D_ 64
#define M_ (B_*T_)      /* 4096 rows */
#define NQKV 3072
#define NFC  4096

// ---------------- scratch (__device__ globals: no allocation allowed) -------
__device__ float g_x2 [M_*C_];                 // masked residual after proj
__device__ float g_imp[M_];
__device__ float g_msk[M_];
// fp16 operand buffers
__device__ __half g_q16[M_*C_];                      // (B,H,T,D)
__device__ __half g_k16[M_*C_];
__device__ __half g_v16[M_*C_];
__device__ __half g_h16[M_*C_];                      // LN out
__device__ __half g_y16[M_*C_];                      // attn out (B,T,C)
__device__ __half g_f16[(size_t)M_*NFC];             // gelu activations
__device__ __half g_wat[C_*NQKV];                    // weights transposed [N][K]
__device__ __half g_wpr[C_*C_];
__device__ __half g_wfc[(size_t)C_*NFC];
__device__ __half g_wf2[(size_t)NFC*C_];

// ---------------- helpers ---------------------------------------------------
__device__ __forceinline__ void mma_f16(float c[4], const uint32_t a[4], const uint32_t b[2]) {
    asm volatile(
        "mma.sync.aligned.m16n8k16.row.col.f32.f16.f16.f32 "
        "{%0,%1,%2,%3}, {%4,%5,%6,%7}, {%8,%9}, {%0,%1,%2,%3};"
        : "+f"(c[0]), "+f"(c[1]), "+f"(c[2]), "+f"(c[3])
        : "r"(a[0]), "r"(a[1]), "r"(a[2]), "r"(a[3]), "r"(b[0]), "r"(b[1]));
}
__device__ __forceinline__ void cp16(void* dst_smem, const void* src) {
    uint32_t d = (uint32_t)__cvta_generic_to_shared(dst_smem);
    asm volatile("cp.async.cg.shared.global [%0], [%1], 16;" :: "r"(d), "l"(src));
}
__device__ __forceinline__ void cp_commit() { asm volatile("cp.async.commit_group;"); }
template<int N_>
__device__ __forceinline__ void cp_wait() { asm volatile("cp.async.wait_group %0;" :: "n"(N_)); }
__device__ __forceinline__ uint32_t smem_u32(const void* p) {
    return (uint32_t)__cvta_generic_to_shared(p);
}
__device__ __forceinline__ void ldmx2t(uint32_t& r0, uint32_t& r1, uint32_t addr) {
    asm volatile("ldmatrix.sync.aligned.m8n8.x2.trans.shared.b16 {%0,%1}, [%2];"
                 : "=r"(r0), "=r"(r1) : "r"(addr));
}
// fast exp(x*0.125) on fma/alu pipes
__device__ __forceinline__ float fexp8(float x) {
    float t = x * 0.18033688011112042f;          // 0.125 * log2(e)
    float z = t + 12582912.0f;
    int   iz = __float_as_int(z);
    float fi = z - 12582912.0f;
    float f  = t - fi;
    float p = 0.0096181291f;
    p = p * f + 0.0555041087f;
    p = p * f + 0.2402265069f;
    p = p * f + 0.6931471806f;
    p = p * f + 1.0f;
    return __int_as_float(__float_as_int(p) + (iz << 23));
}

// ---------------- small kernels --------------------------------------------
__global__ void mask_kernel(const float* __restrict__ imp,
                            const float* __restrict__ am,
                            const float* __restrict__ thr,
                            float* __restrict__ gmask,
                            float* __restrict__ outmask,
                            float* __restrict__ outloss) {
    int i = blockIdx.x * 256 + threadIdx.x;
    if (i < M_) {
        float pm = (imp[i] >= thr[0]) ? 1.f : 0.f;
        float cm = am[i] * pm;
        gmask[i]   = cm;
        outmask[i] = cm;
    }
    if (i == 0) outloss[0] = 0.f;
}

// ---------------- weight transpose tile (fp32 [K][N] -> fp16 [N][K]) --------
__device__ __forceinline__ void wtile(const float* __restrict__ W,
                                      __half* __restrict__ Oh,
                                      int K, int N, int bx, int by) {
    __shared__ float tile[32][33];
    int n0 = bx * 32, k0 = by * 32;
    int tx = threadIdx.x & 31, ty = threadIdx.x >> 5;   // 32 x 8
    #pragma unroll
    for (int i = 0; i < 4; i++)
        tile[ty + i * 8][tx] = W[(size_t)(k0 + ty + i * 8) * N + n0 + tx];
    __syncthreads();
    #pragma unroll
    for (int i = 0; i < 4; i++) {
        int n = n0 + ty + i * 8;
        Oh[(size_t)n * K + k0 + tx] = __float2half_rn(tile[tx][ty + i * 8]);
    }
}

// prepA: zero imp + split wattn (3072 tile blocks)
__global__ void __launch_bounds__(256) prepA_kernel(const float* __restrict__ W,
                                                    __half* __restrict__ Oh,
                                                    float* __restrict__ imp) {
    int blk = blockIdx.x;
    if (blk < 16) imp[blk * 256 + threadIdx.x] = 0.f;
    wtile(W, Oh, C_, NQKV, blk % 96, blk / 96);
}

// prepB: split wproj (1024) + wfc (4096) + wfc2 (4096) = 9216 blocks
__global__ void __launch_bounds__(256) prepB_kernel(const float* __restrict__ Wpr,
                                                    __half* __restrict__ Opr,
                                                    const float* __restrict__ Wfc,
                                                    __half* __restrict__ Ofc,
                                                    const float* __restrict__ Wf2,
                                                    __half* __restrict__ Of2) {
    int blk = blockIdx.x;
    if (blk < 1024) {
        wtile(Wpr, Opr, C_, C_, blk % 32, blk / 32);
    } else if (blk < 5120) {
        int t = blk - 1024;
        wtile(Wfc, Ofc, C_, NFC, t % 128, t / 128);
    } else {
        int t = blk - 5120;
        wtile(Wf2, Of2, NFC, C_, t % 32, t / 32);
    }
}

// ---------------- layer norm -> fp16 ----------------------------------------
__global__ void __launch_bounds__(256) ln_kernel(const float* __restrict__ x,
                                                 const float* __restrict__ w,
                                                 const float* __restrict__ b,
                                                 __half* __restrict__ oh) {
    int row = blockIdx.x;
    int tid = threadIdx.x;
    __shared__ float buf[C_];
    __shared__ float red[8];
    const float* xr = x + (size_t)row * C_;
    float s = 0.f;
    #pragma unroll
    for (int j = tid; j < C_; j += 256) { float v = xr[j]; buf[j] = v; s += v; }
    #pragma unroll
    for (int o = 16; o; o >>= 1) s += __shfl_down_sync(~0u, s, o);
    if ((tid & 31) == 0) red[tid >> 5] = s;
    __syncthreads();
    if (tid < 8) {
        s = red[tid];
        #pragma unroll
        for (int o = 4; o; o >>= 1) s += __shfl_down_sync(0xff, s, o);
        if (tid == 0) red[0] = s;
    }
    __syncthreads();
    float mu = red[0] * (1.f / C_);
    __syncthreads();
    float ss = 0.f;
    #pragma unroll
    for (int j = tid; j < C_; j += 256) { float d = buf[j] - mu; ss += d * d; }
    #pragma unroll
    for (int o = 16; o; o >>= 1) ss += __shfl_down_sync(~0u, ss, o);
    if ((tid & 31) == 0) red[tid >> 5] = ss;
    __syncthreads();
    if (tid < 8) {
        ss = red[tid];
        #pragma unroll
        for (int o = 4; o; o >>= 1) ss += __shfl_down_sync(0xff, ss, o);
        if (tid == 0) red[0] = ss;
    }
    __syncthreads();
    float rstd = rsqrtf(red[0] * (1.f / C_) + 1e-5f);
    #pragma unroll
    for (int j = tid; j < C_; j += 256)
        oh[(size_t)row * C_ + j] = __float2half_rn((buf[j] - mu) * rstd * w[j] + b[j]);
}

// ---------------- fp16 GEMM: 128x128x32-per-stage, cp.async 4-stage ---------
#define STG  4
#define GEMM_SMEM (STG*2*5120*4)      /* 81920 B */

template<int EPI>
__global__ void __launch_bounds__(256, 2) tgemm_kernel(
    const __half* __restrict__ A, const __half* __restrict__ W,
    const float* __restrict__ bias, const float* __restrict__ res,
    const float* __restrict__ mask, float* __restrict__ Cout,
    int M, int N, int K)
{
    extern __shared__ uint32_t smu[];
    int tid  = threadIdx.x;
    int lane = tid & 31;
    int wid  = tid >> 5;
    int warpM = wid >> 2, warpN = wid & 3;
    int g  = lane >> 2, tg = lane & 3;
    int row0 = blockIdx.y * 128, col0 = blockIdx.x * 128;

    int r0s = tid >> 2, c0s = tid & 3;
    int r1s = r0s + 64;

    float acc[4][4][4] = {};
    int nk = K >> 5;

    auto load_stage = [&](int s, int buf) {
        uint32_t* Ad = smu + buf * 2 * 2560;
        uint32_t* Bd = Ad + 2560;
        size_t kb = (size_t)s * 32;
        const __half* Ag = A + (size_t)row0 * K + kb;
        const __half* Bg = W + (size_t)col0 * K + kb;
        cp16(Ad + r0s * 20 + c0s * 4, Ag + (size_t)r0s * K + c0s * 8);
        cp16(Ad + r1s * 20 + c0s * 4, Ag + (size_t)r1s * K + c0s * 8);
        cp16(Bd + r0s * 20 + c0s * 4, Bg + (size_t)r0s * K + c0s * 8);
        cp16(Bd + r1s * 20 + c0s * 4, Bg + (size_t)r1s * K + c0s * 8);
    };

    #pragma unroll
    for (int p = 0; p < STG - 1; p++) { load_stage(p, p); cp_commit(); }

    int mBase = warpM * 64;
    int nBase = warpN * 32;

    for (int kt = 0; kt < nk; kt++) {
        cp_wait<STG - 2>();
        __syncthreads();
        if (kt + STG - 1 < nk) load_stage(kt + STG - 1, (kt + STG - 1) & (STG - 1));
        cp_commit();

        int st = kt & (STG - 1);
        const uint32_t* Ast = smu + st * 2 * 2560;
        const uint32_t* Bst = Ast + 2560;
        #pragma unroll
        for (int kk2 = 0; kk2 < 2; kk2++) {
            int ko = kk2 * 8;
            uint32_t a[4][4], b[4][2];
            #pragma unroll
            for (int mi = 0; mi < 4; mi++) {
                int m = mBase + mi * 16 + g;
                a[mi][0] = Ast[(m    ) * 20 + ko + tg    ];
                a[mi][1] = Ast[(m + 8) * 20 + ko + tg    ];
                a[mi][2] = Ast[(m    ) * 20 + ko + tg + 4];
                a[mi][3] = Ast[(m + 8) * 20 + ko + tg + 4];
            }
            #pragma unroll
            for (int ni = 0; ni < 4; ni++) {
                int n = nBase + ni * 8 + g;
                b[ni][0] = Bst[n * 20 + ko + tg    ];
                b[ni][1] = Bst[n * 20 + ko + tg + 4];
            }
            #pragma unroll
            for (int mi = 0; mi < 4; mi++)
                #pragma unroll
                for (int ni = 0; ni < 4; ni++)
                    mma_f16(acc[mi][ni], a[mi], b[ni]);
        }
    }

    // ---- epilogue ----
    #pragma unroll
    for (int mi = 0; mi < 4; mi++) {
        #pragma unroll
        for (int half = 0; half < 2; half++) {
            int ig = row0 + mBase + mi * 16 + g + half * 8;
            #pragma unroll
            for (int ni = 0; ni < 4; ni++) {
                float v0 = acc[mi][ni][2 * half + 0];
                float v1 = acc[mi][ni][2 * half + 1];
                int jg = col0 + nBase + ni * 8 + tg * 2;
                if (EPI == 0) {
                    int bq = ig >> 10, t = ig & 1023;
                    int part = jg >> 10;
                    int c = jg & 1023;
                    int h = c >> 6, d = c & 63;
                    __half2 hv;
                    hv.x = __float2half_rn(v0 + bias[jg]);
                    hv.y = __float2half_rn(v1 + bias[jg + 1]);
                    __half* dst = (part == 0) ? g_q16 : (part == 1) ? g_k16 : g_v16;
                    *(__half2*)&dst[((size_t)(bq * H_ + h) * T_ + t) * D_ + d] = hv;
                } else if (EPI == 1) {
                    float mrow = mask[ig];
                    Cout[(size_t)ig * N + jg]     = (res[(size_t)ig * N + jg]     + v0 + bias[jg])     * mrow;
                    Cout[(size_t)ig * N + jg + 1] = (res[(size_t)ig * N + jg + 1] + v1 + bias[jg + 1]) * mrow;
                } else if (EPI == 2) {
                    float a0 = v0 + bias[jg], a1 = v1 + bias[jg + 1];
                    float g0 = 0.5f * a0 * (1.f + erff(a0 * 0.70710678118654752f));
                    float g1 = 0.5f * a1 * (1.f + erff(a1 * 0.70710678118654752f));
                    __half2 hv; hv.x = __float2half_rn(g0); hv.y = __float2half_rn(g1);
                    *(__half2*)&g_f16[(size_t)ig * N + jg] = hv;
                } else {
                    Cout[(size_t)ig * N + jg]     = res[(size_t)ig * N + jg]     + v0 + bias[jg];
                    Cout[(size_t)ig * N + jg + 1] = res[(size_t)ig * N + jg + 1] + v1 + bias[jg + 1];
                }
            }
        }
    }
}

// ======================= FUSED FLASH ATTENTION (fp16, 2 CTA/SM) =============
#define QT 32
#define SHSTR 524
#define QSTR 36
#define KVSTR 36
#define OFF_Q    67072
#define OFF_KV   71680
#define OFF_AM   90112
#define OFF_INV  94208
#define OFF_PART 94336
#define FA_SMEM  95424

__global__ void __launch_bounds__(512, 2) fattn_kernel(
    const __half* __restrict__ q, const __half* __restrict__ k,
    const __half* __restrict__ v, const float* __restrict__ am,
    __half* __restrict__ y16, float* __restrict__ imp)
{
    extern __shared__ char smc[];
    uint32_t* Shw = (uint32_t*)smc;
    uint32_t* Qs  = (uint32_t*)(smc + OFF_Q);
    uint32_t* KVs = (uint32_t*)(smc + OFF_KV);
    float*    amS = (float*)(smc + OFF_AM);
    float*    invlS = (float*)(smc + OFF_INV);
    float*    part  = (float*)(smc + OFF_PART);

    int qt = gridDim.x - 1 - blockIdx.x;
    int bh = blockIdx.y;
    int b  = bh >> 4, h = bh & 15;
    int tid  = threadIdx.x;
    int lane = tid & 31;
    int wid  = tid >> 5;
    int g = lane >> 2, tg = lane & 3;

    int q0   = qt * QT;
    int kend = q0 + QT;
    int jmax = ((kend + 63) >> 6) << 6;

    const __half* qb = q + (size_t)bh * T_ * D_;
    const __half* kb = k + (size_t)bh * T_ * D_;
    const __half* vb = v + (size_t)bh * T_ * D_;

    // ---- load Q tile + normalized 0/1 key mask ----
    if (tid < 256) {
        int row = tid >> 3, cs = tid & 7;
        uint4 val = *(const uint4*)(qb + (size_t)(q0 + row) * D_ + cs * 8);
        *(uint4*)&Qs[row * QSTR + cs * 4] = val;
    }
    for (int j = tid; j < T_; j += 512)
        amS[j] = (am[b * T_ + j] != 0.f) ? 1.f : 0.f;
    __syncthreads();

    int warpRow = wid >> 3;
    int warpCol = wid & 7;
    int m0 = warpRow * 16;

    uint32_t aq[4][4];
    #pragma unroll
    for (int ks = 0; ks < 4; ks++) {
        aq[ks][0] = Qs[(m0 + g    ) * QSTR + ks * 8 + tg    ];
        aq[ks][1] = Qs[(m0 + g + 8) * QSTR + ks * 8 + tg    ];
        aq[ks][2] = Qs[(m0 + g    ) * QSTR + ks * 8 + 4 + tg];
        aq[ks][3] = Qs[(m0 + g + 8) * QSTR + ks * 8 + 4 + tg];
    }

    int qg0 = q0 + m0 + g;
    int qg1 = qg0 + 8;
    float rs0 = 0.f, rs1 = 0.f;

    // ---- phase 1: unnormalized probs fused with exp ----
    for (int kc0 = 0; kc0 < jmax; kc0 += 128) {
        int rows_here = min(128, jmax - kc0);
        bool interior = (kc0 + 127 <= q0);     // all keys causally valid for all rows
        __syncthreads();
        for (int idx = tid; idx < rows_here * 8; idx += 512) {
            int r = idx >> 3, cs = idx & 7;
            uint4 val = *(const uint4*)(kb + (size_t)(kc0 + r) * D_ + cs * 8);
            *(uint4*)&KVs[r * KVSTR + cs * 4] = val;
        }
        __syncthreads();
        if (warpCol * 16 < rows_here) {
            float acc[2][4] = {};
            #pragma unroll
            for (int ks = 0; ks < 4; ks++) {
                #pragma unroll
                for (int f = 0; f < 2; f++) {
                    int n = warpCol * 16 + f * 8 + g;
                    uint32_t bb[2];
                    bb[0] = KVs[n * KVSTR + ks * 8 + tg    ];
                    bb[1] = KVs[n * KVSTR + ks * 8 + 4 + tg];
                    mma_f16(acc[f], aq[ks], bb);
                }
            }
            if (interior) {
                #pragma unroll
                for (int f = 0; f < 2; f++) {
                    int j0 = kc0 + warpCol * 16 + f * 8 + tg * 2;
                    float m0v = amS[j0], m1v = amS[j0 + 1];
                    float e00 = fexp8(acc[f][0]) * m0v;
                    float e01 = fexp8(acc[f][1]) * m1v;
                    float e10 = fexp8(acc[f][2]) * m0v;
                    float e11 = fexp8(acc[f][3]) * m1v;
                    rs0 += e00 + e01;
                    rs1 += e10 + e11;
                    __half2 p01 = __floats2half2_rn(e00, e01);
                    __half2 p23 = __floats2half2_rn(e10, e11);
                    int w0 = (j0 >> 1);
                    int r0 = m0 + g;
                    Shw[r0 * SHSTR + w0]       = *(uint32_t*)&p01;
                    Shw[(r0 + 8) * SHSTR + w0] = *(uint32_t*)&p23;
                }
            } else {
                #pragma unroll
                for (int f = 0; f < 2; f++) {
                    int j0 = kc0 + warpCol * 16 + f * 8 + tg * 2;
                    float m0v = amS[j0], m1v = amS[j0 + 1];
                    float e00 = (j0     <= qg0) ? fexp8(acc[f][0]) * m0v : 0.f;
                    float e01 = (j0 + 1 <= qg0) ? fexp8(acc[f][1]) * m1v : 0.f;
                    float e10 = (j0     <= qg1) ? fexp8(acc[f][2]) * m0v : 0.f;
                    float e11 = (j0 + 1 <= qg1) ? fexp8(acc[f][3]) * m1v : 0.f;
                    rs0 += e00 + e01;
                    rs1 += e10 + e11;
                    __half2 p01 = __floats2half2_rn(e00, e01);
                    __half2 p23 = __floats2half2_rn(e10, e11);
                    int w0 = (j0 >> 1);
                    int r0 = m0 + g;
                    Shw[r0 * SHSTR + w0]       = *(uint32_t*)&p01;
                    Shw[(r0 + 8) * SHSTR + w0] = *(uint32_t*)&p23;
                }
            }
        }
    }
    rs0 += __shfl_xor_sync(~0u, rs0, 1); rs0 += __shfl_xor_sync(~0u, rs0, 2);
    rs1 += __shfl_xor_sync(~0u, rs1, 1); rs1 += __shfl_xor_sync(~0u, rs1, 2);
    if (tg == 0) {
        part[wid * 17 + g]     = rs0;
        part[wid * 17 + g + 8] = rs1;
    }
    __syncthreads();
    if (tid < 32) {
        int wr = tid >> 4, lr = tid & 15;
        float s = 0.f;
        #pragma unroll
        for (int w = 0; w < 8; w++) s += part[(wr * 8 + w) * 17 + lr];
        invlS[tid] = 1.f / s;
    }
    __syncthreads();

    // ---- phase 2b: weighted column sums -> importance atomics ----
    if (2 * tid < kend) {
        float cs0 = 0.f, cs1 = 0.f;
        #pragma unroll
        for (int r = 0; r < QT; r++) {
            uint32_t pw = Shw[r * SHSTR + tid];
            __half2 ph = *(__half2*)&pw;
            float wgt = invlS[r];
            cs0 += __half2float(ph.x) * wgt;
            cs1 += __half2float(ph.y) * wgt;
        }
        atomicAdd(&imp[b * T_ + 2 * tid],     cs0 * (1.f / (H_ * T_)));
        atomicAdd(&imp[b * T_ + 2 * tid + 1], cs1 * (1.f / (H_ * T_)));
    }

    // ---- phase 3: y = (P @ V) * invl ----
    int col0 = warpCol * 8;
    uint32_t kvbase = smem_u32(KVs);
    float acc[4] = {};
    for (int kc0 = 0; kc0 < jmax; kc0 += 128) {
        int rows_here = min(128, jmax - kc0);
        __syncthreads();
        for (int idx = tid; idx < rows_here * 8; idx += 512) {
            int r = idx >> 3, cs = idx & 7;
            uint4 val = *(const uint4*)(vb + (size_t)(kc0 + r) * D_ + cs * 8);
            *(uint4*)&KVs[r * KVSTR + cs * 4] = val;
        }
        __syncthreads();
        int ksteps = rows_here >> 4;
        for (int ks = 0; ks < ksteps; ks++) {
            int wc = ((kc0 + ks * 16) >> 1);
            uint32_t a[4], bb[2];
            a[0] = Shw[(m0 + g    ) * SHSTR + wc + tg    ];
            a[1] = Shw[(m0 + g + 8) * SHSTR + wc + tg    ];
            a[2] = Shw[(m0 + g    ) * SHSTR + wc + 4 + tg];
            a[3] = Shw[(m0 + g + 8) * SHSTR + wc + 4 + tg];
            uint32_t addr = kvbase + ((ks * 16 + (lane & 15)) * 72 + col0) * 2;
            ldmx2t(bb[0], bb[1], addr);
            mma_f16(acc, a, bb);
        }
    }
    float sc0 = invlS[m0 + g], sc1 = invlS[m0 + g + 8];
    #pragma unroll
    for (int half = 0; half < 2; half++) {
        int t = q0 + m0 + g + half * 8;
        int d = h * 64 + col0 + tg * 2;
        float s = half ? sc1 : sc0;
        __half2 hv;
        hv.x = __float2half_rn(acc[2 * half] * s);
        hv.y = __float2half_rn(acc[2 * half + 1] * s);
        *(__half2*)&y16[(size_t)(b * T_ + t) * C_ + d] = hv;
    }
}

// ---------------- launch ----------------------------------------------------
extern "C" void kernel_launch(void* const* d_in, const int* in_sizes, int n_in,
                              void* d_out, int out_size) {
    const float* x     = (const float*)d_in[0];
    const float* am    = (const float*)d_in[1];
    const float* ln1w  = (const float*)d_in[2];
    const float* ln1b  = (const float*)d_in[3];
    const float* wattn = (const float*)d_in[4];
    const float* battn = (const float*)d_in[5];
    const float* wproj = (const float*)d_in[6];
    const float* bproj = (const float*)d_in[7];
    const float* thr   = (const float*)d_in[8];
    const float* ln2w  = (const float*)d_in[9];
    const float* ln2b  = (const float*)d_in[10];
    const float* wfc   = (const float*)d_in[11];
    const float* bfc   = (const float*)d_in[12];
    const float* wfc2  = (const float*)d_in[13];
    const float* bfc2  = (const float*)d_in[14];

    float* out      = (float*)d_out;
    float* out_x    = out;
    float* out_mask = out + out_size - 1 - M_;
    float* out_loss = out + out_size - 1;

    float *px2, *pimp, *pmsk;
    cudaGetSymbolAddress((void**)&px2,  g_x2);
    cudaGetSymbolAddress((void**)&pimp, g_imp);
    cudaGetSymbolAddress((void**)&pmsk, g_msk);
    __half *pq16, *pk16, *pv16, *ph16, *py16, *pf16, *pwat, *pwpr, *pwfc, *pwf2;
    cudaGetSymbolAddress((void**)&pq16, g_q16);
    cudaGetSymbolAddress((void**)&pk16, g_k16);
    cudaGetSymbolAddress((void**)&pv16, g_v16);
    cudaGetSymbolAddress((void**)&ph16, g_h16);
    cudaGetSymbolAddress((void**)&py16, g_y16);
    cudaGetSymbolAddress((void**)&pf16, g_f16);
    cudaGetSymbolAddress((void**)&pwat, g_wat);
    cudaGetSymbolAddress((void**)&pwpr, g_wpr);
    cudaGetSymbolAddress((void**)&pwfc, g_wfc);
    cudaGetSymbolAddress((void**)&pwf2, g_wf2);

    static cudaStream_t sB = nullptr;
    static cudaEvent_t evFork = nullptr, evJoin = nullptr;
    static int smem_set = 0;
    if (!smem_set) {
        cudaFuncSetAttribute(fattn_kernel,
                             cudaFuncAttributeMaxDynamicSharedMemorySize, FA_SMEM);
        cudaFuncSetAttribute(tgemm_kernel<0>,
                             cudaFuncAttributeMaxDynamicSharedMemorySize, GEMM_SMEM);
        cudaFuncSetAttribute(tgemm_kernel<1>,
                             cudaFuncAttributeMaxDynamicSharedMemorySize, GEMM_SMEM);
        cudaFuncSetAttribute(tgemm_kernel<2>,
                             cudaFuncAttributeMaxDynamicSharedMemorySize, GEMM_SMEM);
        cudaFuncSetAttribute(tgemm_kernel<3>,
                             cudaFuncAttributeMaxDynamicSharedMemorySize, GEMM_SMEM);
        cudaStreamCreateWithFlags(&sB, cudaStreamNonBlocking);
        cudaEventCreateWithFlags(&evFork, cudaEventDisableTiming);
        cudaEventCreateWithFlags(&evJoin, cudaEventDisableTiming);
        smem_set = 1;
    }

    // fork: side stream prepares proj/fc/fc2 weights while main does LN+QKV+attn
    cudaEventRecord(evFork, 0);
    cudaStreamWaitEvent(sB, evFork, 0);
    prepB_kernel<<<9216, 256, 0, sB>>>(wproj, pwpr, wfc, pwfc, wfc2, pwf2);
    cudaEventRecord(evJoin, sB);

    prepA_kernel<<<3072, 256>>>(wattn, pwat, pimp);
    ln_kernel<<<M_, 256>>>(x, ln1w, ln1b, ph16);
    tgemm_kernel<0><<<dim3(NQKV/128, M_/128), 256, GEMM_SMEM>>>(
        ph16, pwat, battn, nullptr, nullptr, nullptr, M_, NQKV, C_);
    fattn_kernel<<<dim3(T_/QT, B_*H_), 512, FA_SMEM>>>(pq16, pk16, pv16, am, py16, pimp);
    mask_kernel<<<16, 256>>>(pimp, am, thr, pmsk, out_mask, out_loss);

    cudaStreamWaitEvent(0, evJoin, 0);   // join before proj GEMM needs pwpr
    tgemm_kernel<1><<<dim3(C_/128, M_/128), 256, GEMM_SMEM>>>(
        py16, pwpr, bproj, x, pmsk, px2, M_, C_, C_);
    ln_kernel<<<M_, 256>>>(px2, ln2w, ln2b, ph16);
    tgemm_kernel<2><<<dim3(NFC/128, M_/128), 256, GEMM_SMEM>>>(
        ph16, pwfc, bfc, nullptr, nullptr, nullptr, M_, NFC, C_);
    tgemm_kernel<3><<<dim3(C_/128, M_/128), 256, GEMM_SMEM>>>(
        pf16, pwf2, bfc2, px2, nullptr, out_x, M_, C_, NFC);
}

// round 12
// speedup vs baseline: 1.5408x; 1.3203x over previous
#include <cuda_runtime.h>
#include <cuda.h>
#include <cuda_fp16.h>
#include <math.h>
#include <stdint.h>

#define B_ 4
#define T_ 1024
#define C_ 1024
#define H_ 16
#define D_ 64
#define M_ (B_*T_)      /* 4096 rows */
#define NQKV 3072
#define NFC  4096

// ---------------- scratch (__device__ globals: no allocation allowed) -------
__device__ float g_x2 [M_*C_];
__device__ float g_imp[M_];
__device__ float g_msk[M_];
__device__ __half g_q16[M_*C_];
__device__ __half g_k16[M_*C_];
__device__ __half g_v16[M_*C_];
__device__ __half g_h16[M_*C_];
__device__ __half g_y16[M_*C_];
__device__ __half g_f16[(size_t)M_*NFC];
__device__ __half g_wat[C_*NQKV];
__device__ __half g_wpr[C_*C_];
__device__ __half g_wfc[(size_t)C_*NFC];
__device__ __half g_wf2[(size_t)NFC*C_];

// ---------------- helpers ---------------------------------------------------
__device__ __forceinline__ void mma_f16(float c[4], const uint32_t a[4], const uint32_t b[2]) {
    asm volatile(
        "mma.sync.aligned.m16n8k16.row.col.f32.f16.f16.f32 "
        "{%0,%1,%2,%3}, {%4,%5,%6,%7}, {%8,%9}, {%0,%1,%2,%3};"
        : "+f"(c[0]), "+f"(c[1]), "+f"(c[2]), "+f"(c[3])
        : "r"(a[0]), "r"(a[1]), "r"(a[2]), "r"(a[3]), "r"(b[0]), "r"(b[1]));
}
__device__ __forceinline__ uint32_t smem_u32(const void* p) {
    return (uint32_t)__cvta_generic_to_shared(p);
}
__device__ __forceinline__ void ldmx2t(uint32_t& r0, uint32_t& r1, uint32_t addr) {
    asm volatile("ldmatrix.sync.aligned.m8n8.x2.trans.shared.b16 {%0,%1}, [%2];"
                 : "=r"(r0), "=r"(r1) : "r"(addr));
}
__device__ __forceinline__ float fexp8(float x) {
    float t = x * 0.18033688011112042f;
    float z = t + 12582912.0f;
    int   iz = __float_as_int(z);
    float fi = z - 12582912.0f;
    float f  = t - fi;
    float p = 0.0096181291f;
    p = p * f + 0.0555041087f;
    p = p * f + 0.2402265069f;
    p = p * f + 0.6931471806f;
    p = p * f + 1.0f;
    return __int_as_float(__float_as_int(p) + (iz << 23));
}
__device__ __forceinline__ void mbar_init(uint32_t a, uint32_t n) {
    asm volatile("mbarrier.init.shared.b64 [%0], %1;" :: "r"(a), "r"(n) : "memory");
}
__device__ __forceinline__ void mbar_expect(uint32_t a, uint32_t bytes) {
    asm volatile("mbarrier.arrive.expect_tx.shared.b64 _, [%0], %1;"
                 :: "r"(a), "r"(bytes) : "memory");
}
__device__ __forceinline__ void mbar_wait(uint32_t a, uint32_t par) {
    asm volatile("{\n\t.reg .pred P;\n\tWL%=:\n\t"
                 "mbarrier.try_wait.parity.acquire.cta.shared::cta.b64 P, [%0], %1, 0x989680;\n\t"
                 "@P bra WD%=;\n\tbra WL%=;\n\tWD%=:\n\t}"
                 :: "r"(a), "r"(par) : "memory");
}
__device__ __forceinline__ void tma2d(uint32_t dst, const void* map, int cx, int cy,
                                      uint32_t mbar) {
    asm volatile("cp.async.bulk.tensor.2d.shared::cluster.global.tile.mbarrier::complete_tx::bytes "
                 "[%0], [%1, {%2, %3}], [%4];"
                 :: "r"(dst), "l"(map), "r"(cx), "r"(cy), "r"(mbar) : "memory");
}

// ---------------- small kernels --------------------------------------------
__global__ void mask_kernel(const float* __restrict__ imp,
                            const float* __restrict__ am,
                            const float* __restrict__ thr,
                            float* __restrict__ gmask,
                            float* __restrict__ outmask,
                            float* __restrict__ outloss) {
    int i = blockIdx.x * 256 + threadIdx.x;
    if (i < M_) {
        float pm = (imp[i] >= thr[0]) ? 1.f : 0.f;
        float cm = am[i] * pm;
        gmask[i]   = cm;
        outmask[i] = cm;
    }
    if (i == 0) outloss[0] = 0.f;
}

// ---------------- weight transpose tile (fp32 [K][N] -> fp16 [N][K]) --------
__device__ __forceinline__ void wtile(const float* __restrict__ W,
                                      __half* __restrict__ Oh,
                                      int K, int N, int bx, int by) {
    __shared__ float tile[32][33];
    int n0 = bx * 32, k0 = by * 32;
    int tx = threadIdx.x & 31, ty = threadIdx.x >> 5;
    #pragma unroll
    for (int i = 0; i < 4; i++)
        tile[ty + i * 8][tx] = W[(size_t)(k0 + ty + i * 8) * N + n0 + tx];
    __syncthreads();
    #pragma unroll
    for (int i = 0; i < 4; i++) {
        int n = n0 + ty + i * 8;
        Oh[(size_t)n * K + k0 + tx] = __float2half_rn(tile[tx][ty + i * 8]);
    }
}

__global__ void __launch_bounds__(256) prepA_kernel(const float* __restrict__ W,
                                                    __half* __restrict__ Oh,
                                                    float* __restrict__ imp) {
    int blk = blockIdx.x;
    if (blk < 16) imp[blk * 256 + threadIdx.x] = 0.f;
    wtile(W, Oh, C_, NQKV, blk % 96, blk / 96);
}

__global__ void __launch_bounds__(256) prepB_kernel(const float* __restrict__ Wpr,
                                                    __half* __restrict__ Opr,
                                                    const float* __restrict__ Wfc,
                                                    __half* __restrict__ Ofc,
                                                    const float* __restrict__ Wf2,
                                                    __half* __restrict__ Of2) {
    int blk = blockIdx.x;
    if (blk < 1024) {
        wtile(Wpr, Opr, C_, C_, blk % 32, blk / 32);
    } else if (blk < 5120) {
        int t = blk - 1024;
        wtile(Wfc, Ofc, C_, NFC, t % 128, t / 128);
    } else {
        int t = blk - 5120;
        wtile(Wf2, Of2, NFC, C_, t % 32, t / 32);
    }
}

// ---------------- layer norm -> fp16 ----------------------------------------
__global__ void __launch_bounds__(256) ln_kernel(const float* __restrict__ x,
                                                 const float* __restrict__ w,
                                                 const float* __restrict__ b,
                                                 __half* __restrict__ oh) {
    int row = blockIdx.x;
    int tid = threadIdx.x;
    __shared__ float buf[C_];
    __shared__ float red[8];
    const float* xr = x + (size_t)row * C_;
    float s = 0.f;
    #pragma unroll
    for (int j = tid; j < C_; j += 256) { float v = xr[j]; buf[j] = v; s += v; }
    #pragma unroll
    for (int o = 16; o; o >>= 1) s += __shfl_down_sync(~0u, s, o);
    if ((tid & 31) == 0) red[tid >> 5] = s;
    __syncthreads();
    if (tid < 8) {
        s = red[tid];
        #pragma unroll
        for (int o = 4; o; o >>= 1) s += __shfl_down_sync(0xff, s, o);
        if (tid == 0) red[0] = s;
    }
    __syncthreads();
    float mu = red[0] * (1.f / C_);
    __syncthreads();
    float ss = 0.f;
    #pragma unroll
    for (int j = tid; j < C_; j += 256) { float d = buf[j] - mu; ss += d * d; }
    #pragma unroll
    for (int o = 16; o; o >>= 1) ss += __shfl_down_sync(~0u, ss, o);
    if ((tid & 31) == 0) red[tid >> 5] = ss;
    __syncthreads();
    if (tid < 8) {
        ss = red[tid];
        #pragma unroll
        for (int o = 4; o; o >>= 1) ss += __shfl_down_sync(0xff, ss, o);
        if (tid == 0) red[0] = ss;
    }
    __syncthreads();
    float rstd = rsqrtf(red[0] * (1.f / C_) + 1e-5f);
    #pragma unroll
    for (int j = tid; j < C_; j += 256)
        oh[(size_t)row * C_ + j] = __float2half_rn((buf[j] - mu) * rstd * w[j] + b[j]);
}

// ---------------- fp16 GEMM with TMA stage loads ----------------------------
// A: fp16 [M][K]; B: fp16 [N][K] (transposed weights). Stages of K=32.
// TMA 2D box (32,128), SWIZZLE_64B -> smem rows 64B packed, XOR (g&6)<<1.
#define STG 4
#define STAGE_U32 4096                 /* 16KB per stage (A 8KB + B 8KB) */
#define GEMM_SMEM (STG*16384 + 32)     /* + 4 mbarriers */

template<int EPI>
__global__ void __launch_bounds__(256, 2) tcgemm_kernel(
    const __grid_constant__ CUtensorMap tmA,
    const __grid_constant__ CUtensorMap tmB,
    const float* __restrict__ bias, const float* __restrict__ res,
    const float* __restrict__ mask, float* __restrict__ Cout,
    int M, int N, int K)
{
    extern __shared__ uint32_t smu[];
    uint32_t sbase = smem_u32(smu);
    uint32_t mb0 = sbase + STG * 16384;
    int tid  = threadIdx.x;
    int lane = tid & 31;
    int wid  = tid >> 5;
    int warpM = wid >> 2, warpN = wid & 3;
    int g  = lane >> 2, tg = lane & 3;
    int xr = (g & 6) << 1;
    int row0 = blockIdx.y * 128, col0 = blockIdx.x * 128;

    if (tid == 0) {
        #pragma unroll
        for (int s = 0; s < STG; s++) mbar_init(mb0 + s * 8, 1);
    }
    __syncthreads();

    int nk = K >> 5;
    if (tid == 0) {
        #pragma unroll
        for (int p = 0; p < STG - 1; p++) {
            uint32_t mb = mb0 + p * 8;
            mbar_expect(mb, 16384);
            tma2d(sbase + p * 16384,        &tmA, p * 32, row0, mb);
            tma2d(sbase + p * 16384 + 8192, &tmB, p * 32, col0, mb);
        }
    }

    float acc[4][4][4] = {};
    int mBase = warpM * 64;
    int nBase = warpN * 32;

    for (int kt = 0; kt < nk; kt++) {
        int st = kt & (STG - 1);
        mbar_wait(mb0 + st * 8, (uint32_t)((kt >> 2) & 1));
        __syncthreads();
        if (tid == 0 && kt + STG - 1 < nk) {
            int tk = kt + STG - 1;
            int ts = tk & (STG - 1);
            uint32_t mb = mb0 + ts * 8;
            mbar_expect(mb, 16384);
            tma2d(sbase + ts * 16384,        &tmA, tk * 32, row0, mb);
            tma2d(sbase + ts * 16384 + 8192, &tmB, tk * 32, col0, mb);
        }
        const uint32_t* Ast = smu + st * STAGE_U32;
        const uint32_t* Bst = Ast + 2048;
        #pragma unroll
        for (int kk2 = 0; kk2 < 2; kk2++) {
            int c0 = ((kk2 * 8) + tg) ^ xr;
            int c1 = ((kk2 * 8) + tg + 4) ^ xr;
            uint32_t a[4][4], b[4][2];
            #pragma unroll
            for (int mi = 0; mi < 4; mi++) {
                int m = mBase + mi * 16 + g;
                a[mi][0] = Ast[(m << 4) + c0];
                a[mi][1] = Ast[((m + 8) << 4) + c0];
                a[mi][2] = Ast[(m << 4) + c1];
                a[mi][3] = Ast[((m + 8) << 4) + c1];
            }
            #pragma unroll
            for (int ni = 0; ni < 4; ni++) {
                int n = nBase + ni * 8 + g;
                b[ni][0] = Bst[(n << 4) + c0];
                b[ni][1] = Bst[(n << 4) + c1];
            }
            #pragma unroll
            for (int mi = 0; mi < 4; mi++)
                #pragma unroll
                for (int ni = 0; ni < 4; ni++)
                    mma_f16(acc[mi][ni], a[mi], b[ni]);
        }
    }

    // ---- epilogue ----
    #pragma unroll
    for (int mi = 0; mi < 4; mi++) {
        #pragma unroll
        for (int half = 0; half < 2; half++) {
            int ig = row0 + mBase + mi * 16 + g + half * 8;
            #pragma unroll
            for (int ni = 0; ni < 4; ni++) {
                float v0 = acc[mi][ni][2 * half + 0];
                float v1 = acc[mi][ni][2 * half + 1];
                int jg = col0 + nBase + ni * 8 + tg * 2;
                if (EPI == 0) {
                    int bq = ig >> 10, t = ig & 1023;
                    int part = jg >> 10;
                    int c = jg & 1023;
                    int h = c >> 6, d = c & 63;
                    __half2 hv;
                    hv.x = __float2half_rn(v0 + bias[jg]);
                    hv.y = __float2half_rn(v1 + bias[jg + 1]);
                    __half* dst = (part == 0) ? g_q16 : (part == 1) ? g_k16 : g_v16;
                    *(__half2*)&dst[((size_t)(bq * H_ + h) * T_ + t) * D_ + d] = hv;
                } else if (EPI == 1) {
                    float mrow = mask[ig];
                    Cout[(size_t)ig * N + jg]     = (res[(size_t)ig * N + jg]     + v0 + bias[jg])     * mrow;
                    Cout[(size_t)ig * N + jg + 1] = (res[(size_t)ig * N + jg + 1] + v1 + bias[jg + 1]) * mrow;
                } else if (EPI == 2) {
                    float a0 = v0 + bias[jg], a1 = v1 + bias[jg + 1];
                    float g0 = 0.5f * a0 * (1.f + erff(a0 * 0.70710678118654752f));
                    float g1 = 0.5f * a1 * (1.f + erff(a1 * 0.70710678118654752f));
                    __half2 hv; hv.x = __float2half_rn(g0); hv.y = __float2half_rn(g1);
                    *(__half2*)&g_f16[(size_t)ig * N + jg] = hv;
                } else {
                    Cout[(size_t)ig * N + jg]     = res[(size_t)ig * N + jg]     + v0 + bias[jg];
                    Cout[(size_t)ig * N + jg + 1] = res[(size_t)ig * N + jg + 1] + v1 + bias[jg + 1];
                }
            }
        }
    }
}

// ======================= FUSED FLASH ATTENTION (fp16, 2 CTA/SM) =============
#define QT 32
#define SHSTR 524
#define QSTR 36
#define KVSTR 36
#define OFF_Q    67072
#define OFF_KV   71680
#define OFF_AM   90112
#define OFF_INV  94208
#define OFF_PART 94336
#define FA_SMEM  95424

__global__ void __launch_bounds__(512, 2) fattn_kernel(
    const __half* __restrict__ q, const __half* __restrict__ k,
    const __half* __restrict__ v, const float* __restrict__ am,
    __half* __restrict__ y16, float* __restrict__ imp)
{
    extern __shared__ char smc[];
    uint32_t* Shw = (uint32_t*)smc;
    uint32_t* Qs  = (uint32_t*)(smc + OFF_Q);
    uint32_t* KVs = (uint32_t*)(smc + OFF_KV);
    float*    amS = (float*)(smc + OFF_AM);
    float*    invlS = (float*)(smc + OFF_INV);
    float*    part  = (float*)(smc + OFF_PART);

    int qt = gridDim.x - 1 - blockIdx.x;
    int bh = blockIdx.y;
    int b  = bh >> 4, h = bh & 15;
    int tid  = threadIdx.x;
    int lane = tid & 31;
    int wid  = tid >> 5;
    int g = lane >> 2, tg = lane & 3;

    int q0   = qt * QT;
    int kend = q0 + QT;
    int jmax = ((kend + 63) >> 6) << 6;

    const __half* qb = q + (size_t)bh * T_ * D_;
    const __half* kb = k + (size_t)bh * T_ * D_;
    const __half* vb = v + (size_t)bh * T_ * D_;

    if (tid < 256) {
        int row = tid >> 3, cs = tid & 7;
        uint4 val = *(const uint4*)(qb + (size_t)(q0 + row) * D_ + cs * 8);
        *(uint4*)&Qs[row * QSTR + cs * 4] = val;
    }
    for (int j = tid; j < T_; j += 512)
        amS[j] = (am[b * T_ + j] != 0.f) ? 1.f : 0.f;
    __syncthreads();

    int warpRow = wid >> 3;
    int warpCol = wid & 7;
    int m0 = warpRow * 16;

    uint32_t aq[4][4];
    #pragma unroll
    for (int ks = 0; ks < 4; ks++) {
        aq[ks][0] = Qs[(m0 + g    ) * QSTR + ks * 8 + tg    ];
        aq[ks][1] = Qs[(m0 + g + 8) * QSTR + ks * 8 + tg    ];
        aq[ks][2] = Qs[(m0 + g    ) * QSTR + ks * 8 + 4 + tg];
        aq[ks][3] = Qs[(m0 + g + 8) * QSTR + ks * 8 + 4 + tg];
    }

    int qg0 = q0 + m0 + g;
    int qg1 = qg0 + 8;
    float rs0 = 0.f, rs1 = 0.f;

    for (int kc0 = 0; kc0 < jmax; kc0 += 128) {
        int rows_here = min(128, jmax - kc0);
        bool interior = (kc0 + 127 <= q0);
        __syncthreads();
        for (int idx = tid; idx < rows_here * 8; idx += 512) {
            int r = idx >> 3, cs = idx & 7;
            uint4 val = *(const uint4*)(kb + (size_t)(kc0 + r) * D_ + cs * 8);
            *(uint4*)&KVs[r * KVSTR + cs * 4] = val;
        }
        __syncthreads();
        if (warpCol * 16 < rows_here) {
            float acc[2][4] = {};
            #pragma unroll
            for (int ks = 0; ks < 4; ks++) {
                #pragma unroll
                for (int f = 0; f < 2; f++) {
                    int n = warpCol * 16 + f * 8 + g;
                    uint32_t bb[2];
                    bb[0] = KVs[n * KVSTR + ks * 8 + tg    ];
                    bb[1] = KVs[n * KVSTR + ks * 8 + 4 + tg];
                    mma_f16(acc[f], aq[ks], bb);
                }
            }
            if (interior) {
                #pragma unroll
                for (int f = 0; f < 2; f++) {
                    int j0 = kc0 + warpCol * 16 + f * 8 + tg * 2;
                    float m0v = amS[j0], m1v = amS[j0 + 1];
                    float e00 = fexp8(acc[f][0]) * m0v;
                    float e01 = fexp8(acc[f][1]) * m1v;
                    float e10 = fexp8(acc[f][2]) * m0v;
                    float e11 = fexp8(acc[f][3]) * m1v;
                    rs0 += e00 + e01;
                    rs1 += e10 + e11;
                    __half2 p01 = __floats2half2_rn(e00, e01);
                    __half2 p23 = __floats2half2_rn(e10, e11);
                    int w0 = (j0 >> 1);
                    int r0 = m0 + g;
                    Shw[r0 * SHSTR + w0]       = *(uint32_t*)&p01;
                    Shw[(r0 + 8) * SHSTR + w0] = *(uint32_t*)&p23;
                }
            } else {
                #pragma unroll
                for (int f = 0; f < 2; f++) {
                    int j0 = kc0 + warpCol * 16 + f * 8 + tg * 2;
                    float m0v = amS[j0], m1v = amS[j0 + 1];
                    float e00 = (j0     <= qg0) ? fexp8(acc[f][0]) * m0v : 0.f;
                    float e01 = (j0 + 1 <= qg0) ? fexp8(acc[f][1]) * m1v : 0.f;
                    float e10 = (j0     <= qg1) ? fexp8(acc[f][2]) * m0v : 0.f;
                    float e11 = (j0 + 1 <= qg1) ? fexp8(acc[f][3]) * m1v : 0.f;
                    rs0 += e00 + e01;
                    rs1 += e10 + e11;
                    __half2 p01 = __floats2half2_rn(e00, e01);
                    __half2 p23 = __floats2half2_rn(e10, e11);
                    int w0 = (j0 >> 1);
                    int r0 = m0 + g;
                    Shw[r0 * SHSTR + w0]       = *(uint32_t*)&p01;
                    Shw[(r0 + 8) * SHSTR + w0] = *(uint32_t*)&p23;
                }
            }
        }
    }
    rs0 += __shfl_xor_sync(~0u, rs0, 1); rs0 += __shfl_xor_sync(~0u, rs0, 2);
    rs1 += __shfl_xor_sync(~0u, rs1, 1); rs1 += __shfl_xor_sync(~0u, rs1, 2);
    if (tg == 0) {
        part[wid * 17 + g]     = rs0;
        part[wid * 17 + g + 8] = rs1;
    }
    __syncthreads();
    if (tid < 32) {
        int wr = tid >> 4, lr = tid & 15;
        float s = 0.f;
        #pragma unroll
        for (int w = 0; w < 8; w++) s += part[(wr * 8 + w) * 17 + lr];
        invlS[tid] = 1.f / s;
    }
    __syncthreads();

    if (2 * tid < kend) {
        float cs0 = 0.f, cs1 = 0.f;
        #pragma unroll
        for (int r = 0; r < QT; r++) {
            uint32_t pw = Shw[r * SHSTR + tid];
            __half2 ph = *(__half2*)&pw;
            float wgt = invlS[r];
            cs0 += __half2float(ph.x) * wgt;
            cs1 += __half2float(ph.y) * wgt;
        }
        atomicAdd(&imp[b * T_ + 2 * tid],     cs0 * (1.f / (H_ * T_)));
        atomicAdd(&imp[b * T_ + 2 * tid + 1], cs1 * (1.f / (H_ * T_)));
    }

    int col0 = warpCol * 8;
    uint32_t kvbase = smem_u32(KVs);
    float acc[4] = {};
    for (int kc0 = 0; kc0 < jmax; kc0 += 128) {
        int rows_here = min(128, jmax - kc0);
        __syncthreads();
        for (int idx = tid; idx < rows_here * 8; idx += 512) {
            int r = idx >> 3, cs = idx & 7;
            uint4 val = *(const uint4*)(vb + (size_t)(kc0 + r) * D_ + cs * 8);
            *(uint4*)&KVs[r * KVSTR + cs * 4] = val;
        }
        __syncthreads();
        int ksteps = rows_here >> 4;
        for (int ks = 0; ks < ksteps; ks++) {
            int wc = ((kc0 + ks * 16) >> 1);
            uint32_t a[4], bb[2];
            a[0] = Shw[(m0 + g    ) * SHSTR + wc + tg    ];
            a[1] = Shw[(m0 + g + 8) * SHSTR + wc + tg    ];
            a[2] = Shw[(m0 + g    ) * SHSTR + wc + 4 + tg];
            a[3] = Shw[(m0 + g + 8) * SHSTR + wc + 4 + tg];
            uint32_t addr = kvbase + ((ks * 16 + (lane & 15)) * 72 + col0) * 2;
            ldmx2t(bb[0], bb[1], addr);
            mma_f16(acc, a, bb);
        }
    }
    float sc0 = invlS[m0 + g], sc1 = invlS[m0 + g + 8];
    #pragma unroll
    for (int half = 0; half < 2; half++) {
        int t = q0 + m0 + g + half * 8;
        int d = h * 64 + col0 + tg * 2;
        float s = half ? sc1 : sc0;
        __half2 hv;
        hv.x = __float2half_rn(acc[2 * half] * s);
        hv.y = __float2half_rn(acc[2 * half + 1] * s);
        *(__half2*)&y16[(size_t)(b * T_ + t) * C_ + d] = hv;
    }
}

// ---------------- launch ----------------------------------------------------
typedef CUresult (*EncodeFn)(CUtensorMap*, CUtensorMapDataType, cuuint32_t, void*,
                             const cuuint64_t*, const cuuint64_t*, const cuuint32_t*,
                             const cuuint32_t*, CUtensorMapInterleave, CUtensorMapSwizzle,
                             CUtensorMapL2promotion, CUtensorMapFloatOOBfill);

static void make_map(EncodeFn fn, CUtensorMap* m, void* addr, uint64_t K, uint64_t rows) {
    cuuint64_t dims[2]    = {K, rows};
    cuuint64_t strides[1] = {K * 2};
    cuuint32_t box[2]     = {32, 128};
    cuuint32_t estr[2]    = {1, 1};
    fn(m, CU_TENSOR_MAP_DATA_TYPE_UINT16, 2, addr, dims, strides, box, estr,
       CU_TENSOR_MAP_INTERLEAVE_NONE, CU_TENSOR_MAP_SWIZZLE_64B,
       CU_TENSOR_MAP_L2_PROMOTION_L2_128B, CU_TENSOR_MAP_FLOAT_OOB_FILL_NONE);
}

extern "C" void kernel_launch(void* const* d_in, const int* in_sizes, int n_in,
                              void* d_out, int out_size) {
    const float* x     = (const float*)d_in[0];
    const float* am    = (const float*)d_in[1];
    const float* ln1w  = (const float*)d_in[2];
    const float* ln1b  = (const float*)d_in[3];
    const float* wattn = (const float*)d_in[4];
    const float* battn = (const float*)d_in[5];
    const float* wproj = (const float*)d_in[6];
    const float* bproj = (const float*)d_in[7];
    const float* thr   = (const float*)d_in[8];
    const float* ln2w  = (const float*)d_in[9];
    const float* ln2b  = (const float*)d_in[10];
    const float* wfc   = (const float*)d_in[11];
    const float* bfc   = (const float*)d_in[12];
    const float* wfc2  = (const float*)d_in[13];
    const float* bfc2  = (const float*)d_in[14];

    float* out      = (float*)d_out;
    float* out_x    = out;
    float* out_mask = out + out_size - 1 - M_;
    float* out_loss = out + out_size - 1;

    float *px2, *pimp, *pmsk;
    cudaGetSymbolAddress((void**)&px2,  g_x2);
    cudaGetSymbolAddress((void**)&pimp, g_imp);
    cudaGetSymbolAddress((void**)&pmsk, g_msk);
    __half *pq16, *pk16, *pv16, *ph16, *py16, *pf16, *pwat, *pwpr, *pwfc, *pwf2;
    cudaGetSymbolAddress((void**)&pq16, g_q16);
    cudaGetSymbolAddress((void**)&pk16, g_k16);
    cudaGetSymbolAddress((void**)&pv16, g_v16);
    cudaGetSymbolAddress((void**)&ph16, g_h16);
    cudaGetSymbolAddress((void**)&py16, g_y16);
    cudaGetSymbolAddress((void**)&pf16, g_f16);
    cudaGetSymbolAddress((void**)&pwat, g_wat);
    cudaGetSymbolAddress((void**)&pwpr, g_wpr);
    cudaGetSymbolAddress((void**)&pwfc, g_wfc);
    cudaGetSymbolAddress((void**)&pwf2, g_wf2);

    static cudaStream_t sB = nullptr;
    static cudaEvent_t evFork = nullptr, evJoin = nullptr;
    static CUtensorMap tmA_h, tmA_y, tmA_f, tmB_at, tmB_pr, tmB_fc, tmB_f2;
    static int init_done = 0;
    if (!init_done) {
        cudaFuncSetAttribute(fattn_kernel,
                             cudaFuncAttributeMaxDynamicSharedMemorySize, FA_SMEM);
        cudaFuncSetAttribute(tcgemm_kernel<0>,
                             cudaFuncAttributeMaxDynamicSharedMemorySize, GEMM_SMEM);
        cudaFuncSetAttribute(tcgemm_kernel<1>,
                             cudaFuncAttributeMaxDynamicSharedMemorySize, GEMM_SMEM);
        cudaFuncSetAttribute(tcgemm_kernel<2>,
                             cudaFuncAttributeMaxDynamicSharedMemorySize, GEMM_SMEM);
        cudaFuncSetAttribute(tcgemm_kernel<3>,
                             cudaFuncAttributeMaxDynamicSharedMemorySize, GEMM_SMEM);
        cudaStreamCreateWithFlags(&sB, cudaStreamNonBlocking);
        cudaEventCreateWithFlags(&evFork, cudaEventDisableTiming);
        cudaEventCreateWithFlags(&evJoin, cudaEventDisableTiming);

        EncodeFn fn = nullptr;
        cudaDriverEntryPointQueryResult qres;
        cudaGetDriverEntryPoint("cuTensorMapEncodeTiled", (void**)&fn,
                                cudaEnableDefault, &qres);
        make_map(fn, &tmA_h,  ph16, 1024, 4096);
        make_map(fn, &tmA_y,  py16, 1024, 4096);
        make_map(fn, &tmA_f,  pf16, 4096, 4096);
        make_map(fn, &tmB_at, pwat, 1024, 3072);
        make_map(fn, &tmB_pr, pwpr, 1024, 1024);
        make_map(fn, &tmB_fc, pwfc, 1024, 4096);
        make_map(fn, &tmB_f2, pwf2, 4096, 1024);
        init_done = 1;
    }

    cudaEventRecord(evFork, 0);
    cudaStreamWaitEvent(sB, evFork, 0);
    prepB_kernel<<<9216, 256, 0, sB>>>(wproj, pwpr, wfc, pwfc, wfc2, pwf2);
    cudaEventRecord(evJoin, sB);

    prepA_kernel<<<3072, 256>>>(wattn, pwat, pimp);
    ln_kernel<<<M_, 256>>>(x, ln1w, ln1b, ph16);
    tcgemm_kernel<0><<<dim3(NQKV/128, M_/128), 256, GEMM_SMEM>>>(
        tmA_h, tmB_at, battn, nullptr, nullptr, nullptr, M_, NQKV, C_);
    fattn_kernel<<<dim3(T_/QT, B_*H_), 512, FA_SMEM>>>(pq16, pk16, pv16, am, py16, pimp);
    mask_kernel<<<16, 256>>>(pimp, am, thr, pmsk, out_mask, out_loss);

    cudaStreamWaitEvent(0, evJoin, 0);
    tcgemm_kernel<1><<<dim3(C_/128, M_/128), 256, GEMM_SMEM>>>(
        tmA_y, tmB_pr, bproj, x, pmsk, px2, M_, C_, C_);
    ln_kernel<<<M_, 256>>>(px2, ln2w, ln2b, ph16);
    tcgemm_kernel<2><<<dim3(NFC/128, M_/128), 256, GEMM_SMEM>>>(
        tmA_h, tmB_fc, bfc, nullptr, nullptr, nullptr, M_, NFC, C_);
    tcgemm_kernel<3><<<dim3(C_/128, M_/128), 256, GEMM_SMEM>>>(
        tmA_f, tmB_f2, bfc2, px2, nullptr, out_x, M_, C_, NFC);
}

// round 13
// speedup vs baseline: 1.5967x; 1.0363x over previous
#include <cuda_runtime.h>
#include <cuda.h>
#include <cuda_fp16.h>
#include <math.h>
#include <stdint.h>

#define B_ 4
#define T_ 1024
#define C_ 1024
#define H_ 16
#define D_ 64
#define M_ (B_*T_)      /* 4096 rows */
#define NQKV 3072
#define NFC  4096

// ---------------- scratch (__device__ globals: no allocation allowed) -------
__device__ float g_x2 [M_*C_];
__device__ float g_imp[M_];
__device__ float g_msk[M_];
__device__ __half g_q16[M_*C_];
__device__ __half g_k16[M_*C_];
__device__ __half g_v16[M_*C_];
__device__ __half g_h16[M_*C_];
__device__ __half g_y16[M_*C_];
__device__ __half g_f16[(size_t)M_*NFC];
__device__ __half g_wat[C_*NQKV];
__device__ __half g_wpr[C_*C_];
__device__ __half g_wfc[(size_t)C_*NFC];
__device__ __half g_wf2[(size_t)NFC*C_];

// ---------------- helpers ---------------------------------------------------
__device__ __forceinline__ void mma_f16(float c[4], const uint32_t a[4], const uint32_t b[2]) {
    asm volatile(
        "mma.sync.aligned.m16n8k16.row.col.f32.f16.f16.f32 "
        "{%0,%1,%2,%3}, {%4,%5,%6,%7}, {%8,%9}, {%0,%1,%2,%3};"
        : "+f"(c[0]), "+f"(c[1]), "+f"(c[2]), "+f"(c[3])
        : "r"(a[0]), "r"(a[1]), "r"(a[2]), "r"(a[3]), "r"(b[0]), "r"(b[1]));
}
__device__ __forceinline__ uint32_t smem_u32(const void* p) {
    return (uint32_t)__cvta_generic_to_shared(p);
}
__device__ __forceinline__ void ldmx4(uint32_t* r, uint32_t addr) {
    asm volatile("ldmatrix.sync.aligned.m8n8.x4.shared.b16 {%0,%1,%2,%3}, [%4];"
                 : "=r"(r[0]), "=r"(r[1]), "=r"(r[2]), "=r"(r[3]) : "r"(addr));
}
__device__ __forceinline__ void ldmx2(uint32_t& r0, uint32_t& r1, uint32_t addr) {
    asm volatile("ldmatrix.sync.aligned.m8n8.x2.shared.b16 {%0,%1}, [%2];"
                 : "=r"(r0), "=r"(r1) : "r"(addr));
}
__device__ __forceinline__ void ldmx2t(uint32_t& r0, uint32_t& r1, uint32_t addr) {
    asm volatile("ldmatrix.sync.aligned.m8n8.x2.trans.shared.b16 {%0,%1}, [%2];"
                 : "=r"(r0), "=r"(r1) : "r"(addr));
}
__device__ __forceinline__ float fexp8(float x) {
    float t = x * 0.18033688011112042f;
    float z = t + 12582912.0f;
    int   iz = __float_as_int(z);
    float fi = z - 12582912.0f;
    float f  = t - fi;
    float p = 0.0096181291f;
    p = p * f + 0.0555041087f;
    p = p * f + 0.2402265069f;
    p = p * f + 0.6931471806f;
    p = p * f + 1.0f;
    return __int_as_float(__float_as_int(p) + (iz << 23));
}
__device__ __forceinline__ void mbar_init(uint32_t a, uint32_t n) {
    asm volatile("mbarrier.init.shared.b64 [%0], %1;" :: "r"(a), "r"(n) : "memory");
}
__device__ __forceinline__ void mbar_expect(uint32_t a, uint32_t bytes) {
    asm volatile("mbarrier.arrive.expect_tx.shared.b64 _, [%0], %1;"
                 :: "r"(a), "r"(bytes) : "memory");
}
__device__ __forceinline__ void mbar_wait(uint32_t a, uint32_t par) {
    asm volatile("{\n\t.reg .pred P;\n\tWL%=:\n\t"
                 "mbarrier.try_wait.parity.acquire.cta.shared::cta.b64 P, [%0], %1, 0x989680;\n\t"
                 "@P bra WD%=;\n\tbra WL%=;\n\tWD%=:\n\t}"
                 :: "r"(a), "r"(par) : "memory");
}
__device__ __forceinline__ void tma2d(uint32_t dst, const void* map, int cx, int cy,
                                      uint32_t mbar) {
    asm volatile("cp.async.bulk.tensor.2d.shared::cluster.global.tile.mbarrier::complete_tx::bytes "
                 "[%0], [%1, {%2, %3}], [%4];"
                 :: "r"(dst), "l"(map), "r"(cx), "r"(cy), "r"(mbar) : "memory");
}

// ---------------- small kernels --------------------------------------------
__global__ void mask_kernel(const float* __restrict__ imp,
                            const float* __restrict__ am,
                            const float* __restrict__ thr,
                            float* __restrict__ gmask,
                            float* __restrict__ outmask,
                            float* __restrict__ outloss) {
    int i = blockIdx.x * 256 + threadIdx.x;
    if (i < M_) {
        float pm = (imp[i] >= thr[0]) ? 1.f : 0.f;
        float cm = am[i] * pm;
        gmask[i]   = cm;
        outmask[i] = cm;
    }
    if (i == 0) outloss[0] = 0.f;
}

// ---------------- weight transpose tile (fp32 [K][N] -> fp16 [N][K]) --------
__device__ __forceinline__ void wtile(const float* __restrict__ W,
                                      __half* __restrict__ Oh,
                                      int K, int N, int bx, int by) {
    __shared__ float tile[32][33];
    int n0 = bx * 32, k0 = by * 32;
    int tx = threadIdx.x & 31, ty = threadIdx.x >> 5;
    #pragma unroll
    for (int i = 0; i < 4; i++)
        tile[ty + i * 8][tx] = W[(size_t)(k0 + ty + i * 8) * N + n0 + tx];
    __syncthreads();
    #pragma unroll
    for (int i = 0; i < 4; i++) {
        int n = n0 + ty + i * 8;
        Oh[(size_t)n * K + k0 + tx] = __float2half_rn(tile[tx][ty + i * 8]);
    }
}

__global__ void __launch_bounds__(256) prepA_kernel(const float* __restrict__ W,
                                                    __half* __restrict__ Oh,
                                                    float* __restrict__ imp) {
    int blk = blockIdx.x;
    if (blk < 16) imp[blk * 256 + threadIdx.x] = 0.f;
    wtile(W, Oh, C_, NQKV, blk % 96, blk / 96);
}

__global__ void __launch_bounds__(256) prepB_kernel(const float* __restrict__ Wpr,
                                                    __half* __restrict__ Opr,
                                                    const float* __restrict__ Wfc,
                                                    __half* __restrict__ Ofc,
                                                    const float* __restrict__ Wf2,
                                                    __half* __restrict__ Of2) {
    int blk = blockIdx.x;
    if (blk < 1024) {
        wtile(Wpr, Opr, C_, C_, blk % 32, blk / 32);
    } else if (blk < 5120) {
        int t = blk - 1024;
        wtile(Wfc, Ofc, C_, NFC, t % 128, t / 128);
    } else {
        int t = blk - 5120;
        wtile(Wf2, Of2, NFC, C_, t % 32, t / 32);
    }
}

// ---------------- layer norm -> fp16 ----------------------------------------
__global__ void __launch_bounds__(256) ln_kernel(const float* __restrict__ x,
                                                 const float* __restrict__ w,
                                                 const float* __restrict__ b,
                                                 __half* __restrict__ oh) {
    int row = blockIdx.x;
    int tid = threadIdx.x;
    __shared__ float buf[C_];
    __shared__ float red[8];
    const float* xr = x + (size_t)row * C_;
    float s = 0.f;
    #pragma unroll
    for (int j = tid; j < C_; j += 256) { float v = xr[j]; buf[j] = v; s += v; }
    #pragma unroll
    for (int o = 16; o; o >>= 1) s += __shfl_down_sync(~0u, s, o);
    if ((tid & 31) == 0) red[tid >> 5] = s;
    __syncthreads();
    if (tid < 8) {
        s = red[tid];
        #pragma unroll
        for (int o = 4; o; o >>= 1) s += __shfl_down_sync(0xff, s, o);
        if (tid == 0) red[0] = s;
    }
    __syncthreads();
    float mu = red[0] * (1.f / C_);
    __syncthreads();
    float ss = 0.f;
    #pragma unroll
    for (int j = tid; j < C_; j += 256) { float d = buf[j] - mu; ss += d * d; }
    #pragma unroll
    for (int o = 16; o; o >>= 1) ss += __shfl_down_sync(~0u, ss, o);
    if ((tid & 31) == 0) red[tid >> 5] = ss;
    __syncthreads();
    if (tid < 8) {
        ss = red[tid];
        #pragma unroll
        for (int o = 4; o; o >>= 1) ss += __shfl_down_sync(0xff, ss, o);
        if (tid == 0) red[0] = ss;
    }
    __syncthreads();
    float rstd = rsqrtf(red[0] * (1.f / C_) + 1e-5f);
    #pragma unroll
    for (int j = tid; j < C_; j += 256)
        oh[(size_t)row * C_ + j] = __float2half_rn((buf[j] - mu) * rstd * w[j] + b[j]);
}

// ---------------- fp16 GEMM with TMA stage loads + ldmatrix fragments -------
#define STG 4
#define GEMM_SMEM (STG*16384 + 32)

template<int EPI>
__global__ void __launch_bounds__(256, 2) tcgemm_kernel(
    const __grid_constant__ CUtensorMap tmA,
    const __grid_constant__ CUtensorMap tmB,
    const float* __restrict__ bias, const float* __restrict__ res,
    const float* __restrict__ mask, float* __restrict__ Cout,
    int M, int N, int K)
{
    extern __shared__ uint32_t smu[];
    uint32_t sbase = smem_u32(smu);
    uint32_t mb0 = sbase + STG * 16384;
    int tid  = threadIdx.x;
    int lane = tid & 31;
    int wid  = tid >> 5;
    int warpM = wid >> 2, warpN = wid & 3;
    int g  = lane >> 2, tg = lane & 3;
    int row0 = blockIdx.y * 128, col0 = blockIdx.x * 128;

    if (tid == 0) {
        #pragma unroll
        for (int s = 0; s < STG; s++) mbar_init(mb0 + s * 8, 1);
    }
    __syncthreads();

    int nk = K >> 5;
    if (tid == 0) {
        #pragma unroll
        for (int p = 0; p < STG - 1; p++) {
            uint32_t mb = mb0 + p * 8;
            mbar_expect(mb, 16384);
            tma2d(sbase + p * 16384,        &tmA, p * 32, row0, mb);
            tma2d(sbase + p * 16384 + 8192, &tmB, p * 32, col0, mb);
        }
    }

    int mBase = warpM * 64;
    int nBase = warpN * 32;

    // --- precomputed ldmatrix byte offsets (SW64 row-XOR folded in) ---
    // A x4: lane groups 0-7/8-15/16-23/24-31 -> (m,klo)/(m+8,klo)/(m,khi)/(m+8,khi)
    int rl = lane & 7;
    int qh = (lane >> 3) & 1;     // +8 rows for matrices 1,3
    int qc = lane >> 4;           // +1 chunk for matrices 2,3
    uint32_t offA[4], offB[4];
    #pragma unroll
    for (int mi = 0; mi < 4; mi++) {
        int r = mBase + mi * 16 + rl + qh * 8;
        offA[mi] = (uint32_t)(r * 64 + ((qc ^ ((r >> 1) & 3)) << 4));
    }
    // B x2: lanes 0-7 matrix0 (klo), 8-15 matrix1 (khi)
    int qb = (lane >> 3) & 1;
    #pragma unroll
    for (int ni = 0; ni < 4; ni++) {
        int r = nBase + ni * 8 + rl;
        offB[ni] = (uint32_t)(r * 64 + ((qb ^ ((r >> 1) & 3)) << 4));
    }

    float acc[4][4][4] = {};

    for (int kt = 0; kt < nk; kt++) {
        int st = kt & (STG - 1);
        mbar_wait(mb0 + st * 8, (uint32_t)((kt >> 2) & 1));
        __syncthreads();
        if (tid == 0 && kt + STG - 1 < nk) {
            int tk = kt + STG - 1;
            int ts = tk & (STG - 1);
            uint32_t mb = mb0 + ts * 8;
            mbar_expect(mb, 16384);
            tma2d(sbase + ts * 16384,        &tmA, tk * 32, row0, mb);
            tma2d(sbase + ts * 16384 + 8192, &tmB, tk * 32, col0, mb);
        }
        uint32_t stA = sbase + st * 16384;
        uint32_t stB = stA + 8192;
        #pragma unroll
        for (int kk2 = 0; kk2 < 2; kk2++) {
            uint32_t xv = kk2 * 32;      // chunk+2 under SW64 == byte ^32
            uint32_t a[4][4], b[4][2];
            #pragma unroll
            for (int mi = 0; mi < 4; mi++) ldmx4(a[mi], stA + (offA[mi] ^ xv));
            #pragma unroll
            for (int ni = 0; ni < 4; ni++) ldmx2(b[ni][0], b[ni][1], stB + (offB[ni] ^ xv));
            #pragma unroll
            for (int mi = 0; mi < 4; mi++)
                #pragma unroll
                for (int ni = 0; ni < 4; ni++)
                    mma_f16(acc[mi][ni], a[mi], b[ni]);
        }
    }

    // ---- epilogue ----
    #pragma unroll
    for (int mi = 0; mi < 4; mi++) {
        #pragma unroll
        for (int half = 0; half < 2; half++) {
            int ig = row0 + mBase + mi * 16 + g + half * 8;
            #pragma unroll
            for (int ni = 0; ni < 4; ni++) {
                float v0 = acc[mi][ni][2 * half + 0];
                float v1 = acc[mi][ni][2 * half + 1];
                int jg = col0 + nBase + ni * 8 + tg * 2;
                if (EPI == 0) {
                    int bq = ig >> 10, t = ig & 1023;
                    int part = jg >> 10;
                    int c = jg & 1023;
                    int h = c >> 6, d = c & 63;
                    __half2 hv;
                    hv.x = __float2half_rn(v0 + bias[jg]);
                    hv.y = __float2half_rn(v1 + bias[jg + 1]);
                    __half* dst = (part == 0) ? g_q16 : (part == 1) ? g_k16 : g_v16;
                    *(__half2*)&dst[((size_t)(bq * H_ + h) * T_ + t) * D_ + d] = hv;
                } else if (EPI == 1) {
                    float mrow = mask[ig];
                    Cout[(size_t)ig * N + jg]     = (res[(size_t)ig * N + jg]     + v0 + bias[jg])     * mrow;
                    Cout[(size_t)ig * N + jg + 1] = (res[(size_t)ig * N + jg + 1] + v1 + bias[jg + 1]) * mrow;
                } else if (EPI == 2) {
                    float a0 = v0 + bias[jg], a1 = v1 + bias[jg + 1];
                    float g0 = 0.5f * a0 * (1.f + erff(a0 * 0.70710678118654752f));
                    float g1 = 0.5f * a1 * (1.f + erff(a1 * 0.70710678118654752f));
                    __half2 hv; hv.x = __float2half_rn(g0); hv.y = __float2half_rn(g1);
                    *(__half2*)&g_f16[(size_t)ig * N + jg] = hv;
                } else {
                    Cout[(size_t)ig * N + jg]     = res[(size_t)ig * N + jg]     + v0 + bias[jg];
                    Cout[(size_t)ig * N + jg + 1] = res[(size_t)ig * N + jg + 1] + v1 + bias[jg + 1];
                }
            }
        }
    }
}

// ======================= FUSED FLASH ATTENTION (fp16, 2 CTA/SM) =============
#define QT 32
#define SHSTR 524
#define QSTR 36
#define KVSTR 36
#define OFF_Q    67072
#define OFF_KV   71680
#define OFF_AM   90112
#define OFF_INV  94208
#define OFF_PART 94336
#define FA_SMEM  95424

__global__ void __launch_bounds__(512, 2) fattn_kernel(
    const __half* __restrict__ q, const __half* __restrict__ k,
    const __half* __restrict__ v, const float* __restrict__ am,
    __half* __restrict__ y16, float* __restrict__ imp)
{
    extern __shared__ char smc[];
    uint32_t* Shw = (uint32_t*)smc;
    uint32_t* Qs  = (uint32_t*)(smc + OFF_Q);
    uint32_t* KVs = (uint32_t*)(smc + OFF_KV);
    float*    amS = (float*)(smc + OFF_AM);
    float*    invlS = (float*)(smc + OFF_INV);
    float*    part  = (float*)(smc + OFF_PART);

    int qt = gridDim.x - 1 - blockIdx.x;
    int bh = blockIdx.y;
    int b  = bh >> 4, h = bh & 15;
    int tid  = threadIdx.x;
    int lane = tid & 31;
    int wid  = tid >> 5;
    int g = lane >> 2, tg = lane & 3;

    int q0   = qt * QT;
    int kend = q0 + QT;
    int jmax = ((kend + 63) >> 6) << 6;

    const __half* qb = q + (size_t)bh * T_ * D_;
    const __half* kb = k + (size_t)bh * T_ * D_;
    const __half* vb = v + (size_t)bh * T_ * D_;

    if (tid < 256) {
        int row = tid >> 3, cs = tid & 7;
        uint4 val = *(const uint4*)(qb + (size_t)(q0 + row) * D_ + cs * 8);
        *(uint4*)&Qs[row * QSTR + cs * 4] = val;
    }
    for (int j = tid; j < T_; j += 512)
        amS[j] = (am[b * T_ + j] != 0.f) ? 1.f : 0.f;
    __syncthreads();

    int warpRow = wid >> 3;
    int warpCol = wid & 7;
    int m0 = warpRow * 16;

    uint32_t aq[4][4];
    #pragma unroll
    for (int ks = 0; ks < 4; ks++) {
        aq[ks][0] = Qs[(m0 + g    ) * QSTR + ks * 8 + tg    ];
        aq[ks][1] = Qs[(m0 + g + 8) * QSTR + ks * 8 + tg    ];
        aq[ks][2] = Qs[(m0 + g    ) * QSTR + ks * 8 + 4 + tg];
        aq[ks][3] = Qs[(m0 + g + 8) * QSTR + ks * 8 + 4 + tg];
    }

    int qg0 = q0 + m0 + g;
    int qg1 = qg0 + 8;
    float rs0 = 0.f, rs1 = 0.f;
    uint32_t kvbase = smem_u32(KVs);
    // phase-1 B ldmatrix offsets: lanes 0-7 matrix0 (k lo), 8-15 matrix1 (k hi)
    int rl = lane & 7, qb2 = (lane >> 3) & 1;
    uint32_t offK[2];
    #pragma unroll
    for (int f = 0; f < 2; f++)
        offK[f] = (uint32_t)((warpCol * 16 + f * 8 + rl) * 144 + qb2 * 16);

    for (int kc0 = 0; kc0 < jmax; kc0 += 128) {
        int rows_here = min(128, jmax - kc0);
        bool interior = (kc0 + 127 <= q0);
        __syncthreads();
        for (int idx = tid; idx < rows_here * 8; idx += 512) {
            int r = idx >> 3, cs = idx & 7;
            uint4 val = *(const uint4*)(kb + (size_t)(kc0 + r) * D_ + cs * 8);
            *(uint4*)&KVs[r * KVSTR + cs * 4] = val;
        }
        __syncthreads();
        if (warpCol * 16 < rows_here) {
            float acc[2][4] = {};
            #pragma unroll
            for (int ks = 0; ks < 4; ks++) {
                #pragma unroll
                for (int f = 0; f < 2; f++) {
                    uint32_t bb0, bb1;
                    ldmx2(bb0, bb1, kvbase + offK[f] + ks * 32);
                    uint32_t bb[2] = {bb0, bb1};
                    mma_f16(acc[f], aq[ks], bb);
                }
            }
            if (interior) {
                #pragma unroll
                for (int f = 0; f < 2; f++) {
                    int j0 = kc0 + warpCol * 16 + f * 8 + tg * 2;
                    float m0v = amS[j0], m1v = amS[j0 + 1];
                    float e00 = fexp8(acc[f][0]) * m0v;
                    float e01 = fexp8(acc[f][1]) * m1v;
                    float e10 = fexp8(acc[f][2]) * m0v;
                    float e11 = fexp8(acc[f][3]) * m1v;
                    rs0 += e00 + e01;
                    rs1 += e10 + e11;
                    __half2 p01 = __floats2half2_rn(e00, e01);
                    __half2 p23 = __floats2half2_rn(e10, e11);
                    int w0 = (j0 >> 1);
                    int r0 = m0 + g;
                    Shw[r0 * SHSTR + w0]       = *(uint32_t*)&p01;
                    Shw[(r0 + 8) * SHSTR + w0] = *(uint32_t*)&p23;
                }
            } else {
                #pragma unroll
                for (int f = 0; f < 2; f++) {
                    int j0 = kc0 + warpCol * 16 + f * 8 + tg * 2;
                    float m0v = amS[j0], m1v = amS[j0 + 1];
                    float e00 = (j0     <= qg0) ? fexp8(acc[f][0]) * m0v : 0.f;
                    float e01 = (j0 + 1 <= qg0) ? fexp8(acc[f][1]) * m1v : 0.f;
                    float e10 = (j0     <= qg1) ? fexp8(acc[f][2]) * m0v : 0.f;
                    float e11 = (j0 + 1 <= qg1) ? fexp8(acc[f][3]) * m1v : 0.f;
                    rs0 += e00 + e01;
                    rs1 += e10 + e11;
                    __half2 p01 = __floats2half2_rn(e00, e01);
                    __half2 p23 = __floats2half2_rn(e10, e11);
                    int w0 = (j0 >> 1);
                    int r0 = m0 + g;
                    Shw[r0 * SHSTR + w0]       = *(uint32_t*)&p01;
                    Shw[(r0 + 8) * SHSTR + w0] = *(uint32_t*)&p23;
                }
            }
        }
    }
    rs0 += __shfl_xor_sync(~0u, rs0, 1); rs0 += __shfl_xor_sync(~0u, rs0, 2);
    rs1 += __shfl_xor_sync(~0u, rs1, 1); rs1 += __shfl_xor_sync(~0u, rs1, 2);
    if (tg == 0) {
        part[wid * 17 + g]     = rs0;
        part[wid * 17 + g + 8] = rs1;
    }
    __syncthreads();
    if (tid < 32) {
        int wr = tid >> 4, lr = tid & 15;
        float s = 0.f;
        #pragma unroll
        for (int w = 0; w < 8; w++) s += part[(wr * 8 + w) * 17 + lr];
        invlS[tid] = 1.f / s;
    }
    __syncthreads();

    if (2 * tid < kend) {
        float cs0 = 0.f, cs1 = 0.f;
        #pragma unroll
        for (int r = 0; r < QT; r++) {
            uint32_t pw = Shw[r * SHSTR + tid];
            __half2 ph = *(__half2*)&pw;
            float wgt = invlS[r];
            cs0 += __half2float(ph.x) * wgt;
            cs1 += __half2float(ph.y) * wgt;
        }
        atomicAdd(&imp[b * T_ + 2 * tid],     cs0 * (1.f / (H_ * T_)));
        atomicAdd(&imp[b * T_ + 2 * tid + 1], cs1 * (1.f / (H_ * T_)));
    }

    int col0 = warpCol * 8;
    float acc[4] = {};
    for (int kc0 = 0; kc0 < jmax; kc0 += 128) {
        int rows_here = min(128, jmax - kc0);
        __syncthreads();
        for (int idx = tid; idx < rows_here * 8; idx += 512) {
            int r = idx >> 3, cs = idx & 7;
            uint4 val = *(const uint4*)(vb + (size_t)(kc0 + r) * D_ + cs * 8);
            *(uint4*)&KVs[r * KVSTR + cs * 4] = val;
        }
        __syncthreads();
        int ksteps = rows_here >> 4;
        for (int ks = 0; ks < ksteps; ks++) {
            int wc = ((kc0 + ks * 16) >> 1);
            uint32_t a[4], bb[2];
            a[0] = Shw[(m0 + g    ) * SHSTR + wc + tg    ];
            a[1] = Shw[(m0 + g + 8) * SHSTR + wc + tg    ];
            a[2] = Shw[(m0 + g    ) * SHSTR + wc + 4 + tg];
            a[3] = Shw[(m0 + g + 8) * SHSTR + wc + 4 + tg];
            uint32_t addr = kvbase + ((ks * 16 + (lane & 15)) * 72 + col0) * 2;
            ldmx2t(bb[0], bb[1], addr);
            mma_f16(acc, a, bb);
        }
    }
    float sc0 = invlS[m0 + g], sc1 = invlS[m0 + g + 8];
    #pragma unroll
    for (int half = 0; half < 2; half++) {
        int t = q0 + m0 + g + half * 8;
        int d = h * 64 + col0 + tg * 2;
        float s = half ? sc1 : sc0;
        __half2 hv;
        hv.x = __float2half_rn(acc[2 * half] * s);
        hv.y = __float2half_rn(acc[2 * half + 1] * s);
        *(__half2*)&y16[(size_t)(b * T_ + t) * C_ + d] = hv;
    }
}

// ---------------- launch ----------------------------------------------------
typedef CUresult (*EncodeFn)(CUtensorMap*, CUtensorMapDataType, cuuint32_t, void*,
                             const cuuint64_t*, const cuuint64_t*, const cuuint32_t*,
                             const cuuint32_t*, CUtensorMapInterleave, CUtensorMapSwizzle,
                             CUtensorMapL2promotion, CUtensorMapFloatOOBfill);

static void make_map(EncodeFn fn, CUtensorMap* m, void* addr, uint64_t K, uint64_t rows) {
    cuuint64_t dims[2]    = {K, rows};
    cuuint64_t strides[1] = {K * 2};
    cuuint32_t box[2]     = {32, 128};
    cuuint32_t estr[2]    = {1, 1};
    fn(m, CU_TENSOR_MAP_DATA_TYPE_UINT16, 2, addr, dims, strides, box, estr,
       CU_TENSOR_MAP_INTERLEAVE_NONE, CU_TENSOR_MAP_SWIZZLE_64B,
       CU_TENSOR_MAP_L2_PROMOTION_L2_128B, CU_TENSOR_MAP_FLOAT_OOB_FILL_NONE);
}

extern "C" void kernel_launch(void* const* d_in, const int* in_sizes, int n_in,
                              void* d_out, int out_size) {
    const float* x     = (const float*)d_in[0];
    const float* am    = (const float*)d_in[1];
    const float* ln1w  = (const float*)d_in[2];
    const float* ln1b  = (const float*)d_in[3];
    const float* wattn = (const float*)d_in[4];
    const float* battn = (const float*)d_in[5];
    const float* wproj = (const float*)d_in[6];
    const float* bproj = (const float*)d_in[7];
    const float* thr   = (const float*)d_in[8];
    const float* ln2w  = (const float*)d_in[9];
    const float* ln2b  = (const float*)d_in[10];
    const float* wfc   = (const float*)d_in[11];
    const float* bfc   = (const float*)d_in[12];
    const float* wfc2  = (const float*)d_in[13];
    const float* bfc2  = (const float*)d_in[14];

    float* out      = (float*)d_out;
    float* out_x    = out;
    float* out_mask = out + out_size - 1 - M_;
    float* out_loss = out + out_size - 1;

    float *px2, *pimp, *pmsk;
    cudaGetSymbolAddress((void**)&px2,  g_x2);
    cudaGetSymbolAddress((void**)&pimp, g_imp);
    cudaGetSymbolAddress((void**)&pmsk, g_msk);
    __half *pq16, *pk16, *pv16, *ph16, *py16, *pf16, *pwat, *pwpr, *pwfc, *pwf2;
    cudaGetSymbolAddress((void**)&pq16, g_q16);
    cudaGetSymbolAddress((void**)&pk16, g_k16);
    cudaGetSymbolAddress((void**)&pv16, g_v16);
    cudaGetSymbolAddress((void**)&ph16, g_h16);
    cudaGetSymbolAddress((void**)&py16, g_y16);
    cudaGetSymbolAddress((void**)&pf16, g_f16);
    cudaGetSymbolAddress((void**)&pwat, g_wat);
    cudaGetSymbolAddress((void**)&pwpr, g_wpr);
    cudaGetSymbolAddress((void**)&pwfc, g_wfc);
    cudaGetSymbolAddress((void**)&pwf2, g_wf2);

    static cudaStream_t sB = nullptr;
    static cudaEvent_t evFork = nullptr, evJoin = nullptr;
    static CUtensorMap tmA_h, tmA_y, tmA_f, tmB_at, tmB_pr, tmB_fc, tmB_f2;
    static int init_done = 0;
    if (!init_done) {
        cudaFuncSetAttribute(fattn_kernel,
                             cudaFuncAttributeMaxDynamicSharedMemorySize, FA_SMEM);
        cudaFuncSetAttribute(tcgemm_kernel<0>,
                             cudaFuncAttributeMaxDynamicSharedMemorySize, GEMM_SMEM);
        cudaFuncSetAttribute(tcgemm_kernel<1>,
                             cudaFuncAttributeMaxDynamicSharedMemorySize, GEMM_SMEM);
        cudaFuncSetAttribute(tcgemm_kernel<2>,
                             cudaFuncAttributeMaxDynamicSharedMemorySize, GEMM_SMEM);
        cudaFuncSetAttribute(tcgemm_kernel<3>,
                             cudaFuncAttributeMaxDynamicSharedMemorySize, GEMM_SMEM);
        cudaStreamCreateWithFlags(&sB, cudaStreamNonBlocking);
        cudaEventCreateWithFlags(&evFork, cudaEventDisableTiming);
        cudaEventCreateWithFlags(&evJoin, cudaEventDisableTiming);

        EncodeFn fn = nullptr;
        cudaDriverEntryPointQueryResult qres;
        cudaGetDriverEntryPoint("cuTensorMapEncodeTiled", (void**)&fn,
                                cudaEnableDefault, &qres);
        make_map(fn, &tmA_h,  ph16, 1024, 4096);
        make_map(fn, &tmA_y,  py16, 1024, 4096);
        make_map(fn, &tmA_f,  pf16, 4096, 4096);
        make_map(fn, &tmB_at, pwat, 1024, 3072);
        make_map(fn, &tmB_pr, pwpr, 1024, 1024);
        make_map(fn, &tmB_fc, pwfc, 1024, 4096);
        make_map(fn, &tmB_f2, pwf2, 4096, 1024);
        init_done = 1;
    }

    cudaEventRecord(evFork, 0);
    cudaStreamWaitEvent(sB, evFork, 0);
    prepB_kernel<<<9216, 256, 0, sB>>>(wproj, pwpr, wfc, pwfc, wfc2, pwf2);
    cudaEventRecord(evJoin, sB);

    prepA_kernel<<<3072, 256>>>(wattn, pwat, pimp);
    ln_kernel<<<M_, 256>>>(x, ln1w, ln1b, ph16);
    tcgemm_kernel<0><<<dim3(NQKV/128, M_/128), 256, GEMM_SMEM>>>(
        tmA_h, tmB_at, battn, nullptr, nullptr, nullptr, M_, NQKV, C_);
    fattn_kernel<<<dim3(T_/QT, B_*H_), 512, FA_SMEM>>>(pq16, pk16, pv16, am, py16, pimp);
    mask_kernel<<<16, 256>>>(pimp, am, thr, pmsk, out_mask, out_loss);

    cudaStreamWaitEvent(0, evJoin, 0);
    tcgemm_kernel<1><<<dim3(C_/128, M_/128), 256, GEMM_SMEM>>>(
        tmA_y, tmB_pr, bproj, x, pmsk, px2, M_, C_, C_);
    ln_kernel<<<M_, 256>>>(px2, ln2w, ln2b, ph16);
    tcgemm_kernel<2><<<dim3(NFC/128, M_/128), 256, GEMM_SMEM>>>(
        tmA_h, tmB_fc, bfc, nullptr, nullptr, nullptr, M_, NFC, C_);
    tcgemm_kernel<3><<<dim3(C_/128, M_/128), 256, GEMM_SMEM>>>(
        tmA_f, tmB_f2, bfc2, px2, nullptr, out_x, M_, C_, NFC);
}

// round 14
// speedup vs baseline: 1.7150x; 1.0741x over previous
#include <cuda_runtime.h>
#include <cuda.h>
#include <cuda_fp16.h>
#include <math.h>
#include <stdint.h>

#define B_ 4
#define T_ 1024
#define C_ 1024
#define H_ 16
#define D_ 64
#define M_ (B_*T_)      /* 4096 rows */
#define NQKV 3072
#define NFC  4096

// ---------------- scratch (__device__ globals: no allocation allowed) -------
__device__ float g_x2 [M_*C_];
__device__ float g_imp[M_];
__device__ float g_msk[M_];
__device__ __half g_q16[M_*C_];
__device__ __half g_k16[M_*C_];
__device__ __half g_v16[M_*C_];
__device__ __half g_h16[M_*C_];
__device__ __half g_y16[M_*C_];
__device__ __half g_f16[(size_t)M_*NFC];
__device__ __half g_wat[C_*NQKV];
__device__ __half g_wpr[C_*C_];
__device__ __half g_wfc[(size_t)C_*NFC];
__device__ __half g_wf2[(size_t)NFC*C_];

// ---------------- helpers ---------------------------------------------------
__device__ __forceinline__ void mma_f16(float c[4], const uint32_t a[4], const uint32_t b[2]) {
    asm volatile(
        "mma.sync.aligned.m16n8k16.row.col.f32.f16.f16.f32 "
        "{%0,%1,%2,%3}, {%4,%5,%6,%7}, {%8,%9}, {%0,%1,%2,%3};"
        : "+f"(c[0]), "+f"(c[1]), "+f"(c[2]), "+f"(c[3])
        : "r"(a[0]), "r"(a[1]), "r"(a[2]), "r"(a[3]), "r"(b[0]), "r"(b[1]));
}
__device__ __forceinline__ uint32_t smem_u32(const void* p) {
    return (uint32_t)__cvta_generic_to_shared(p);
}
__device__ __forceinline__ void ldmx4(uint32_t* r, uint32_t addr) {
    asm volatile("ldmatrix.sync.aligned.m8n8.x4.shared.b16 {%0,%1,%2,%3}, [%4];"
                 : "=r"(r[0]), "=r"(r[1]), "=r"(r[2]), "=r"(r[3]) : "r"(addr));
}
__device__ __forceinline__ void ldmx2(uint32_t& r0, uint32_t& r1, uint32_t addr) {
    asm volatile("ldmatrix.sync.aligned.m8n8.x2.shared.b16 {%0,%1}, [%2];"
                 : "=r"(r0), "=r"(r1) : "r"(addr));
}
__device__ __forceinline__ void ldmx2t(uint32_t& r0, uint32_t& r1, uint32_t addr) {
    asm volatile("ldmatrix.sync.aligned.m8n8.x2.trans.shared.b16 {%0,%1}, [%2];"
                 : "=r"(r0), "=r"(r1) : "r"(addr));
}
__device__ __forceinline__ float fexp8(float x) {
    float t = x * 0.18033688011112042f;
    float z = t + 12582912.0f;
    int   iz = __float_as_int(z);
    float fi = z - 12582912.0f;
    float f  = t - fi;
    float p = 0.0096181291f;
    p = p * f + 0.0555041087f;
    p = p * f + 0.2402265069f;
    p = p * f + 0.6931471806f;
    p = p * f + 1.0f;
    return __int_as_float(__float_as_int(p) + (iz << 23));
}
__device__ __forceinline__ void mbar_init(uint32_t a, uint32_t n) {
    asm volatile("mbarrier.init.shared.b64 [%0], %1;" :: "r"(a), "r"(n) : "memory");
}
__device__ __forceinline__ void mbar_expect(uint32_t a, uint32_t bytes) {
    asm volatile("mbarrier.arrive.expect_tx.shared.b64 _, [%0], %1;"
                 :: "r"(a), "r"(bytes) : "memory");
}
__device__ __forceinline__ void mbar_wait(uint32_t a, uint32_t par) {
    asm volatile("{\n\t.reg .pred P;\n\tWL%=:\n\t"
                 "mbarrier.try_wait.parity.acquire.cta.shared::cta.b64 P, [%0], %1, 0x989680;\n\t"
                 "@P bra WD%=;\n\tbra WL%=;\n\tWD%=:\n\t}"
                 :: "r"(a), "r"(par) : "memory");
}
__device__ __forceinline__ void tma2d(uint32_t dst, const void* map, int cx, int cy,
                                      uint32_t mbar) {
    asm volatile("cp.async.bulk.tensor.2d.shared::cluster.global.tile.mbarrier::complete_tx::bytes "
                 "[%0], [%1, {%2, %3}], [%4];"
                 :: "r"(dst), "l"(map), "r"(cx), "r"(cy), "r"(mbar) : "memory");
}

// ---------------- small kernels --------------------------------------------
__global__ void mask_kernel(const float* __restrict__ imp,
                            const float* __restrict__ am,
                            const float* __restrict__ thr,
                            float* __restrict__ gmask,
                            float* __restrict__ outmask,
                            float* __restrict__ outloss) {
    int i = blockIdx.x * 256 + threadIdx.x;
    if (i < M_) {
        float pm = (imp[i] >= thr[0]) ? 1.f : 0.f;
        float cm = am[i] * pm;
        gmask[i]   = cm;
        outmask[i] = cm;
    }
    if (i == 0) outloss[0] = 0.f;
}

// ---------------- weight transpose tile (fp32 [K][N] -> fp16 [N][K]) --------
__device__ __forceinline__ void wtile(const float* __restrict__ W,
                                      __half* __restrict__ Oh,
                                      int K, int N, int bx, int by) {
    __shared__ float tile[32][33];
    int n0 = bx * 32, k0 = by * 32;
    int tx = threadIdx.x & 31, ty = threadIdx.x >> 5;
    #pragma unroll
    for (int i = 0; i < 4; i++)
        tile[ty + i * 8][tx] = W[(size_t)(k0 + ty + i * 8) * N + n0 + tx];
    __syncthreads();
    #pragma unroll
    for (int i = 0; i < 4; i++) {
        int n = n0 + ty + i * 8;
        Oh[(size_t)n * K + k0 + tx] = __float2half_rn(tile[tx][ty + i * 8]);
    }
}

__global__ void __launch_bounds__(256) prepA_kernel(const float* __restrict__ W,
                                                    __half* __restrict__ Oh,
                                                    float* __restrict__ imp) {
    int blk = blockIdx.x;
    if (blk < 16) imp[blk * 256 + threadIdx.x] = 0.f;
    wtile(W, Oh, C_, NQKV, blk % 96, blk / 96);
}

__global__ void __launch_bounds__(256) prepB_kernel(const float* __restrict__ Wpr,
                                                    __half* __restrict__ Opr,
                                                    const float* __restrict__ Wfc,
                                                    __half* __restrict__ Ofc,
                                                    const float* __restrict__ Wf2,
                                                    __half* __restrict__ Of2) {
    int blk = blockIdx.x;
    if (blk < 1024) {
        wtile(Wpr, Opr, C_, C_, blk % 32, blk / 32);
    } else if (blk < 5120) {
        int t = blk - 1024;
        wtile(Wfc, Ofc, C_, NFC, t % 128, t / 128);
    } else {
        int t = blk - 5120;
        wtile(Wf2, Of2, NFC, C_, t % 32, t / 32);
    }
}

// ---------------- layer norm -> fp16 ----------------------------------------
__global__ void __launch_bounds__(256) ln_kernel(const float* __restrict__ x,
                                                 const float* __restrict__ w,
                                                 const float* __restrict__ b,
                                                 __half* __restrict__ oh) {
    int row = blockIdx.x;
    int tid = threadIdx.x;
    __shared__ float buf[C_];
    __shared__ float red[8];
    const float* xr = x + (size_t)row * C_;
    float s = 0.f;
    #pragma unroll
    for (int j = tid; j < C_; j += 256) { float v = xr[j]; buf[j] = v; s += v; }
    #pragma unroll
    for (int o = 16; o; o >>= 1) s += __shfl_down_sync(~0u, s, o);
    if ((tid & 31) == 0) red[tid >> 5] = s;
    __syncthreads();
    if (tid < 8) {
        s = red[tid];
        #pragma unroll
        for (int o = 4; o; o >>= 1) s += __shfl_down_sync(0xff, s, o);
        if (tid == 0) red[0] = s;
    }
    __syncthreads();
    float mu = red[0] * (1.f / C_);
    __syncthreads();
    float ss = 0.f;
    #pragma unroll
    for (int j = tid; j < C_; j += 256) { float d = buf[j] - mu; ss += d * d; }
    #pragma unroll
    for (int o = 16; o; o >>= 1) ss += __shfl_down_sync(~0u, ss, o);
    if ((tid & 31) == 0) red[tid >> 5] = ss;
    __syncthreads();
    if (tid < 8) {
        ss = red[tid];
        #pragma unroll
        for (int o = 4; o; o >>= 1) ss += __shfl_down_sync(0xff, ss, o);
        if (tid == 0) red[0] = ss;
    }
    __syncthreads();
    float rstd = rsqrtf(red[0] * (1.f / C_) + 1e-5f);
    #pragma unroll
    for (int j = tid; j < C_; j += 256)
        oh[(size_t)row * C_ + j] = __float2half_rn((buf[j] - mu) * rstd * w[j] + b[j]);
}

// ---------------- fp16 GEMM: TMA, K=64 stages, 3-stage ring, ldmatrix -------
#define STG 3
#define STAGE_BYTES 32768          /* A 16KB (2 x 8KB chunks) + B 16KB */
#define GEMM_SMEM (STG*STAGE_BYTES + 32)

template<int EPI>
__global__ void __launch_bounds__(256, 2) tcgemm_kernel(
    const __grid_constant__ CUtensorMap tmA,
    const __grid_constant__ CUtensorMap tmB,
    const float* __restrict__ bias, const float* __restrict__ res,
    const float* __restrict__ mask, float* __restrict__ Cout,
    int M, int N, int K)
{
    extern __shared__ uint32_t smu[];
    uint32_t sbase = smem_u32(smu);
    uint32_t mb0 = sbase + STG * STAGE_BYTES;
    int tid  = threadIdx.x;
    int lane = tid & 31;
    int wid  = tid >> 5;
    int warpM = wid >> 2, warpN = wid & 3;
    int g  = lane >> 2, tg = lane & 3;
    int row0 = blockIdx.y * 128, col0 = blockIdx.x * 128;

    if (tid == 0) {
        #pragma unroll
        for (int s = 0; s < STG; s++) mbar_init(mb0 + s * 8, 1);
    }
    __syncthreads();

    int nk = K >> 6;               // K=64 per stage
    if (tid == 0) {
        #pragma unroll
        for (int p = 0; p < STG - 1; p++) {
            uint32_t mb = mb0 + p * 8;
            uint32_t sb = sbase + p * STAGE_BYTES;
            mbar_expect(mb, STAGE_BYTES);
            tma2d(sb,         &tmA, p * 64,      row0, mb);
            tma2d(sb + 8192,  &tmA, p * 64 + 32, row0, mb);
            tma2d(sb + 16384, &tmB, p * 64,      col0, mb);
            tma2d(sb + 24576, &tmB, p * 64 + 32, col0, mb);
        }
    }

    int mBase = warpM * 64;
    int nBase = warpN * 32;

    // --- precomputed ldmatrix byte offsets (SW64 row-XOR folded in) ---
    int rl = lane & 7;
    int qh = (lane >> 3) & 1;
    int qc = lane >> 4;
    uint32_t offA[4], offB[4];
    #pragma unroll
    for (int mi = 0; mi < 4; mi++) {
        int r = mBase + mi * 16 + rl + qh * 8;
        offA[mi] = (uint32_t)(r * 64 + ((qc ^ ((r >> 1) & 3)) << 4));
    }
    int qb = (lane >> 3) & 1;
    #pragma unroll
    for (int ni = 0; ni < 4; ni++) {
        int r = nBase + ni * 8 + rl;
        offB[ni] = (uint32_t)(r * 64 + ((qb ^ ((r >> 1) & 3)) << 4));
    }

    float acc[4][4][4] = {};
    int st = 0, par = 0, st2 = STG - 1;

    for (int kt = 0; kt < nk; kt++) {
        mbar_wait(mb0 + st * 8, (uint32_t)par);
        __syncthreads();
        if (tid == 0 && kt + STG - 1 < nk) {
            int tk = kt + STG - 1;
            uint32_t mb = mb0 + st2 * 8;
            uint32_t sb = sbase + st2 * STAGE_BYTES;
            mbar_expect(mb, STAGE_BYTES);
            tma2d(sb,         &tmA, tk * 64,      row0, mb);
            tma2d(sb + 8192,  &tmA, tk * 64 + 32, row0, mb);
            tma2d(sb + 16384, &tmB, tk * 64,      col0, mb);
            tma2d(sb + 24576, &tmB, tk * 64 + 32, col0, mb);
        }
        uint32_t stA = sbase + st * STAGE_BYTES;
        uint32_t stB = stA + 16384;
        #pragma unroll
        for (int sub = 0; sub < 2; sub++) {
            uint32_t baseA = stA + sub * 8192;
            uint32_t baseB = stB + sub * 8192;
            #pragma unroll
            for (int kk2 = 0; kk2 < 2; kk2++) {
                uint32_t xv = kk2 * 32;
                uint32_t a[4][4], b[4][2];
                #pragma unroll
                for (int mi = 0; mi < 4; mi++) ldmx4(a[mi], baseA + (offA[mi] ^ xv));
                #pragma unroll
                for (int ni = 0; ni < 4; ni++) ldmx2(b[ni][0], b[ni][1], baseB + (offB[ni] ^ xv));
                #pragma unroll
                for (int mi = 0; mi < 4; mi++)
                    #pragma unroll
                    for (int ni = 0; ni < 4; ni++)
                        mma_f16(acc[mi][ni], a[mi], b[ni]);
            }
        }
        st++; if (st == STG) { st = 0; par ^= 1; }
        st2++; if (st2 == STG) st2 = 0;
    }

    // ---- epilogue ----
    #pragma unroll
    for (int mi = 0; mi < 4; mi++) {
        #pragma unroll
        for (int half = 0; half < 2; half++) {
            int ig = row0 + mBase + mi * 16 + g + half * 8;
            #pragma unroll
            for (int ni = 0; ni < 4; ni++) {
                float v0 = acc[mi][ni][2 * half + 0];
                float v1 = acc[mi][ni][2 * half + 1];
                int jg = col0 + nBase + ni * 8 + tg * 2;
                if (EPI == 0) {
                    int bq = ig >> 10, t = ig & 1023;
                    int part = jg >> 10;
                    int c = jg & 1023;
                    int h = c >> 6, d = c & 63;
                    __half2 hv;
                    hv.x = __float2half_rn(v0 + bias[jg]);
                    hv.y = __float2half_rn(v1 + bias[jg + 1]);
                    __half* dst = (part == 0) ? g_q16 : (part == 1) ? g_k16 : g_v16;
                    *(__half2*)&dst[((size_t)(bq * H_ + h) * T_ + t) * D_ + d] = hv;
                } else if (EPI == 1) {
                    float mrow = mask[ig];
                    Cout[(size_t)ig * N + jg]     = (res[(size_t)ig * N + jg]     + v0 + bias[jg])     * mrow;
                    Cout[(size_t)ig * N + jg + 1] = (res[(size_t)ig * N + jg + 1] + v1 + bias[jg + 1]) * mrow;
                } else if (EPI == 2) {
                    float a0 = v0 + bias[jg], a1 = v1 + bias[jg + 1];
                    float g0 = 0.5f * a0 * (1.f + erff(a0 * 0.70710678118654752f));
                    float g1 = 0.5f * a1 * (1.f + erff(a1 * 0.70710678118654752f));
                    __half2 hv; hv.x = __float2half_rn(g0); hv.y = __float2half_rn(g1);
                    *(__half2*)&g_f16[(size_t)ig * N + jg] = hv;
                } else {
                    Cout[(size_t)ig * N + jg]     = res[(size_t)ig * N + jg]     + v0 + bias[jg];
                    Cout[(size_t)ig * N + jg + 1] = res[(size_t)ig * N + jg + 1] + v1 + bias[jg + 1];
                }
            }
        }
    }
}

// ======================= FUSED FLASH ATTENTION (fp16, 2 CTA/SM) =============
#define QT 32
#define SHSTR 524
#define QSTR 36
#define KVSTR 36
#define OFF_Q    67072
#define OFF_KV   71680
#define OFF_AM   90112
#define OFF_INV  94208
#define OFF_PART 94336
#define FA_SMEM  95424

__global__ void __launch_bounds__(512, 2) fattn_kernel(
    const __half* __restrict__ q, const __half* __restrict__ k,
    const __half* __restrict__ v, const float* __restrict__ am,
    __half* __restrict__ y16, float* __restrict__ imp)
{
    extern __shared__ char smc[];
    uint32_t* Shw = (uint32_t*)smc;
    uint32_t* Qs  = (uint32_t*)(smc + OFF_Q);
    uint32_t* KVs = (uint32_t*)(smc + OFF_KV);
    float*    amS = (float*)(smc + OFF_AM);
    float*    invlS = (float*)(smc + OFF_INV);
    float*    part  = (float*)(smc + OFF_PART);

    int qt = gridDim.x - 1 - blockIdx.x;
    int bh = blockIdx.y;
    int b  = bh >> 4, h = bh & 15;
    int tid  = threadIdx.x;
    int lane = tid & 31;
    int wid  = tid >> 5;
    int g = lane >> 2, tg = lane & 3;

    int q0   = qt * QT;
    int kend = q0 + QT;
    int jmax = ((kend + 63) >> 6) << 6;

    const __half* qb = q + (size_t)bh * T_ * D_;
    const __half* kb = k + (size_t)bh * T_ * D_;
    const __half* vb = v + (size_t)bh * T_ * D_;

    if (tid < 256) {
        int row = tid >> 3, cs = tid & 7;
        uint4 val = *(const uint4*)(qb + (size_t)(q0 + row) * D_ + cs * 8);
        *(uint4*)&Qs[row * QSTR + cs * 4] = val;
    }
    for (int j = tid; j < T_; j += 512)
        amS[j] = (am[b * T_ + j] != 0.f) ? 1.f : 0.f;
    __syncthreads();

    int warpRow = wid >> 3;
    int warpCol = wid & 7;
    int m0 = warpRow * 16;

    uint32_t aq[4][4];
    #pragma unroll
    for (int ks = 0; ks < 4; ks++) {
        aq[ks][0] = Qs[(m0 + g    ) * QSTR + ks * 8 + tg    ];
        aq[ks][1] = Qs[(m0 + g + 8) * QSTR + ks * 8 + tg    ];
        aq[ks][2] = Qs[(m0 + g    ) * QSTR + ks * 8 + 4 + tg];
        aq[ks][3] = Qs[(m0 + g + 8) * QSTR + ks * 8 + 4 + tg];
    }

    int qg0 = q0 + m0 + g;
    int qg1 = qg0 + 8;
    float rs0 = 0.f, rs1 = 0.f;
    uint32_t kvbase = smem_u32(KVs);
    int rl = lane & 7, qb2 = (lane >> 3) & 1;
    uint32_t offK[2];
    #pragma unroll
    for (int f = 0; f < 2; f++)
        offK[f] = (uint32_t)((warpCol * 16 + f * 8 + rl) * 144 + qb2 * 16);

    for (int kc0 = 0; kc0 < jmax; kc0 += 128) {
        int rows_here = min(128, jmax - kc0);
        bool interior = (kc0 + 127 <= q0);
        __syncthreads();
        for (int idx = tid; idx < rows_here * 8; idx += 512) {
            int r = idx >> 3, cs = idx & 7;
            uint4 val = *(const uint4*)(kb + (size_t)(kc0 + r) * D_ + cs * 8);
            *(uint4*)&KVs[r * KVSTR + cs * 4] = val;
        }
        __syncthreads();
        if (warpCol * 16 < rows_here) {
            float acc[2][4] = {};
            #pragma unroll
            for (int ks = 0; ks < 4; ks++) {
                #pragma unroll
                for (int f = 0; f < 2; f++) {
                    uint32_t bb0, bb1;
                    ldmx2(bb0, bb1, kvbase + offK[f] + ks * 32);
                    uint32_t bb[2] = {bb0, bb1};
                    mma_f16(acc[f], aq[ks], bb);
                }
            }
            if (interior) {
                #pragma unroll
                for (int f = 0; f < 2; f++) {
                    int j0 = kc0 + warpCol * 16 + f * 8 + tg * 2;
                    float m0v = amS[j0], m1v = amS[j0 + 1];
                    float e00 = fexp8(acc[f][0]) * m0v;
                    float e01 = fexp8(acc[f][1]) * m1v;
                    float e10 = fexp8(acc[f][2]) * m0v;
                    float e11 = fexp8(acc[f][3]) * m1v;
                    rs0 += e00 + e01;
                    rs1 += e10 + e11;
                    __half2 p01 = __floats2half2_rn(e00, e01);
                    __half2 p23 = __floats2half2_rn(e10, e11);
                    int w0 = (j0 >> 1);
                    int r0 = m0 + g;
                    Shw[r0 * SHSTR + w0]       = *(uint32_t*)&p01;
                    Shw[(r0 + 8) * SHSTR + w0] = *(uint32_t*)&p23;
                }
            } else {
                #pragma unroll
                for (int f = 0; f < 2; f++) {
                    int j0 = kc0 + warpCol * 16 + f * 8 + tg * 2;
                    float m0v = amS[j0], m1v = amS[j0 + 1];
                    float e00 = (j0     <= qg0) ? fexp8(acc[f][0]) * m0v : 0.f;
                    float e01 = (j0 + 1 <= qg0) ? fexp8(acc[f][1]) * m1v : 0.f;
                    float e10 = (j0     <= qg1) ? fexp8(acc[f][2]) * m0v : 0.f;
                    float e11 = (j0 + 1 <= qg1) ? fexp8(acc[f][3]) * m1v : 0.f;
                    rs0 += e00 + e01;
                    rs1 += e10 + e11;
                    __half2 p01 = __floats2half2_rn(e00, e01);
                    __half2 p23 = __floats2half2_rn(e10, e11);
                    int w0 = (j0 >> 1);
                    int r0 = m0 + g;
                    Shw[r0 * SHSTR + w0]       = *(uint32_t*)&p01;
                    Shw[(r0 + 8) * SHSTR + w0] = *(uint32_t*)&p23;
                }
            }
        }
    }
    rs0 += __shfl_xor_sync(~0u, rs0, 1); rs0 += __shfl_xor_sync(~0u, rs0, 2);
    rs1 += __shfl_xor_sync(~0u, rs1, 1); rs1 += __shfl_xor_sync(~0u, rs1, 2);
    if (tg == 0) {
        part[wid * 17 + g]     = rs0;
        part[wid * 17 + g + 8] = rs1;
    }
    __syncthreads();
    if (tid < 32) {
        int wr = tid >> 4, lr = tid & 15;
        float s = 0.f;
        #pragma unroll
        for (int w = 0; w < 8; w++) s += part[(wr * 8 + w) * 17 + lr];
        invlS[tid] = 1.f / s;
    }
    __syncthreads();

    if (2 * tid < kend) {
        float cs0 = 0.f, cs1 = 0.f;
        #pragma unroll
        for (int r = 0; r < QT; r++) {
            uint32_t pw = Shw[r * SHSTR + tid];
            __half2 ph = *(__half2*)&pw;
            float wgt = invlS[r];
            cs0 += __half2float(ph.x) * wgt;
            cs1 += __half2float(ph.y) * wgt;
        }
        atomicAdd(&imp[b * T_ + 2 * tid],     cs0 * (1.f / (H_ * T_)));
        atomicAdd(&imp[b * T_ + 2 * tid + 1], cs1 * (1.f / (H_ * T_)));
    }

    int col0 = warpCol * 8;
    float acc[4] = {};
    for (int kc0 = 0; kc0 < jmax; kc0 += 128) {
        int rows_here = min(128, jmax - kc0);
        __syncthreads();
        for (int idx = tid; idx < rows_here * 8; idx += 512) {
            int r = idx >> 3, cs = idx & 7;
            uint4 val = *(const uint4*)(vb + (size_t)(kc0 + r) * D_ + cs * 8);
            *(uint4*)&KVs[r * KVSTR + cs * 4] = val;
        }
        __syncthreads();
        int ksteps = rows_here >> 4;
        for (int ks = 0; ks < ksteps; ks++) {
            int wc = ((kc0 + ks * 16) >> 1);
            uint32_t a[4], bb[2];
            a[0] = Shw[(m0 + g    ) * SHSTR + wc + tg    ];
            a[1] = Shw[(m0 + g + 8) * SHSTR + wc + tg    ];
            a[2] = Shw[(m0 + g    ) * SHSTR + wc + 4 + tg];
            a[3] = Shw[(m0 + g + 8) * SHSTR + wc + 4 + tg];
            uint32_t addr = kvbase + ((ks * 16 + (lane & 15)) * 72 + col0) * 2;
            ldmx2t(bb[0], bb[1], addr);
            mma_f16(acc, a, bb);
        }
    }
    float sc0 = invlS[m0 + g], sc1 = invlS[m0 + g + 8];
    #pragma unroll
    for (int half = 0; half < 2; half++) {
        int t = q0 + m0 + g + half * 8;
        int d = h * 64 + col0 + tg * 2;
        float s = half ? sc1 : sc0;
        __half2 hv;
        hv.x = __float2half_rn(acc[2 * half] * s);
        hv.y = __float2half_rn(acc[2 * half + 1] * s);
        *(__half2*)&y16[(size_t)(b * T_ + t) * C_ + d] = hv;
    }
}

// ---------------- launch ----------------------------------------------------
typedef CUresult (*EncodeFn)(CUtensorMap*, CUtensorMapDataType, cuuint32_t, void*,
                             const cuuint64_t*, const cuuint64_t*, const cuuint32_t*,
                             const cuuint32_t*, CUtensorMapInterleave, CUtensorMapSwizzle,
                             CUtensorMapL2promotion, CUtensorMapFloatOOBfill);

static void make_map(EncodeFn fn, CUtensorMap* m, void* addr, uint64_t K, uint64_t rows) {
    cuuint64_t dims[2]    = {K, rows};
    cuuint64_t strides[1] = {K * 2};
    cuuint32_t box[2]     = {32, 128};
    cuuint32_t estr[2]    = {1, 1};
    fn(m, CU_TENSOR_MAP_DATA_TYPE_UINT16, 2, addr, dims, strides, box, estr,
       CU_TENSOR_MAP_INTERLEAVE_NONE, CU_TENSOR_MAP_SWIZZLE_64B,
       CU_TENSOR_MAP_L2_PROMOTION_L2_128B, CU_TENSOR_MAP_FLOAT_OOB_FILL_NONE);
}

extern "C" void kernel_launch(void* const* d_in, const int* in_sizes, int n_in,
                              void* d_out, int out_size) {
    const float* x     = (const float*)d_in[0];
    const float* am    = (const float*)d_in[1];
    const float* ln1w  = (const float*)d_in[2];
    const float* ln1b  = (const float*)d_in[3];
    const float* wattn = (const float*)d_in[4];
    const float* battn = (const float*)d_in[5];
    const float* wproj = (const float*)d_in[6];
    const float* bproj = (const float*)d_in[7];
    const float* thr   = (const float*)d_in[8];
    const float* ln2w  = (const float*)d_in[9];
    const float* ln2b  = (const float*)d_in[10];
    const float* wfc   = (const float*)d_in[11];
    const float* bfc   = (const float*)d_in[12];
    const float* wfc2  = (const float*)d_in[13];
    const float* bfc2  = (const float*)d_in[14];

    float* out      = (float*)d_out;
    float* out_x    = out;
    float* out_mask = out + out_size - 1 - M_;
    float* out_loss = out + out_size - 1;

    float *px2, *pimp, *pmsk;
    cudaGetSymbolAddress((void**)&px2,  g_x2);
    cudaGetSymbolAddress((void**)&pimp, g_imp);
    cudaGetSymbolAddress((void**)&pmsk, g_msk);
    __half *pq16, *pk16, *pv16, *ph16, *py16, *pf16, *pwat, *pwpr, *pwfc, *pwf2;
    cudaGetSymbolAddress((void**)&pq16, g_q16);
    cudaGetSymbolAddress((void**)&pk16, g_k16);
    cudaGetSymbolAddress((void**)&pv16, g_v16);
    cudaGetSymbolAddress((void**)&ph16, g_h16);
    cudaGetSymbolAddress((void**)&py16, g_y16);
    cudaGetSymbolAddress((void**)&pf16, g_f16);
    cudaGetSymbolAddress((void**)&pwat, g_wat);
    cudaGetSymbolAddress((void**)&pwpr, g_wpr);
    cudaGetSymbolAddress((void**)&pwfc, g_wfc);
    cudaGetSymbolAddress((void**)&pwf2, g_wf2);

    static cudaStream_t sB = nullptr;
    static cudaEvent_t evFork = nullptr, evJoin = nullptr;
    static CUtensorMap tmA_h, tmA_y, tmA_f, tmB_at, tmB_pr, tmB_fc, tmB_f2;
    static int init_done = 0;
    if (!init_done) {
        cudaFuncSetAttribute(fattn_kernel,
                             cudaFuncAttributeMaxDynamicSharedMemorySize, FA_SMEM);
        cudaFuncSetAttribute(tcgemm_kernel<0>,
                             cudaFuncAttributeMaxDynamicSharedMemorySize, GEMM_SMEM);
        cudaFuncSetAttribute(tcgemm_kernel<1>,
                             cudaFuncAttributeMaxDynamicSharedMemorySize, GEMM_SMEM);
        cudaFuncSetAttribute(tcgemm_kernel<2>,
                             cudaFuncAttributeMaxDynamicSharedMemorySize, GEMM_SMEM);
        cudaFuncSetAttribute(tcgemm_kernel<3>,
                             cudaFuncAttributeMaxDynamicSharedMemorySize, GEMM_SMEM);
        cudaStreamCreateWithFlags(&sB, cudaStreamNonBlocking);
        cudaEventCreateWithFlags(&evFork, cudaEventDisableTiming);
        cudaEventCreateWithFlags(&evJoin, cudaEventDisableTiming);

        EncodeFn fn = nullptr;
        cudaDriverEntryPointQueryResult qres;
        cudaGetDriverEntryPoint("cuTensorMapEncodeTiled", (void**)&fn,
                                cudaEnableDefault, &qres);
        make_map(fn, &tmA_h,  ph16, 1024, 4096);
        make_map(fn, &tmA_y,  py16, 1024, 4096);
        make_map(fn, &tmA_f,  pf16, 4096, 4096);
        make_map(fn, &tmB_at, pwat, 1024, 3072);
        make_map(fn, &tmB_pr, pwpr, 1024, 1024);
        make_map(fn, &tmB_fc, pwfc, 1024, 4096);
        make_map(fn, &tmB_f2, pwf2, 4096, 1024);
        init_done = 1;
    }

    cudaEventRecord(evFork, 0);
    cudaStreamWaitEvent(sB, evFork, 0);
    prepB_kernel<<<9216, 256, 0, sB>>>(wproj, pwpr, wfc, pwfc, wfc2, pwf2);
    cudaEventRecord(evJoin, sB);

    prepA_kernel<<<3072, 256>>>(wattn, pwat, pimp);
    ln_kernel<<<M_, 256>>>(x, ln1w, ln1b, ph16);
    tcgemm_kernel<0><<<dim3(NQKV/128, M_/128), 256, GEMM_SMEM>>>(
        tmA_h, tmB_at, battn, nullptr, nullptr, nullptr, M_, NQKV, C_);
    fattn_kernel<<<dim3(T_/QT, B_*H_), 512, FA_SMEM>>>(pq16, pk16, pv16, am, py16, pimp);
    mask_kernel<<<16, 256>>>(pimp, am, thr, pmsk, out_mask, out_loss);

    cudaStreamWaitEvent(0, evJoin, 0);
    tcgemm_kernel<1><<<dim3(C_/128, M_/128), 256, GEMM_SMEM>>>(
        tmA_y, tmB_pr, bproj, x, pmsk, px2, M_, C_, C_);
    ln_kernel<<<M_, 256>>>(px2, ln2w, ln2b, ph16);
    tcgemm_kernel<2><<<dim3(NFC/128, M_/128), 256, GEMM_SMEM>>>(
        tmA_h, tmB_fc, bfc, nullptr, nullptr, nullptr, M_, NFC, C_);
    tcgemm_kernel<3><<<dim3(C_/128, M_/128), 256, GEMM_SMEM>>>(
        tmA_f, tmB_f2, bfc2, px2, nullptr, out_x, M_, C_, NFC);
}

// round 15
// speedup vs baseline: 1.7745x; 1.0347x over previous
#include <cuda_runtime.h>
#include <cuda.h>
#include <cuda_fp16.h>
#include <math.h>
#include <stdint.h>

#define B_ 4
#define T_ 1024
#define C_ 1024
#define H_ 16
#define D_ 64
#define M_ (B_*T_)      /* 4096 rows */
#define NQKV 3072
#define NFC  4096

// ---------------- scratch (__device__ globals: no allocation allowed) -------
__device__ float g_x2 [M_*C_];
__device__ float g_imp[M_];
__device__ float g_msk[M_];
__device__ __half g_q16[M_*C_];
__device__ __half g_k16[M_*C_];
__device__ __half g_v16[M_*C_];
__device__ __half g_h16[M_*C_];
__device__ __half g_y16[M_*C_];
__device__ __half g_f16[(size_t)M_*NFC];
__device__ __half g_wat[C_*NQKV];
__device__ __half g_wpr[C_*C_];
__device__ __half g_wfc[(size_t)C_*NFC];
__device__ __half g_wf2[(size_t)NFC*C_];

// ---------------- helpers ---------------------------------------------------
__device__ __forceinline__ void mma_f16(float c[4], const uint32_t a[4], const uint32_t b[2]) {
    asm volatile(
        "mma.sync.aligned.m16n8k16.row.col.f32.f16.f16.f32 "
        "{%0,%1,%2,%3}, {%4,%5,%6,%7}, {%8,%9}, {%0,%1,%2,%3};"
        : "+f"(c[0]), "+f"(c[1]), "+f"(c[2]), "+f"(c[3])
        : "r"(a[0]), "r"(a[1]), "r"(a[2]), "r"(a[3]), "r"(b[0]), "r"(b[1]));
}
__device__ __forceinline__ uint32_t smem_u32(const void* p) {
    return (uint32_t)__cvta_generic_to_shared(p);
}
__device__ __forceinline__ void ldmx4(uint32_t* r, uint32_t addr) {
    asm volatile("ldmatrix.sync.aligned.m8n8.x4.shared.b16 {%0,%1,%2,%3}, [%4];"
                 : "=r"(r[0]), "=r"(r[1]), "=r"(r[2]), "=r"(r[3]) : "r"(addr));
}
__device__ __forceinline__ void ldmx2(uint32_t& r0, uint32_t& r1, uint32_t addr) {
    asm volatile("ldmatrix.sync.aligned.m8n8.x2.shared.b16 {%0,%1}, [%2];"
                 : "=r"(r0), "=r"(r1) : "r"(addr));
}
__device__ __forceinline__ void ldmx2t(uint32_t& r0, uint32_t& r1, uint32_t addr) {
    asm volatile("ldmatrix.sync.aligned.m8n8.x2.trans.shared.b16 {%0,%1}, [%2];"
                 : "=r"(r0), "=r"(r1) : "r"(addr));
}
__device__ __forceinline__ float fexp8(float x) {
    float t = x * 0.18033688011112042f;
    float z = t + 12582912.0f;
    int   iz = __float_as_int(z);
    float fi = z - 12582912.0f;
    float f  = t - fi;
    float p = 0.0096181291f;
    p = p * f + 0.0555041087f;
    p = p * f + 0.2402265069f;
    p = p * f + 0.6931471806f;
    p = p * f + 1.0f;
    return __int_as_float(__float_as_int(p) + (iz << 23));
}
__device__ __forceinline__ void mbar_init(uint32_t a, uint32_t n) {
    asm volatile("mbarrier.init.shared.b64 [%0], %1;" :: "r"(a), "r"(n) : "memory");
}
__device__ __forceinline__ void mbar_expect(uint32_t a, uint32_t bytes) {
    asm volatile("mbarrier.arrive.expect_tx.shared.b64 _, [%0], %1;"
                 :: "r"(a), "r"(bytes) : "memory");
}
__device__ __forceinline__ void mbar_arrive(uint32_t a) {
    asm volatile("mbarrier.arrive.release.cta.shared.b64 _, [%0];" :: "r"(a) : "memory");
}
__device__ __forceinline__ void mbar_wait(uint32_t a, uint32_t par) {
    asm volatile("{\n\t.reg .pred P;\n\tWL%=:\n\t"
                 "mbarrier.try_wait.parity.acquire.cta.shared::cta.b64 P, [%0], %1, 0x989680;\n\t"
                 "@P bra WD%=;\n\tbra WL%=;\n\tWD%=:\n\t}"
                 :: "r"(a), "r"(par) : "memory");
}
__device__ __forceinline__ void tma2d(uint32_t dst, const void* map, int cx, int cy,
                                      uint32_t mbar) {
    asm volatile("cp.async.bulk.tensor.2d.shared::cluster.global.tile.mbarrier::complete_tx::bytes "
                 "[%0], [%1, {%2, %3}], [%4];"
                 :: "r"(dst), "l"(map), "r"(cx), "r"(cy), "r"(mbar) : "memory");
}

// ---------------- small kernels --------------------------------------------
__global__ void mask_kernel(const float* __restrict__ imp,
                            const float* __restrict__ am,
                            const float* __restrict__ thr,
                            float* __restrict__ gmask,
                            float* __restrict__ outmask,
                            float* __restrict__ outloss) {
    int i = blockIdx.x * 256 + threadIdx.x;
    if (i < M_) {
        float pm = (imp[i] >= thr[0]) ? 1.f : 0.f;
        float cm = am[i] * pm;
        gmask[i]   = cm;
        outmask[i] = cm;
    }
    if (i == 0) outloss[0] = 0.f;
}

// ---------------- weight transpose tile (fp32 [K][N] -> fp16 [N][K]) --------
__device__ __forceinline__ void wtile(const float* __restrict__ W,
                                      __half* __restrict__ Oh,
                                      int K, int N, int bx, int by) {
    __shared__ float tile[32][33];
    int n0 = bx * 32, k0 = by * 32;
    int tx = threadIdx.x & 31, ty = threadIdx.x >> 5;
    #pragma unroll
    for (int i = 0; i < 4; i++)
        tile[ty + i * 8][tx] = W[(size_t)(k0 + ty + i * 8) * N + n0 + tx];
    __syncthreads();
    #pragma unroll
    for (int i = 0; i < 4; i++) {
        int n = n0 + ty + i * 8;
        Oh[(size_t)n * K + k0 + tx] = __float2half_rn(tile[tx][ty + i * 8]);
    }
}

__global__ void __launch_bounds__(256) prepA_kernel(const float* __restrict__ W,
                                                    __half* __restrict__ Oh,
                                                    float* __restrict__ imp) {
    int blk = blockIdx.x;
    if (blk < 16) imp[blk * 256 + threadIdx.x] = 0.f;
    wtile(W, Oh, C_, NQKV, blk % 96, blk / 96);
}

__global__ void __launch_bounds__(256) prepB_kernel(const float* __restrict__ Wpr,
                                                    __half* __restrict__ Opr,
                                                    const float* __restrict__ Wfc,
                                                    __half* __restrict__ Ofc,
                                                    const float* __restrict__ Wf2,
                                                    __half* __restrict__ Of2) {
    int blk = blockIdx.x;
    if (blk < 1024) {
        wtile(Wpr, Opr, C_, C_, blk % 32, blk / 32);
    } else if (blk < 5120) {
        int t = blk - 1024;
        wtile(Wfc, Ofc, C_, NFC, t % 128, t / 128);
    } else {
        int t = blk - 5120;
        wtile(Wf2, Of2, NFC, C_, t % 32, t / 32);
    }
}

// ---------------- layer norm -> fp16 ----------------------------------------
__global__ void __launch_bounds__(256) ln_kernel(const float* __restrict__ x,
                                                 const float* __restrict__ w,
                                                 const float* __restrict__ b,
                                                 __half* __restrict__ oh) {
    int row = blockIdx.x;
    int tid = threadIdx.x;
    __shared__ float buf[C_];
    __shared__ float red[8];
    const float* xr = x + (size_t)row * C_;
    float s = 0.f;
    #pragma unroll
    for (int j = tid; j < C_; j += 256) { float v = xr[j]; buf[j] = v; s += v; }
    #pragma unroll
    for (int o = 16; o; o >>= 1) s += __shfl_down_sync(~0u, s, o);
    if ((tid & 31) == 0) red[tid >> 5] = s;
    __syncthreads();
    if (tid < 8) {
        s = red[tid];
        #pragma unroll
        for (int o = 4; o; o >>= 1) s += __shfl_down_sync(0xff, s, o);
        if (tid == 0) red[0] = s;
    }
    __syncthreads();
    float mu = red[0] * (1.f / C_);
    __syncthreads();
    float ss = 0.f;
    #pragma unroll
    for (int j = tid; j < C_; j += 256) { float d = buf[j] - mu; ss += d * d; }
    #pragma unroll
    for (int o = 16; o; o >>= 1) ss += __shfl_down_sync(~0u, ss, o);
    if ((tid & 31) == 0) red[tid >> 5] = ss;
    __syncthreads();
    if (tid < 8) {
        ss = red[tid];
        #pragma unroll
        for (int o = 4; o; o >>= 1) ss += __shfl_down_sync(0xff, ss, o);
        if (tid == 0) red[0] = ss;
    }
    __syncthreads();
    float rstd = rsqrtf(red[0] * (1.f / C_) + 1e-5f);
    #pragma unroll
    for (int j = tid; j < C_; j += 256)
        oh[(size_t)row * C_ + j] = __float2half_rn((buf[j] - mu) * rstd * w[j] + b[j]);
}

// ------- fp16 GEMM: TMA K=64 stages, 3-ring, full/empty mbarriers -----------
#define STG 3
#define STAGE_BYTES 32768
#define GEMM_SMEM (STG*STAGE_BYTES + 64)   /* full[3] + empty[3] mbarriers */

template<int EPI>
__global__ void __launch_bounds__(256, 2) tcgemm_kernel(
    const __grid_constant__ CUtensorMap tmA,
    const __grid_constant__ CUtensorMap tmB,
    const float* __restrict__ bias, const float* __restrict__ res,
    const float* __restrict__ mask, float* __restrict__ Cout,
    int M, int N, int K)
{
    extern __shared__ uint32_t smu[];
    uint32_t sbase = smem_u32(smu);
    uint32_t mbF = sbase + STG * STAGE_BYTES;        // full barriers
    uint32_t mbE = mbF + STG * 8;                    // empty barriers
    int tid  = threadIdx.x;
    int lane = tid & 31;
    int wid  = tid >> 5;
    int warpM = wid >> 2, warpN = wid & 3;
    int g  = lane >> 2, tg = lane & 3;
    int row0 = blockIdx.y * 128, col0 = blockIdx.x * 128;

    if (tid == 0) {
        #pragma unroll
        for (int s = 0; s < STG; s++) {
            mbar_init(mbF + s * 8, 1);
            mbar_init(mbE + s * 8, 256);
        }
    }
    __syncthreads();

    int nk = K >> 6;
    if (tid == 0) {
        #pragma unroll
        for (int p = 0; p < STG - 1; p++) {
            uint32_t mb = mbF + p * 8;
            uint32_t sb = sbase + p * STAGE_BYTES;
            mbar_expect(mb, STAGE_BYTES);
            tma2d(sb,         &tmA, p * 64,      row0, mb);
            tma2d(sb + 8192,  &tmA, p * 64 + 32, row0, mb);
            tma2d(sb + 16384, &tmB, p * 64,      col0, mb);
            tma2d(sb + 24576, &tmB, p * 64 + 32, col0, mb);
        }
    }

    int mBase = warpM * 64;
    int nBase = warpN * 32;

    int rl = lane & 7;
    int qh = (lane >> 3) & 1;
    int qc = lane >> 4;
    uint32_t offA[4], offB[4];
    #pragma unroll
    for (int mi = 0; mi < 4; mi++) {
        int r = mBase + mi * 16 + rl + qh * 8;
        offA[mi] = (uint32_t)(r * 64 + ((qc ^ ((r >> 1) & 3)) << 4));
    }
    int qb = (lane >> 3) & 1;
    #pragma unroll
    for (int ni = 0; ni < 4; ni++) {
        int r = nBase + ni * 8 + rl;
        offB[ni] = (uint32_t)(r * 64 + ((qb ^ ((r >> 1) & 3)) << 4));
    }

    float acc[4][4][4] = {};
    int st = 0, par = 0, st2 = STG - 1;
    int ep0 = 0, ep1 = 0, ep2 = 0;

    for (int kt = 0; kt < nk; kt++) {
        // producer: issue stage kt+STG-1 (after its prior consumers drained)
        if (tid == 0 && kt + STG - 1 < nk) {
            int tk = kt + STG - 1;
            if (tk >= STG) {
                int p2 = (st2 == 0) ? ep0 : (st2 == 1) ? ep1 : ep2;
                mbar_wait(mbE + st2 * 8, (uint32_t)p2);
                if (st2 == 0) ep0 ^= 1; else if (st2 == 1) ep1 ^= 1; else ep2 ^= 1;
            }
            uint32_t mb = mbF + st2 * 8;
            uint32_t sb = sbase + st2 * STAGE_BYTES;
            mbar_expect(mb, STAGE_BYTES);
            tma2d(sb,         &tmA, tk * 64,      row0, mb);
            tma2d(sb + 8192,  &tmA, tk * 64 + 32, row0, mb);
            tma2d(sb + 16384, &tmB, tk * 64,      col0, mb);
            tma2d(sb + 24576, &tmB, tk * 64 + 32, col0, mb);
        }
        // consumer: wait data, compute, release stage
        mbar_wait(mbF + st * 8, (uint32_t)par);
        uint32_t stA = sbase + st * STAGE_BYTES;
        uint32_t stB = stA + 16384;
        #pragma unroll
        for (int sub = 0; sub < 2; sub++) {
            uint32_t baseA = stA + sub * 8192;
            uint32_t baseB = stB + sub * 8192;
            #pragma unroll
            for (int kk2 = 0; kk2 < 2; kk2++) {
                uint32_t xv = kk2 * 32;
                uint32_t a[4][4], b[4][2];
                #pragma unroll
                for (int mi = 0; mi < 4; mi++) ldmx4(a[mi], baseA + (offA[mi] ^ xv));
                #pragma unroll
                for (int ni = 0; ni < 4; ni++) ldmx2(b[ni][0], b[ni][1], baseB + (offB[ni] ^ xv));
                #pragma unroll
                for (int mi = 0; mi < 4; mi++)
                    #pragma unroll
                    for (int ni = 0; ni < 4; ni++)
                        mma_f16(acc[mi][ni], a[mi], b[ni]);
            }
        }
        mbar_arrive(mbE + st * 8);
        st++; if (st == STG) { st = 0; par ^= 1; }
        st2++; if (st2 == STG) st2 = 0;
    }

    // ---- epilogue ----
    #pragma unroll
    for (int mi = 0; mi < 4; mi++) {
        #pragma unroll
        for (int half = 0; half < 2; half++) {
            int ig = row0 + mBase + mi * 16 + g + half * 8;
            #pragma unroll
            for (int ni = 0; ni < 4; ni++) {
                float v0 = acc[mi][ni][2 * half + 0];
                float v1 = acc[mi][ni][2 * half + 1];
                int jg = col0 + nBase + ni * 8 + tg * 2;
                if (EPI == 0) {
                    int bq = ig >> 10, t = ig & 1023;
                    int part = jg >> 10;
                    int c = jg & 1023;
                    int h = c >> 6, d = c & 63;
                    __half2 hv;
                    hv.x = __float2half_rn(v0 + bias[jg]);
                    hv.y = __float2half_rn(v1 + bias[jg + 1]);
                    __half* dst = (part == 0) ? g_q16 : (part == 1) ? g_k16 : g_v16;
                    *(__half2*)&dst[((size_t)(bq * H_ + h) * T_ + t) * D_ + d] = hv;
                } else if (EPI == 1) {
                    float mrow = mask[ig];
                    Cout[(size_t)ig * N + jg]     = (res[(size_t)ig * N + jg]     + v0 + bias[jg])     * mrow;
                    Cout[(size_t)ig * N + jg + 1] = (res[(size_t)ig * N + jg + 1] + v1 + bias[jg + 1]) * mrow;
                } else if (EPI == 2) {
                    float a0 = v0 + bias[jg], a1 = v1 + bias[jg + 1];
                    float g0 = 0.5f * a0 * (1.f + erff(a0 * 0.70710678118654752f));
                    float g1 = 0.5f * a1 * (1.f + erff(a1 * 0.70710678118654752f));
                    __half2 hv; hv.x = __float2half_rn(g0); hv.y = __float2half_rn(g1);
                    *(__half2*)&g_f16[(size_t)ig * N + jg] = hv;
                } else {
                    Cout[(size_t)ig * N + jg]     = res[(size_t)ig * N + jg]     + v0 + bias[jg];
                    Cout[(size_t)ig * N + jg + 1] = res[(size_t)ig * N + jg + 1] + v1 + bias[jg + 1];
                }
            }
        }
    }
}

// ======================= FUSED FLASH ATTENTION (fp16, 2 CTA/SM) =============
#define QT 32
#define SHSTR 524
#define QSTR 36
#define KVSTR 36
#define OFF_Q    67072
#define OFF_KV   71680
#define OFF_AM   90112
#define OFF_INV  94208
#define OFF_PART 94336
#define FA_SMEM  95424

__global__ void __launch_bounds__(512, 2) fattn_kernel(
    const __half* __restrict__ q, const __half* __restrict__ k,
    const __half* __restrict__ v, const float* __restrict__ am,
    __half* __restrict__ y16, float* __restrict__ imp)
{
    extern __shared__ char smc[];
    uint32_t* Shw = (uint32_t*)smc;
    uint32_t* Qs  = (uint32_t*)(smc + OFF_Q);
    uint32_t* KVs = (uint32_t*)(smc + OFF_KV);
    float*    amS = (float*)(smc + OFF_AM);
    float*    invlS = (float*)(smc + OFF_INV);
    float*    part  = (float*)(smc + OFF_PART);

    int qt = gridDim.x - 1 - blockIdx.x;
    int bh = blockIdx.y;
    int b  = bh >> 4, h = bh & 15;
    int tid  = threadIdx.x;
    int lane = tid & 31;
    int wid  = tid >> 5;
    int g = lane >> 2, tg = lane & 3;

    int q0   = qt * QT;
    int kend = q0 + QT;
    int jmax = ((kend + 63) >> 6) << 6;

    const __half* qb = q + (size_t)bh * T_ * D_;
    const __half* kb = k + (size_t)bh * T_ * D_;
    const __half* vb = v + (size_t)bh * T_ * D_;

    if (tid < 256) {
        int row = tid >> 3, cs = tid & 7;
        uint4 val = *(const uint4*)(qb + (size_t)(q0 + row) * D_ + cs * 8);
        *(uint4*)&Qs[row * QSTR + cs * 4] = val;
    }
    for (int j = tid; j < T_; j += 512)
        amS[j] = (am[b * T_ + j] != 0.f) ? 1.f : 0.f;
    __syncthreads();

    int warpRow = wid >> 3;
    int warpCol = wid & 7;
    int m0 = warpRow * 16;

    uint32_t aq[4][4];
    #pragma unroll
    for (int ks = 0; ks < 4; ks++) {
        aq[ks][0] = Qs[(m0 + g    ) * QSTR + ks * 8 + tg    ];
        aq[ks][1] = Qs[(m0 + g + 8) * QSTR + ks * 8 + tg    ];
        aq[ks][2] = Qs[(m0 + g    ) * QSTR + ks * 8 + 4 + tg];
        aq[ks][3] = Qs[(m0 + g + 8) * QSTR + ks * 8 + 4 + tg];
    }

    int qg0 = q0 + m0 + g;
    int qg1 = qg0 + 8;
    float rs0 = 0.f, rs1 = 0.f;
    uint32_t kvbase = smem_u32(KVs);
    uint32_t shbase = smem_u32(Shw);
    int rl = lane & 7, qb2 = (lane >> 3) & 1;
    int qh = (lane >> 3) & 1, qc = lane >> 4;
    uint32_t offK[2];
    #pragma unroll
    for (int f = 0; f < 2; f++)
        offK[f] = (uint32_t)((warpCol * 16 + f * 8 + rl) * 144 + qb2 * 16);
    // phase-3 P a-fragment ldmatrix.x4 offset (rows stride SHSTR*4 bytes)
    uint32_t offS = (uint32_t)((m0 + rl + qh * 8) * (SHSTR * 4) + qc * 16);

    for (int kc0 = 0; kc0 < jmax; kc0 += 128) {
        int rows_here = min(128, jmax - kc0);
        bool interior = (kc0 + 127 <= q0);
        __syncthreads();
        for (int idx = tid; idx < rows_here * 8; idx += 512) {
            int r = idx >> 3, cs = idx & 7;
            uint4 val = *(const uint4*)(kb + (size_t)(kc0 + r) * D_ + cs * 8);
            *(uint4*)&KVs[r * KVSTR + cs * 4] = val;
        }
        __syncthreads();
        if (warpCol * 16 < rows_here) {
            float acc[2][4] = {};
            #pragma unroll
            for (int ks = 0; ks < 4; ks++) {
                #pragma unroll
                for (int f = 0; f < 2; f++) {
                    uint32_t bb0, bb1;
                    ldmx2(bb0, bb1, kvbase + offK[f] + ks * 32);
                    uint32_t bb[2] = {bb0, bb1};
                    mma_f16(acc[f], aq[ks], bb);
                }
            }
            if (interior) {
                #pragma unroll
                for (int f = 0; f < 2; f++) {
                    int j0 = kc0 + warpCol * 16 + f * 8 + tg * 2;
                    float m0v = amS[j0], m1v = amS[j0 + 1];
                    float e00 = fexp8(acc[f][0]) * m0v;
                    float e01 = fexp8(acc[f][1]) * m1v;
                    float e10 = fexp8(acc[f][2]) * m0v;
                    float e11 = fexp8(acc[f][3]) * m1v;
                    rs0 += e00 + e01;
                    rs1 += e10 + e11;
                    __half2 p01 = __floats2half2_rn(e00, e01);
                    __half2 p23 = __floats2half2_rn(e10, e11);
                    int w0 = (j0 >> 1);
                    int r0 = m0 + g;
                    Shw[r0 * SHSTR + w0]       = *(uint32_t*)&p01;
                    Shw[(r0 + 8) * SHSTR + w0] = *(uint32_t*)&p23;
                }
            } else {
                #pragma unroll
                for (int f = 0; f < 2; f++) {
                    int j0 = kc0 + warpCol * 16 + f * 8 + tg * 2;
                    float m0v = amS[j0], m1v = amS[j0 + 1];
                    float e00 = (j0     <= qg0) ? fexp8(acc[f][0]) * m0v : 0.f;
                    float e01 = (j0 + 1 <= qg0) ? fexp8(acc[f][1]) * m1v : 0.f;
                    float e10 = (j0     <= qg1) ? fexp8(acc[f][2]) * m0v : 0.f;
                    float e11 = (j0 + 1 <= qg1) ? fexp8(acc[f][3]) * m1v : 0.f;
                    rs0 += e00 + e01;
                    rs1 += e10 + e11;
                    __half2 p01 = __floats2half2_rn(e00, e01);
                    __half2 p23 = __floats2half2_rn(e10, e11);
                    int w0 = (j0 >> 1);
                    int r0 = m0 + g;
                    Shw[r0 * SHSTR + w0]       = *(uint32_t*)&p01;
                    Shw[(r0 + 8) * SHSTR + w0] = *(uint32_t*)&p23;
                }
            }
        }
    }
    rs0 += __shfl_xor_sync(~0u, rs0, 1); rs0 += __shfl_xor_sync(~0u, rs0, 2);
    rs1 += __shfl_xor_sync(~0u, rs1, 1); rs1 += __shfl_xor_sync(~0u, rs1, 2);
    if (tg == 0) {
        part[wid * 17 + g]     = rs0;
        part[wid * 17 + g + 8] = rs1;
    }
    __syncthreads();
    if (tid < 32) {
        int wr = tid >> 4, lr = tid & 15;
        float s = 0.f;
        #pragma unroll
        for (int w = 0; w < 8; w++) s += part[(wr * 8 + w) * 17 + lr];
        invlS[tid] = 1.f / s;
    }
    __syncthreads();

    if (2 * tid < kend) {
        float cs0 = 0.f, cs1 = 0.f;
        #pragma unroll
        for (int r = 0; r < QT; r++) {
            uint32_t pw = Shw[r * SHSTR + tid];
            __half2 ph = *(__half2*)&pw;
            float wgt = invlS[r];
            cs0 += __half2float(ph.x) * wgt;
            cs1 += __half2float(ph.y) * wgt;
        }
        atomicAdd(&imp[b * T_ + 2 * tid],     cs0 * (1.f / (H_ * T_)));
        atomicAdd(&imp[b * T_ + 2 * tid + 1], cs1 * (1.f / (H_ * T_)));
    }

    int col0 = warpCol * 8;
    float acc[4] = {};
    for (int kc0 = 0; kc0 < jmax; kc0 += 128) {
        int rows_here = min(128, jmax - kc0);
        __syncthreads();
        for (int idx = tid; idx < rows_here * 8; idx += 512) {
            int r = idx >> 3, cs = idx & 7;
            uint4 val = *(const uint4*)(vb + (size_t)(kc0 + r) * D_ + cs * 8);
            *(uint4*)&KVs[r * KVSTR + cs * 4] = val;
        }
        __syncthreads();
        int ksteps = rows_here >> 4;
        for (int ks = 0; ks < ksteps; ks++) {
            uint32_t a[4], bb[2];
            ldmx4(a, shbase + offS + (uint32_t)((kc0 + ks * 16) * 2));
            uint32_t addr = kvbase + ((ks * 16 + (lane & 15)) * 72 + col0) * 2;
            ldmx2t(bb[0], bb[1], addr);
            mma_f16(acc, a, bb);
        }
    }
    float sc0 = invlS[m0 + g], sc1 = invlS[m0 + g + 8];
    #pragma unroll
    for (int half = 0; half < 2; half++) {
        int t = q0 + m0 + g + half * 8;
        int d = h * 64 + col0 + tg * 2;
        float s = half ? sc1 : sc0;
        __half2 hv;
        hv.x = __float2half_rn(acc[2 * half] * s);
        hv.y = __float2half_rn(acc[2 * half + 1] * s);
        *(__half2*)&y16[(size_t)(b * T_ + t) * C_ + d] = hv;
    }
}

// ---------------- launch ----------------------------------------------------
typedef CUresult (*EncodeFn)(CUtensorMap*, CUtensorMapDataType, cuuint32_t, void*,
                             const cuuint64_t*, const cuuint64_t*, const cuuint32_t*,
                             const cuuint32_t*, CUtensorMapInterleave, CUtensorMapSwizzle,
                             CUtensorMapL2promotion, CUtensorMapFloatOOBfill);

static void make_map(EncodeFn fn, CUtensorMap* m, void* addr, uint64_t K, uint64_t rows) {
    cuuint64_t dims[2]    = {K, rows};
    cuuint64_t strides[1] = {K * 2};
    cuuint32_t box[2]     = {32, 128};
    cuuint32_t estr[2]    = {1, 1};
    fn(m, CU_TENSOR_MAP_DATA_TYPE_UINT16, 2, addr, dims, strides, box, estr,
       CU_TENSOR_MAP_INTERLEAVE_NONE, CU_TENSOR_MAP_SWIZZLE_64B,
       CU_TENSOR_MAP_L2_PROMOTION_L2_128B, CU_TENSOR_MAP_FLOAT_OOB_FILL_NONE);
}

extern "C" void kernel_launch(void* const* d_in, const int* in_sizes, int n_in,
                              void* d_out, int out_size) {
    const float* x     = (const float*)d_in[0];
    const float* am    = (const float*)d_in[1];
    const float* ln1w  = (const float*)d_in[2];
    const float* ln1b  = (const float*)d_in[3];
    const float* wattn = (const float*)d_in[4];
    const float* battn = (const float*)d_in[5];
    const float* wproj = (const float*)d_in[6];
    const float* bproj = (const float*)d_in[7];
    const float* thr   = (const float*)d_in[8];
    const float* ln2w  = (const float*)d_in[9];
    const float* ln2b  = (const float*)d_in[10];
    const float* wfc   = (const float*)d_in[11];
    const float* bfc   = (const float*)d_in[12];
    const float* wfc2  = (const float*)d_in[13];
    const float* bfc2  = (const float*)d_in[14];

    float* out      = (float*)d_out;
    float* out_x    = out;
    float* out_mask = out + out_size - 1 - M_;
    float* out_loss = out + out_size - 1;

    float *px2, *pimp, *pmsk;
    cudaGetSymbolAddress((void**)&px2,  g_x2);
    cudaGetSymbolAddress((void**)&pimp, g_imp);
    cudaGetSymbolAddress((void**)&pmsk, g_msk);
    __half *pq16, *pk16, *pv16, *ph16, *py16, *pf16, *pwat, *pwpr, *pwfc, *pwf2;
    cudaGetSymbolAddress((void**)&pq16, g_q16);
    cudaGetSymbolAddress((void**)&pk16, g_k16);
    cudaGetSymbolAddress((void**)&pv16, g_v16);
    cudaGetSymbolAddress((void**)&ph16, g_h16);
    cudaGetSymbolAddress((void**)&py16, g_y16);
    cudaGetSymbolAddress((void**)&pf16, g_f16);
    cudaGetSymbolAddress((void**)&pwat, g_wat);
    cudaGetSymbolAddress((void**)&pwpr, g_wpr);
    cudaGetSymbolAddress((void**)&pwfc, g_wfc);
    cudaGetSymbolAddress((void**)&pwf2, g_wf2);

    static cudaStream_t sB = nullptr;
    static cudaEvent_t evFork = nullptr, evJoin = nullptr;
    static CUtensorMap tmA_h, tmA_y, tmA_f, tmB_at, tmB_pr, tmB_fc, tmB_f2;
    static int init_done = 0;
    if (!init_done) {
        cudaFuncSetAttribute(fattn_kernel,
                             cudaFuncAttributeMaxDynamicSharedMemorySize, FA_SMEM);
        cudaFuncSetAttribute(tcgemm_kernel<0>,
                             cudaFuncAttributeMaxDynamicSharedMemorySize, GEMM_SMEM);
        cudaFuncSetAttribute(tcgemm_kernel<1>,
                             cudaFuncAttributeMaxDynamicSharedMemorySize, GEMM_SMEM);
        cudaFuncSetAttribute(tcgemm_kernel<2>,
                             cudaFuncAttributeMaxDynamicSharedMemorySize, GEMM_SMEM);
        cudaFuncSetAttribute(tcgemm_kernel<3>,
                             cudaFuncAttributeMaxDynamicSharedMemorySize, GEMM_SMEM);
        cudaStreamCreateWithFlags(&sB, cudaStreamNonBlocking);
        cudaEventCreateWithFlags(&evFork, cudaEventDisableTiming);
        cudaEventCreateWithFlags(&evJoin, cudaEventDisableTiming);

        EncodeFn fn = nullptr;
        cudaDriverEntryPointQueryResult qres;
        cudaGetDriverEntryPoint("cuTensorMapEncodeTiled", (void**)&fn,
                                cudaEnableDefault, &qres);
        make_map(fn, &tmA_h,  ph16, 1024, 4096);
        make_map(fn, &tmA_y,  py16, 1024, 4096);
        make_map(fn, &tmA_f,  pf16, 4096, 4096);
        make_map(fn, &tmB_at, pwat, 1024, 3072);
        make_map(fn, &tmB_pr, pwpr, 1024, 1024);
        make_map(fn, &tmB_fc, pwfc, 1024, 4096);
        make_map(fn, &tmB_f2, pwf2, 4096, 1024);
        init_done = 1;
    }

    cudaEventRecord(evFork, 0);
    cudaStreamWaitEvent(sB, evFork, 0);
    prepB_kernel<<<9216, 256, 0, sB>>>(wproj, pwpr, wfc, pwfc, wfc2, pwf2);
    cudaEventRecord(evJoin, sB);

    prepA_kernel<<<3072, 256>>>(wattn, pwat, pimp);
    ln_kernel<<<M_, 256>>>(x, ln1w, ln1b, ph16);
    tcgemm_kernel<0><<<dim3(NQKV/128, M_/128), 256, GEMM_SMEM>>>(
        tmA_h, tmB_at, battn, nullptr, nullptr, nullptr, M_, NQKV, C_);
    fattn_kernel<<<dim3(T_/QT, B_*H_), 512, FA_SMEM>>>(pq16, pk16, pv16, am, py16, pimp);
    mask_kernel<<<16, 256>>>(pimp, am, thr, pmsk, out_mask, out_loss);

    cudaStreamWaitEvent(0, evJoin, 0);
    tcgemm_kernel<1><<<dim3(C_/128, M_/128), 256, GEMM_SMEM>>>(
        tmA_y, tmB_pr, bproj, x, pmsk, px2, M_, C_, C_);
    ln_kernel<<<M_, 256>>>(px2, ln2w, ln2b, ph16);
    tcgemm_kernel<2><<<dim3(NFC/128, M_/128), 256, GEMM_SMEM>>>(
        tmA_h, tmB_fc, bfc, nullptr, nullptr, nullptr, M_, NFC, C_);
    tcgemm_kernel<3><<<dim3(C_/128, M_/128), 256, GEMM_SMEM>>>(
        tmA_f, tmB_f2, bfc2, px2, nullptr, out_x, M_, C_, NFC);
}

// round 16
// speedup vs baseline: 1.8250x; 1.0285x over previous
#include <cuda_runtime.h>
#include <cuda.h>
#include <cuda_fp16.h>
#include <math.h>
#include <stdint.h>

#define B_ 4
#define T_ 1024
#define C_ 1024
#define H_ 16
#define D_ 64
#define M_ (B_*T_)      /* 4096 rows */
#define NQKV 3072
#define NFC  4096

// ---------------- scratch (__device__ globals: no allocation allowed) -------
__device__ float g_x2 [M_*C_];
__device__ float g_imp[M_];
__device__ __half g_q16[M_*C_];
__device__ __half g_k16[M_*C_];
__device__ __half g_v16[M_*C_];
__device__ __half g_h16[M_*C_];
__device__ __half g_y16[M_*C_];
__device__ __half g_f16[(size_t)M_*NFC];
__device__ __half g_wat[C_*NQKV];
__device__ __half g_wpr[C_*C_];
__device__ __half g_wfc[(size_t)C_*NFC];
__device__ __half g_wf2[(size_t)NFC*C_];

// ---------------- helpers ---------------------------------------------------
__device__ __forceinline__ void mma_f16(float c[4], const uint32_t a[4], const uint32_t b[2]) {
    asm volatile(
        "mma.sync.aligned.m16n8k16.row.col.f32.f16.f16.f32 "
        "{%0,%1,%2,%3}, {%4,%5,%6,%7}, {%8,%9}, {%0,%1,%2,%3};"
        : "+f"(c[0]), "+f"(c[1]), "+f"(c[2]), "+f"(c[3])
        : "r"(a[0]), "r"(a[1]), "r"(a[2]), "r"(a[3]), "r"(b[0]), "r"(b[1]));
}
__device__ __forceinline__ uint32_t smem_u32(const void* p) {
    return (uint32_t)__cvta_generic_to_shared(p);
}
__device__ __forceinline__ void ldmx4(uint32_t* r, uint32_t addr) {
    asm volatile("ldmatrix.sync.aligned.m8n8.x4.shared.b16 {%0,%1,%2,%3}, [%4];"
                 : "=r"(r[0]), "=r"(r[1]), "=r"(r[2]), "=r"(r[3]) : "r"(addr));
}
__device__ __forceinline__ void ldmx2(uint32_t& r0, uint32_t& r1, uint32_t addr) {
    asm volatile("ldmatrix.sync.aligned.m8n8.x2.shared.b16 {%0,%1}, [%2];"
                 : "=r"(r0), "=r"(r1) : "r"(addr));
}
__device__ __forceinline__ void ldmx2t(uint32_t& r0, uint32_t& r1, uint32_t addr) {
    asm volatile("ldmatrix.sync.aligned.m8n8.x2.trans.shared.b16 {%0,%1}, [%2];"
                 : "=r"(r0), "=r"(r1) : "r"(addr));
}
__device__ __forceinline__ float fexp8(float x) {
    float t = x * 0.18033688011112042f;
    float z = t + 12582912.0f;
    int   iz = __float_as_int(z);
    float fi = z - 12582912.0f;
    float f  = t - fi;
    float p = 0.0096181291f;
    p = p * f + 0.0555041087f;
    p = p * f + 0.2402265069f;
    p = p * f + 0.6931471806f;
    p = p * f + 1.0f;
    return __int_as_float(__float_as_int(p) + (iz << 23));
}
__device__ __forceinline__ void cp16(void* dst_smem, const void* src) {
    uint32_t d = (uint32_t)__cvta_generic_to_shared(dst_smem);
    asm volatile("cp.async.cg.shared.global [%0], [%1], 16;" :: "r"(d), "l"(src));
}
__device__ __forceinline__ void cp_commit() { asm volatile("cp.async.commit_group;"); }
template<int N_>
__device__ __forceinline__ void cp_wait() { asm volatile("cp.async.wait_group %0;" :: "n"(N_)); }
__device__ __forceinline__ void mbar_init(uint32_t a, uint32_t n) {
    asm volatile("mbarrier.init.shared.b64 [%0], %1;" :: "r"(a), "r"(n) : "memory");
}
__device__ __forceinline__ void mbar_expect(uint32_t a, uint32_t bytes) {
    asm volatile("mbarrier.arrive.expect_tx.shared.b64 _, [%0], %1;"
                 :: "r"(a), "r"(bytes) : "memory");
}
__device__ __forceinline__ void mbar_arrive(uint32_t a) {
    asm volatile("mbarrier.arrive.release.cta.shared.b64 _, [%0];" :: "r"(a) : "memory");
}
__device__ __forceinline__ void mbar_wait(uint32_t a, uint32_t par) {
    asm volatile("{\n\t.reg .pred P;\n\tWL%=:\n\t"
                 "mbarrier.try_wait.parity.acquire.cta.shared::cta.b64 P, [%0], %1, 0x989680;\n\t"
                 "@P bra WD%=;\n\tbra WL%=;\n\tWD%=:\n\t}"
                 :: "r"(a), "r"(par) : "memory");
}
__device__ __forceinline__ void tma2d(uint32_t dst, const void* map, int cx, int cy,
                                      uint32_t mbar) {
    asm volatile("cp.async.bulk.tensor.2d.shared::cluster.global.tile.mbarrier::complete_tx::bytes "
                 "[%0], [%1, {%2, %3}], [%4];"
                 :: "r"(dst), "l"(map), "r"(cx), "r"(cy), "r"(mbar) : "memory");
}

// ---------------- weight transpose tile (fp32 [K][N] -> fp16 [N][K]) --------
__device__ __forceinline__ void wtile(const float* __restrict__ W,
                                      __half* __restrict__ Oh,
                                      int K, int N, int bx, int by) {
    __shared__ float tile[32][33];
    int n0 = bx * 32, k0 = by * 32;
    int tx = threadIdx.x & 31, ty = threadIdx.x >> 5;
    #pragma unroll
    for (int i = 0; i < 4; i++)
        tile[ty + i * 8][tx] = W[(size_t)(k0 + ty + i * 8) * N + n0 + tx];
    __syncthreads();
    #pragma unroll
    for (int i = 0; i < 4; i++) {
        int n = n0 + ty + i * 8;
        Oh[(size_t)n * K + k0 + tx] = __float2half_rn(tile[tx][ty + i * 8]);
    }
}

__global__ void __launch_bounds__(256) prepA_kernel(const float* __restrict__ W,
                                                    __half* __restrict__ Oh,
                                                    float* __restrict__ imp) {
    int blk = blockIdx.x;
    if (blk < 16) imp[blk * 256 + threadIdx.x] = 0.f;
    wtile(W, Oh, C_, NQKV, blk % 96, blk / 96);
}

__global__ void __launch_bounds__(256) prepB_kernel(const float* __restrict__ Wpr,
                                                    __half* __restrict__ Opr,
                                                    const float* __restrict__ Wfc,
                                                    __half* __restrict__ Ofc,
                                                    const float* __restrict__ Wf2,
                                                    __half* __restrict__ Of2) {
    int blk = blockIdx.x;
    if (blk < 1024) {
        wtile(Wpr, Opr, C_, C_, blk % 32, blk / 32);
    } else if (blk < 5120) {
        int t = blk - 1024;
        wtile(Wfc, Ofc, C_, NFC, t % 128, t / 128);
    } else {
        int t = blk - 5120;
        wtile(Wf2, Of2, NFC, C_, t % 32, t / 32);
    }
}

// ---------------- layer norm -> fp16 ----------------------------------------
__global__ void __launch_bounds__(256) ln_kernel(const float* __restrict__ x,
                                                 const float* __restrict__ w,
                                                 const float* __restrict__ b,
                                                 __half* __restrict__ oh) {
    int row = blockIdx.x;
    int tid = threadIdx.x;
    __shared__ float buf[C_];
    __shared__ float red[8];
    const float* xr = x + (size_t)row * C_;
    float s = 0.f;
    #pragma unroll
    for (int j = tid; j < C_; j += 256) { float v = xr[j]; buf[j] = v; s += v; }
    #pragma unroll
    for (int o = 16; o; o >>= 1) s += __shfl_down_sync(~0u, s, o);
    if ((tid & 31) == 0) red[tid >> 5] = s;
    __syncthreads();
    if (tid < 8) {
        s = red[tid];
        #pragma unroll
        for (int o = 4; o; o >>= 1) s += __shfl_down_sync(0xff, s, o);
        if (tid == 0) red[0] = s;
    }
    __syncthreads();
    float mu = red[0] * (1.f / C_);
    __syncthreads();
    float ss = 0.f;
    #pragma unroll
    for (int j = tid; j < C_; j += 256) { float d = buf[j] - mu; ss += d * d; }
    #pragma unroll
    for (int o = 16; o; o >>= 1) ss += __shfl_down_sync(~0u, ss, o);
    if ((tid & 31) == 0) red[tid >> 5] = ss;
    __syncthreads();
    if (tid < 8) {
        ss = red[tid];
        #pragma unroll
        for (int o = 4; o; o >>= 1) ss += __shfl_down_sync(0xff, ss, o);
        if (tid == 0) red[0] = ss;
    }
    __syncthreads();
    float rstd = rsqrtf(red[0] * (1.f / C_) + 1e-5f);
    #pragma unroll
    for (int j = tid; j < C_; j += 256)
        oh[(size_t)row * C_ + j] = __float2half_rn((buf[j] - mu) * rstd * w[j] + b[j]);
}

// ------- fp16 GEMM: TMA K=64 stages, 3-ring, full/empty mbarriers -----------
#define STG 3
#define STAGE_BYTES 32768
#define GEMM_SMEM (STG*STAGE_BYTES + 64)

template<int EPI>
__global__ void __launch_bounds__(256, 2) tcgemm_kernel(
    const __grid_constant__ CUtensorMap tmA,
    const __grid_constant__ CUtensorMap tmB,
    const float* __restrict__ bias, const float* __restrict__ res,
    const float* __restrict__ mask, float* __restrict__ Cout,
    int M, int N, int K,
    const float* __restrict__ am2, const float* __restrict__ thr2,
    float* __restrict__ omask, float* __restrict__ oloss)
{
    extern __shared__ uint32_t smu[];
    uint32_t sbase = smem_u32(smu);
    uint32_t mbF = sbase + STG * STAGE_BYTES;
    uint32_t mbE = mbF + STG * 8;
    int tid  = threadIdx.x;
    int lane = tid & 31;
    int wid  = tid >> 5;
    int warpM = wid >> 2, warpN = wid & 3;
    int g  = lane >> 2, tg = lane & 3;
    int row0 = blockIdx.y * 128, col0 = blockIdx.x * 128;

    if (EPI == 1 && blockIdx.x == 0 && blockIdx.y == 0 && tid == 0)
        oloss[0] = 0.f;

    if (tid == 0) {
        #pragma unroll
        for (int s = 0; s < STG; s++) {
            mbar_init(mbF + s * 8, 1);
            mbar_init(mbE + s * 8, 256);
        }
    }
    __syncthreads();

    int nk = K >> 6;
    if (tid == 0) {
        #pragma unroll
        for (int p = 0; p < STG - 1; p++) {
            uint32_t mb = mbF + p * 8;
            uint32_t sb = sbase + p * STAGE_BYTES;
            mbar_expect(mb, STAGE_BYTES);
            tma2d(sb,         &tmA, p * 64,      row0, mb);
            tma2d(sb + 8192,  &tmA, p * 64 + 32, row0, mb);
            tma2d(sb + 16384, &tmB, p * 64,      col0, mb);
            tma2d(sb + 24576, &tmB, p * 64 + 32, col0, mb);
        }
    }

    int mBase = warpM * 64;
    int nBase = warpN * 32;

    int rl = lane & 7;
    int qh = (lane >> 3) & 1;
    int qc = lane >> 4;
    uint32_t offA[4], offB[4];
    #pragma unroll
    for (int mi = 0; mi < 4; mi++) {
        int r = mBase + mi * 16 + rl + qh * 8;
        offA[mi] = (uint32_t)(r * 64 + ((qc ^ ((r >> 1) & 3)) << 4));
    }
    int qb = (lane >> 3) & 1;
    #pragma unroll
    for (int ni = 0; ni < 4; ni++) {
        int r = nBase + ni * 8 + rl;
        offB[ni] = (uint32_t)(r * 64 + ((qb ^ ((r >> 1) & 3)) << 4));
    }

    float acc[4][4][4] = {};
    int st = 0, par = 0, st2 = STG - 1;
    int ep0 = 0, ep1 = 0, ep2 = 0;

    for (int kt = 0; kt < nk; kt++) {
        if (tid == 0 && kt + STG - 1 < nk) {
            int tk = kt + STG - 1;
            if (tk >= STG) {
                int p2 = (st2 == 0) ? ep0 : (st2 == 1) ? ep1 : ep2;
                mbar_wait(mbE + st2 * 8, (uint32_t)p2);
                if (st2 == 0) ep0 ^= 1; else if (st2 == 1) ep1 ^= 1; else ep2 ^= 1;
            }
            uint32_t mb = mbF + st2 * 8;
            uint32_t sb = sbase + st2 * STAGE_BYTES;
            mbar_expect(mb, STAGE_BYTES);
            tma2d(sb,         &tmA, tk * 64,      row0, mb);
            tma2d(sb + 8192,  &tmA, tk * 64 + 32, row0, mb);
            tma2d(sb + 16384, &tmB, tk * 64,      col0, mb);
            tma2d(sb + 24576, &tmB, tk * 64 + 32, col0, mb);
        }
        mbar_wait(mbF + st * 8, (uint32_t)par);
        uint32_t stA = sbase + st * STAGE_BYTES;
        uint32_t stB = stA + 16384;
        #pragma unroll
        for (int sub = 0; sub < 2; sub++) {
            uint32_t baseA = stA + sub * 8192;
            uint32_t baseB = stB + sub * 8192;
            #pragma unroll
            for (int kk2 = 0; kk2 < 2; kk2++) {
                uint32_t xv = kk2 * 32;
                uint32_t a[4][4], b[4][2];
                #pragma unroll
                for (int mi = 0; mi < 4; mi++) ldmx4(a[mi], baseA + (offA[mi] ^ xv));
                #pragma unroll
                for (int ni = 0; ni < 4; ni++) ldmx2(b[ni][0], b[ni][1], baseB + (offB[ni] ^ xv));
                #pragma unroll
                for (int mi = 0; mi < 4; mi++)
                    #pragma unroll
                    for (int ni = 0; ni < 4; ni++)
                        mma_f16(acc[mi][ni], a[mi], b[ni]);
            }
        }
        mbar_arrive(mbE + st * 8);
        st++; if (st == STG) { st = 0; par ^= 1; }
        st2++; if (st2 == STG) st2 = 0;
    }

    // ---- epilogue ----
    float thv = 0.f;
    if (EPI == 1) thv = thr2[0];
    #pragma unroll
    for (int mi = 0; mi < 4; mi++) {
        #pragma unroll
        for (int half = 0; half < 2; half++) {
            int ig = row0 + mBase + mi * 16 + g + half * 8;
            float mrow = 0.f;
            if (EPI == 1) {
                mrow = (mask[ig] >= thv) ? am2[ig] : 0.f;   // mask param = imp
                if (blockIdx.x == 0 && warpN == 0 && tg == 0)
                    omask[ig] = mrow;
            }
            #pragma unroll
            for (int ni = 0; ni < 4; ni++) {
                float v0 = acc[mi][ni][2 * half + 0];
                float v1 = acc[mi][ni][2 * half + 1];
                int jg = col0 + nBase + ni * 8 + tg * 2;
                if (EPI == 0) {
                    int bq = ig >> 10, t = ig & 1023;
                    int part = jg >> 10;
                    int c = jg & 1023;
                    int h = c >> 6, d = c & 63;
                    __half2 hv;
                    hv.x = __float2half_rn(v0 + bias[jg]);
                    hv.y = __float2half_rn(v1 + bias[jg + 1]);
                    __half* dst = (part == 0) ? g_q16 : (part == 1) ? g_k16 : g_v16;
                    *(__half2*)&dst[((size_t)(bq * H_ + h) * T_ + t) * D_ + d] = hv;
                } else if (EPI == 1) {
                    Cout[(size_t)ig * N + jg]     = (res[(size_t)ig * N + jg]     + v0 + bias[jg])     * mrow;
                    Cout[(size_t)ig * N + jg + 1] = (res[(size_t)ig * N + jg + 1] + v1 + bias[jg + 1]) * mrow;
                } else if (EPI == 2) {
                    float a0 = v0 + bias[jg], a1 = v1 + bias[jg + 1];
                    float g0 = 0.5f * a0 * (1.f + erff(a0 * 0.70710678118654752f));
                    float g1 = 0.5f * a1 * (1.f + erff(a1 * 0.70710678118654752f));
                    __half2 hv; hv.x = __float2half_rn(g0); hv.y = __float2half_rn(g1);
                    *(__half2*)&g_f16[(size_t)ig * N + jg] = hv;
                } else {
                    Cout[(size_t)ig * N + jg]     = res[(size_t)ig * N + jg]     + v0 + bias[jg];
                    Cout[(size_t)ig * N + jg + 1] = res[(size_t)ig * N + jg + 1] + v1 + bias[jg + 1];
                }
            }
        }
    }
}

// ======= FUSED FLASH ATTENTION (fp16, 2 CTA/SM, prefetched chunks) ==========
#define QT 32
#define SHSTR 524
#define QSTR 36
#define KVSTR 36
#define KVBYTES (128*KVSTR*4)          /* 18432 */
#define OFF_Q    67072
#define OFF_KV0  71680
#define OFF_KV1  (OFF_KV0 + KVBYTES)   /* 90112 */
#define OFF_AM   (OFF_KV1 + KVBYTES)   /* 108544 */
#define OFF_INV  (OFF_AM + 4096)       /* 112640 */
#define OFF_PART (OFF_INV + 128)       /* 112768 */
#define FA_SMEM  (OFF_PART + 1088)     /* 113856 */

__global__ void __launch_bounds__(512, 2) fattn_kernel(
    const __half* __restrict__ q, const __half* __restrict__ k,
    const __half* __restrict__ v, const float* __restrict__ am,
    __half* __restrict__ y16, float* __restrict__ imp)
{
    extern __shared__ char smc[];
    uint32_t* Shw = (uint32_t*)smc;
    uint32_t* Qs  = (uint32_t*)(smc + OFF_Q);
    uint32_t* KV0 = (uint32_t*)(smc + OFF_KV0);
    uint32_t* KV1 = (uint32_t*)(smc + OFF_KV1);
    float*    amS = (float*)(smc + OFF_AM);
    float*    invlS = (float*)(smc + OFF_INV);
    float*    part  = (float*)(smc + OFF_PART);

    int qt = gridDim.x - 1 - blockIdx.x;
    int bh = blockIdx.y;
    int b  = bh >> 4, h = bh & 15;
    int tid  = threadIdx.x;
    int lane = tid & 31;
    int wid  = tid >> 5;
    int g = lane >> 2, tg = lane & 3;

    int q0   = qt * QT;
    int kend = q0 + QT;
    int jmax = ((kend + 63) >> 6) << 6;
    int nch  = (jmax + 127) >> 7;

    const __half* qb = q + (size_t)bh * T_ * D_;
    const __half* kb = k + (size_t)bh * T_ * D_;
    const __half* vb = v + (size_t)bh * T_ * D_;

    // prefetch K chunk 0 (before Q loads, for latency head start)
    {
        int rows_here = min(128, jmax);
        for (int idx = tid; idx < rows_here * 8; idx += 512) {
            int r = idx >> 3, cs = idx & 7;
            cp16(KV0 + r * KVSTR + cs * 4, kb + (size_t)r * D_ + cs * 8);
        }
        cp_commit();
    }

    if (tid < 256) {
        int row = tid >> 3, cs = tid & 7;
        uint4 val = *(const uint4*)(qb + (size_t)(q0 + row) * D_ + cs * 8);
        *(uint4*)&Qs[row * QSTR + cs * 4] = val;
    }
    for (int j = tid; j < T_; j += 512)
        amS[j] = (am[b * T_ + j] != 0.f) ? 1.f : 0.f;
    __syncthreads();

    int warpRow = wid >> 3;
    int warpCol = wid & 7;
    int m0 = warpRow * 16;

    uint32_t aq[4][4];
    #pragma unroll
    for (int ks = 0; ks < 4; ks++) {
        aq[ks][0] = Qs[(m0 + g    ) * QSTR + ks * 8 + tg    ];
        aq[ks][1] = Qs[(m0 + g + 8) * QSTR + ks * 8 + tg    ];
        aq[ks][2] = Qs[(m0 + g    ) * QSTR + ks * 8 + 4 + tg];
        aq[ks][3] = Qs[(m0 + g + 8) * QSTR + ks * 8 + 4 + tg];
    }

    int qg0 = q0 + m0 + g;
    int qg1 = qg0 + 8;
    float rs0 = 0.f, rs1 = 0.f;
    uint32_t kvb0 = smem_u32(KV0);
    uint32_t kvb1 = smem_u32(KV1);
    uint32_t shbase = smem_u32(Shw);
    int rl = lane & 7, qb2 = (lane >> 3) & 1;
    int qh = (lane >> 3) & 1, qc = lane >> 4;
    uint32_t offK[2];
    #pragma unroll
    for (int f = 0; f < 2; f++)
        offK[f] = (uint32_t)((warpCol * 16 + f * 8 + rl) * 144 + qb2 * 16);
    uint32_t offS = (uint32_t)((m0 + rl + qh * 8) * (SHSTR * 4) + qc * 16);

    // ---- phase 1 ----
    for (int ic = 0; ic < nch; ic++) {
        int kc0 = ic * 128;
        int rows_here = min(128, jmax - kc0);
        bool interior = (kc0 + 127 <= q0);
        cp_wait<0>();
        __syncthreads();      // chunk ic ready; all threads done with chunk ic-1
        if (ic + 1 < nch) {   // prefetch ic+1 into other buffer (safe: see barrier)
            int nk0 = (ic + 1) * 128;
            int nrows = min(128, jmax - nk0);
            uint32_t* dst = ((ic + 1) & 1) ? KV1 : KV0;
            for (int idx = tid; idx < nrows * 8; idx += 512) {
                int r = idx >> 3, cs = idx & 7;
                cp16(dst + r * KVSTR + cs * 4, kb + (size_t)(nk0 + r) * D_ + cs * 8);
            }
        }
        cp_commit();
        uint32_t kvbase = (ic & 1) ? kvb1 : kvb0;
        if (warpCol * 16 < rows_here) {
            float acc[2][4] = {};
            #pragma unroll
            for (int ks = 0; ks < 4; ks++) {
                #pragma unroll
                for (int f = 0; f < 2; f++) {
                    uint32_t bb0, bb1;
                    ldmx2(bb0, bb1, kvbase + offK[f] + ks * 32);
                    uint32_t bb[2] = {bb0, bb1};
                    mma_f16(acc[f], aq[ks], bb);
                }
            }
            if (interior) {
                #pragma unroll
                for (int f = 0; f < 2; f++) {
                    int j0 = kc0 + warpCol * 16 + f * 8 + tg * 2;
                    float m0v = amS[j0], m1v = amS[j0 + 1];
                    float e00 = fexp8(acc[f][0]) * m0v;
                    float e01 = fexp8(acc[f][1]) * m1v;
                    float e10 = fexp8(acc[f][2]) * m0v;
                    float e11 = fexp8(acc[f][3]) * m1v;
                    rs0 += e00 + e01;
                    rs1 += e10 + e11;
                    __half2 p01 = __floats2half2_rn(e00, e01);
                    __half2 p23 = __floats2half2_rn(e10, e11);
                    int w0 = (j0 >> 1);
                    int r0 = m0 + g;
                    Shw[r0 * SHSTR + w0]       = *(uint32_t*)&p01;
                    Shw[(r0 + 8) * SHSTR + w0] = *(uint32_t*)&p23;
                }
            } else {
                #pragma unroll
                for (int f = 0; f < 2; f++) {
                    int j0 = kc0 + warpCol * 16 + f * 8 + tg * 2;
                    float m0v = amS[j0], m1v = amS[j0 + 1];
                    float e00 = (j0     <= qg0) ? fexp8(acc[f][0]) * m0v : 0.f;
                    float e01 = (j0 + 1 <= qg0) ? fexp8(acc[f][1]) * m1v : 0.f;
                    float e10 = (j0     <= qg1) ? fexp8(acc[f][2]) * m0v : 0.f;
                    float e11 = (j0 + 1 <= qg1) ? fexp8(acc[f][3]) * m1v : 0.f;
                    rs0 += e00 + e01;
                    rs1 += e10 + e11;
                    __half2 p01 = __floats2half2_rn(e00, e01);
                    __half2 p23 = __floats2half2_rn(e10, e11);
                    int w0 = (j0 >> 1);
                    int r0 = m0 + g;
                    Shw[r0 * SHSTR + w0]       = *(uint32_t*)&p01;
                    Shw[(r0 + 8) * SHSTR + w0] = *(uint32_t*)&p23;
                }
            }
        }
    }
    rs0 += __shfl_xor_sync(~0u, rs0, 1); rs0 += __shfl_xor_sync(~0u, rs0, 2);
    rs1 += __shfl_xor_sync(~0u, rs1, 1); rs1 += __shfl_xor_sync(~0u, rs1, 2);
    if (tg == 0) {
        part[wid * 17 + g]     = rs0;
        part[wid * 17 + g + 8] = rs1;
    }
    __syncthreads();
    if (tid < 32) {
        int wr = tid >> 4, lr = tid & 15;
        float s = 0.f;
        #pragma unroll
        for (int w = 0; w < 8; w++) s += part[(wr * 8 + w) * 17 + lr];
        invlS[tid] = 1.f / s;
    }
    __syncthreads();

    // prefetch V chunk 0 (all phase-1 KV reads are behind the barriers above)
    {
        int rows_here = min(128, jmax);
        for (int idx = tid; idx < rows_here * 8; idx += 512) {
            int r = idx >> 3, cs = idx & 7;
            cp16(KV0 + r * KVSTR + cs * 4, vb + (size_t)r * D_ + cs * 8);
        }
        cp_commit();
    }

    if (2 * tid < kend) {
        float cs0 = 0.f, cs1 = 0.f;
        #pragma unroll
        for (int r = 0; r < QT; r++) {
            uint32_t pw = Shw[r * SHSTR + tid];
            __half2 ph = *(__half2*)&pw;
            float wgt = invlS[r];
            cs0 += __half2float(ph.x) * wgt;
            cs1 += __half2float(ph.y) * wgt;
        }
        atomicAdd(&imp[b * T_ + 2 * tid],     cs0 * (1.f / (H_ * T_)));
        atomicAdd(&imp[b * T_ + 2 * tid + 1], cs1 * (1.f / (H_ * T_)));
    }

    // ---- phase 3 ----
    int col0 = warpCol * 8;
    float acc[4] = {};
    for (int ic = 0; ic < nch; ic++) {
        int kc0 = ic * 128;
        int rows_here = min(128, jmax - kc0);
        cp_wait<0>();
        __syncthreads();
        if (ic + 1 < nch) {
            int nk0 = (ic + 1) * 128;
            int nrows = min(128, jmax - nk0);
            uint32_t* dst = ((ic + 1) & 1) ? KV1 : KV0;
            for (int idx = tid; idx < nrows * 8; idx += 512) {
                int r = idx >> 3, cs = idx & 7;
                cp16(dst + r * KVSTR + cs * 4, vb + (size_t)(nk0 + r) * D_ + cs * 8);
            }
        }
        cp_commit();
        uint32_t kvbase = (ic & 1) ? kvb1 : kvb0;
        int ksteps = rows_here >> 4;
        for (int ks = 0; ks < ksteps; ks++) {
            uint32_t a[4], bb[2];
            ldmx4(a, shbase + offS + (uint32_t)((kc0 + ks * 16) * 2));
            uint32_t addr = kvbase + ((ks * 16 + (lane & 15)) * 72 + col0) * 2;
            ldmx2t(bb[0], bb[1], addr);
            mma_f16(acc, a, bb);
        }
    }
    float sc0 = invlS[m0 + g], sc1 = invlS[m0 + g + 8];
    #pragma unroll
    for (int half = 0; half < 2; half++) {
        int t = q0 + m0 + g + half * 8;
        int d = h * 64 + col0 + tg * 2;
        float s = half ? sc1 : sc0;
        __half2 hv;
        hv.x = __float2half_rn(acc[2 * half] * s);
        hv.y = __float2half_rn(acc[2 * half + 1] * s);
        *(__half2*)&y16[(size_t)(b * T_ + t) * C_ + d] = hv;
    }
}

// ---------------- launch ----------------------------------------------------
typedef CUresult (*EncodeFn)(CUtensorMap*, CUtensorMapDataType, cuuint32_t, void*,
                             const cuuint64_t*, const cuuint64_t*, const cuuint32_t*,
                             const cuuint32_t*, CUtensorMapInterleave, CUtensorMapSwizzle,
                             CUtensorMapL2promotion, CUtensorMapFloatOOBfill);

static void make_map(EncodeFn fn, CUtensorMap* m, void* addr, uint64_t K, uint64_t rows) {
    cuuint64_t dims[2]    = {K, rows};
    cuuint64_t strides[1] = {K * 2};
    cuuint32_t box[2]     = {32, 128};
    cuuint32_t estr[2]    = {1, 1};
    fn(m, CU_TENSOR_MAP_DATA_TYPE_UINT16, 2, addr, dims, strides, box, estr,
       CU_TENSOR_MAP_INTERLEAVE_NONE, CU_TENSOR_MAP_SWIZZLE_64B,
       CU_TENSOR_MAP_L2_PROMOTION_L2_128B, CU_TENSOR_MAP_FLOAT_OOB_FILL_NONE);
}

extern "C" void kernel_launch(void* const* d_in, const int* in_sizes, int n_in,
                              void* d_out, int out_size) {
    const float* x     = (const float*)d_in[0];
    const float* am    = (const float*)d_in[1];
    const float* ln1w  = (const float*)d_in[2];
    const float* ln1b  = (const float*)d_in[3];
    const float* wattn = (const float*)d_in[4];
    const float* battn = (const float*)d_in[5];
    const float* wproj = (const float*)d_in[6];
    const float* bproj = (const float*)d_in[7];
    const float* thr   = (const float*)d_in[8];
    const float* ln2w  = (const float*)d_in[9];
    const float* ln2b  = (const float*)d_in[10];
    const float* wfc   = (const float*)d_in[11];
    const float* bfc   = (const float*)d_in[12];
    const float* wfc2  = (const float*)d_in[13];
    const float* bfc2  = (const float*)d_in[14];

    float* out      = (float*)d_out;
    float* out_x    = out;
    float* out_mask = out + out_size - 1 - M_;
    float* out_loss = out + out_size - 1;

    float *px2, *pimp;
    cudaGetSymbolAddress((void**)&px2,  g_x2);
    cudaGetSymbolAddress((void**)&pimp, g_imp);
    __half *pq16, *pk16, *pv16, *ph16, *py16, *pf16, *pwat, *pwpr, *pwfc, *pwf2;
    cudaGetSymbolAddress((void**)&pq16, g_q16);
    cudaGetSymbolAddress((void**)&pk16, g_k16);
    cudaGetSymbolAddress((void**)&pv16, g_v16);
    cudaGetSymbolAddress((void**)&ph16, g_h16);
    cudaGetSymbolAddress((void**)&py16, g_y16);
    cudaGetSymbolAddress((void**)&pf16, g_f16);
    cudaGetSymbolAddress((void**)&pwat, g_wat);
    cudaGetSymbolAddress((void**)&pwpr, g_wpr);
    cudaGetSymbolAddress((void**)&pwfc, g_wfc);
    cudaGetSymbolAddress((void**)&pwf2, g_wf2);

    static cudaStream_t sB = nullptr;
    static cudaEvent_t evFork = nullptr, evJoin = nullptr;
    static CUtensorMap tmA_h, tmA_y, tmA_f, tmB_at, tmB_pr, tmB_fc, tmB_f2;
    static int init_done = 0;
    if (!init_done) {
        cudaFuncSetAttribute(fattn_kernel,
                             cudaFuncAttributeMaxDynamicSharedMemorySize, FA_SMEM);
        cudaFuncSetAttribute(tcgemm_kernel<0>,
                             cudaFuncAttributeMaxDynamicSharedMemorySize, GEMM_SMEM);
        cudaFuncSetAttribute(tcgemm_kernel<1>,
                             cudaFuncAttributeMaxDynamicSharedMemorySize, GEMM_SMEM);
        cudaFuncSetAttribute(tcgemm_kernel<2>,
                             cudaFuncAttributeMaxDynamicSharedMemorySize, GEMM_SMEM);
        cudaFuncSetAttribute(tcgemm_kernel<3>,
                             cudaFuncAttributeMaxDynamicSharedMemorySize, GEMM_SMEM);
        cudaStreamCreateWithFlags(&sB, cudaStreamNonBlocking);
        cudaEventCreateWithFlags(&evFork, cudaEventDisableTiming);
        cudaEventCreateWithFlags(&evJoin, cudaEventDisableTiming);

        EncodeFn fn = nullptr;
        cudaDriverEntryPointQueryResult qres;
        cudaGetDriverEntryPoint("cuTensorMapEncodeTiled", (void**)&fn,
                                cudaEnableDefault, &qres);
        make_map(fn, &tmA_h,  ph16, 1024, 4096);
        make_map(fn, &tmA_y,  py16, 1024, 4096);
        make_map(fn, &tmA_f,  pf16, 4096, 4096);
        make_map(fn, &tmB_at, pwat, 1024, 3072);
        make_map(fn, &tmB_pr, pwpr, 1024, 1024);
        make_map(fn, &tmB_fc, pwfc, 1024, 4096);
        make_map(fn, &tmB_f2, pwf2, 4096, 1024);
        init_done = 1;
    }

    cudaEventRecord(evFork, 0);
    cudaStreamWaitEvent(sB, evFork, 0);
    prepB_kernel<<<9216, 256, 0, sB>>>(wproj, pwpr, wfc, pwfc, wfc2, pwf2);
    cudaEventRecord(evJoin, sB);

    prepA_kernel<<<3072, 256>>>(wattn, pwat, pimp);
    ln_kernel<<<M_, 256>>>(x, ln1w, ln1b, ph16);
    tcgemm_kernel<0><<<dim3(NQKV/128, M_/128), 256, GEMM_SMEM>>>(
        tmA_h, tmB_at, battn, nullptr, nullptr, nullptr, M_, NQKV, C_,
        nullptr, nullptr, nullptr, nullptr);
    fattn_kernel<<<dim3(T_/QT, B_*H_), 512, FA_SMEM>>>(pq16, pk16, pv16, am, py16, pimp);

    cudaStreamWaitEvent(0, evJoin, 0);
    tcgemm_kernel<1><<<dim3(C_/128, M_/128), 256, GEMM_SMEM>>>(
        tmA_y, tmB_pr, bproj, x, pimp, px2, M_, C_, C_,
        am, thr, out_mask, out_loss);
    ln_kernel<<<M_, 256>>>(px2, ln2w, ln2b, ph16);
    tcgemm_kernel<2><<<dim3(NFC/128, M_/128), 256, GEMM_SMEM>>>(
        tmA_h, tmB_fc, bfc, nullptr, nullptr, nullptr, M_, NFC, C_,
        nullptr, nullptr, nullptr, nullptr);
    tcgemm_kernel<3><<<dim3(C_/128, M_/128), 256, GEMM_SMEM>>>(
        tmA_f, tmB_f2, bfc2, px2, nullptr, out_x, M_, C_, NFC,
        nullptr, nullptr, nullptr, nullptr);
}

// round 17
// speedup vs baseline: 1.8350x; 1.0054x over previous
#include <cuda_runtime.h>
#include <cuda.h>
#include <cuda_fp16.h>
#include <math.h>
#include <stdint.h>

#define B_ 4
#define T_ 1024
#define C_ 1024
#define H_ 16
#define D_ 64
#define M_ (B_*T_)      /* 4096 rows */
#define NQKV 3072
#define NFC  4096

// ---------------- scratch (__device__ globals: no allocation allowed) -------
__device__ float g_x2 [M_*C_];
__device__ float g_imp[M_];
__device__ __half g_q16[M_*C_];
__device__ __half g_k16[M_*C_];
__device__ __half g_v16[M_*C_];
__device__ __half g_h16[M_*C_];
__device__ __half g_y16[M_*C_];
__device__ __half g_f16[(size_t)M_*NFC];
__device__ __half g_wat[C_*NQKV];
__device__ __half g_wpr[C_*C_];
__device__ __half g_wfc[(size_t)C_*NFC];
__device__ __half g_wf2[(size_t)NFC*C_];

// ---------------- helpers ---------------------------------------------------
__device__ __forceinline__ void mma_f16(float c[4], const uint32_t a[4], const uint32_t b[2]) {
    asm volatile(
        "mma.sync.aligned.m16n8k16.row.col.f32.f16.f16.f32 "
        "{%0,%1,%2,%3}, {%4,%5,%6,%7}, {%8,%9}, {%0,%1,%2,%3};"
        : "+f"(c[0]), "+f"(c[1]), "+f"(c[2]), "+f"(c[3])
        : "r"(a[0]), "r"(a[1]), "r"(a[2]), "r"(a[3]), "r"(b[0]), "r"(b[1]));
}
__device__ __forceinline__ uint32_t smem_u32(const void* p) {
    return (uint32_t)__cvta_generic_to_shared(p);
}
__device__ __forceinline__ void ldmx4(uint32_t* r, uint32_t addr) {
    asm volatile("ldmatrix.sync.aligned.m8n8.x4.shared.b16 {%0,%1,%2,%3}, [%4];"
                 : "=r"(r[0]), "=r"(r[1]), "=r"(r[2]), "=r"(r[3]) : "r"(addr));
}
__device__ __forceinline__ void ldmx2(uint32_t& r0, uint32_t& r1, uint32_t addr) {
    asm volatile("ldmatrix.sync.aligned.m8n8.x2.shared.b16 {%0,%1}, [%2];"
                 : "=r"(r0), "=r"(r1) : "r"(addr));
}
__device__ __forceinline__ void ldmx2t(uint32_t& r0, uint32_t& r1, uint32_t addr) {
    asm volatile("ldmatrix.sync.aligned.m8n8.x2.trans.shared.b16 {%0,%1}, [%2];"
                 : "=r"(r0), "=r"(r1) : "r"(addr));
}
__device__ __forceinline__ float fexp8(float x) {
    float t = x * 0.18033688011112042f;
    float z = t + 12582912.0f;
    int   iz = __float_as_int(z);
    float fi = z - 12582912.0f;
    float f  = t - fi;
    float p = 0.0096181291f;
    p = p * f + 0.0555041087f;
    p = p * f + 0.2402265069f;
    p = p * f + 0.6931471806f;
    p = p * f + 1.0f;
    return __int_as_float(__float_as_int(p) + (iz << 23));
}
__device__ __forceinline__ void cp16(void* dst_smem, const void* src) {
    uint32_t d = (uint32_t)__cvta_generic_to_shared(dst_smem);
    asm volatile("cp.async.cg.shared.global [%0], [%1], 16;" :: "r"(d), "l"(src));
}
__device__ __forceinline__ void cp_commit() { asm volatile("cp.async.commit_group;"); }
template<int N_>
__device__ __forceinline__ void cp_wait() { asm volatile("cp.async.wait_group %0;" :: "n"(N_)); }
__device__ __forceinline__ void mbar_init(uint32_t a, uint32_t n) {
    asm volatile("mbarrier.init.shared.b64 [%0], %1;" :: "r"(a), "r"(n) : "memory");
}
__device__ __forceinline__ void mbar_expect(uint32_t a, uint32_t bytes) {
    asm volatile("mbarrier.arrive.expect_tx.shared.b64 _, [%0], %1;"
                 :: "r"(a), "r"(bytes) : "memory");
}
__device__ __forceinline__ void mbar_arrive(uint32_t a) {
    asm volatile("mbarrier.arrive.release.cta.shared.b64 _, [%0];" :: "r"(a) : "memory");
}
__device__ __forceinline__ void mbar_wait(uint32_t a, uint32_t par) {
    asm volatile("{\n\t.reg .pred P;\n\tWL%=:\n\t"
                 "mbarrier.try_wait.parity.acquire.cta.shared::cta.b64 P, [%0], %1, 0x989680;\n\t"
                 "@P bra WD%=;\n\tbra WL%=;\n\tWD%=:\n\t}"
                 :: "r"(a), "r"(par) : "memory");
}
__device__ __forceinline__ void tma2d(uint32_t dst, const void* map, int cx, int cy,
                                      uint32_t mbar) {
    asm volatile("cp.async.bulk.tensor.2d.shared::cluster.global.tile.mbarrier::complete_tx::bytes "
                 "[%0], [%1, {%2, %3}], [%4];"
                 :: "r"(dst), "l"(map), "r"(cx), "r"(cy), "r"(mbar) : "memory");
}

// ---------------- weight transpose tile (fp32 [K][N] -> fp16 [N][K]) --------
__device__ __forceinline__ void wtile(const float* __restrict__ W,
                                      __half* __restrict__ Oh,
                                      int K, int N, int bx, int by) {
    __shared__ float tile[32][33];
    int n0 = bx * 32, k0 = by * 32;
    int tx = threadIdx.x & 31, ty = threadIdx.x >> 5;
    #pragma unroll
    for (int i = 0; i < 4; i++)
        tile[ty + i * 8][tx] = W[(size_t)(k0 + ty + i * 8) * N + n0 + tx];
    __syncthreads();
    #pragma unroll
    for (int i = 0; i < 4; i++) {
        int n = n0 + ty + i * 8;
        Oh[(size_t)n * K + k0 + tx] = __float2half_rn(tile[tx][ty + i * 8]);
    }
}

__global__ void __launch_bounds__(256) prepA_kernel(const float* __restrict__ W,
                                                    __half* __restrict__ Oh,
                                                    float* __restrict__ imp) {
    int blk = blockIdx.x;
    if (blk < 16) imp[blk * 256 + threadIdx.x] = 0.f;
    wtile(W, Oh, C_, NQKV, blk % 96, blk / 96);
}

__global__ void __launch_bounds__(256) prepB_kernel(const float* __restrict__ Wpr,
                                                    __half* __restrict__ Opr,
                                                    const float* __restrict__ Wfc,
                                                    __half* __restrict__ Ofc,
                                                    const float* __restrict__ Wf2,
                                                    __half* __restrict__ Of2) {
    int blk = blockIdx.x;
    if (blk < 1024) {
        wtile(Wpr, Opr, C_, C_, blk % 32, blk / 32);
    } else if (blk < 5120) {
        int t = blk - 1024;
        wtile(Wfc, Ofc, C_, NFC, t % 128, t / 128);
    } else {
        int t = blk - 5120;
        wtile(Wf2, Of2, NFC, C_, t % 32, t / 32);
    }
}

// ---------------- layer norm -> fp16 ----------------------------------------
__global__ void __launch_bounds__(256) ln_kernel(const float* __restrict__ x,
                                                 const float* __restrict__ w,
                                                 const float* __restrict__ b,
                                                 __half* __restrict__ oh) {
    int row = blockIdx.x;
    int tid = threadIdx.x;
    __shared__ float buf[C_];
    __shared__ float red[8];
    const float* xr = x + (size_t)row * C_;
    float s = 0.f;
    #pragma unroll
    for (int j = tid; j < C_; j += 256) { float v = xr[j]; buf[j] = v; s += v; }
    #pragma unroll
    for (int o = 16; o; o >>= 1) s += __shfl_down_sync(~0u, s, o);
    if ((tid & 31) == 0) red[tid >> 5] = s;
    __syncthreads();
    if (tid < 8) {
        s = red[tid];
        #pragma unroll
        for (int o = 4; o; o >>= 1) s += __shfl_down_sync(0xff, s, o);
        if (tid == 0) red[0] = s;
    }
    __syncthreads();
    float mu = red[0] * (1.f / C_);
    __syncthreads();
    float ss = 0.f;
    #pragma unroll
    for (int j = tid; j < C_; j += 256) { float d = buf[j] - mu; ss += d * d; }
    #pragma unroll
    for (int o = 16; o; o >>= 1) ss += __shfl_down_sync(~0u, ss, o);
    if ((tid & 31) == 0) red[tid >> 5] = ss;
    __syncthreads();
    if (tid < 8) {
        ss = red[tid];
        #pragma unroll
        for (int o = 4; o; o >>= 1) ss += __shfl_down_sync(0xff, ss, o);
        if (tid == 0) red[0] = ss;
    }
    __syncthreads();
    float rstd = rsqrtf(red[0] * (1.f / C_) + 1e-5f);
    #pragma unroll
    for (int j = tid; j < C_; j += 256)
        oh[(size_t)row * C_ + j] = __float2half_rn((buf[j] - mu) * rstd * w[j] + b[j]);
}

// ------- fp16 GEMM: TMA K=64 stages, 3-ring, full/empty mbarriers -----------
#define STG 3
#define STAGE_BYTES 32768
#define GEMM_SMEM (STG*STAGE_BYTES + 64)

template<int EPI>
__global__ void __launch_bounds__(256, 2) tcgemm_kernel(
    const __grid_constant__ CUtensorMap tmA,
    const __grid_constant__ CUtensorMap tmB,
    const float* __restrict__ bias, const float* __restrict__ res,
    const float* __restrict__ mask, float* __restrict__ Cout,
    int M, int N, int K,
    const float* __restrict__ am2, const float* __restrict__ thr2,
    float* __restrict__ omask, float* __restrict__ oloss)
{
    extern __shared__ uint32_t smu[];
    uint32_t sbase = smem_u32(smu);
    uint32_t mbF = sbase + STG * STAGE_BYTES;
    uint32_t mbE = mbF + STG * 8;
    int tid  = threadIdx.x;
    int lane = tid & 31;
    int wid  = tid >> 5;
    int warpM = wid >> 2, warpN = wid & 3;
    int g  = lane >> 2, tg = lane & 3;
    int row0 = blockIdx.y * 128, col0 = blockIdx.x * 128;

    if (EPI == 1 && blockIdx.x == 0 && blockIdx.y == 0 && tid == 0)
        oloss[0] = 0.f;

    if (tid == 0) {
        #pragma unroll
        for (int s = 0; s < STG; s++) {
            mbar_init(mbF + s * 8, 1);
            mbar_init(mbE + s * 8, 8);     // one arrive per warp
        }
    }
    __syncthreads();

    int nk = K >> 6;
    if (tid == 0) {
        #pragma unroll
        for (int p = 0; p < STG - 1; p++) {
            uint32_t mb = mbF + p * 8;
            uint32_t sb = sbase + p * STAGE_BYTES;
            mbar_expect(mb, STAGE_BYTES);
            tma2d(sb,         &tmA, p * 64,      row0, mb);
            tma2d(sb + 8192,  &tmA, p * 64 + 32, row0, mb);
            tma2d(sb + 16384, &tmB, p * 64,      col0, mb);
            tma2d(sb + 24576, &tmB, p * 64 + 32, col0, mb);
        }
    }

    int mBase = warpM * 64;
    int nBase = warpN * 32;

    int rl = lane & 7;
    int qh = (lane >> 3) & 1;
    int qc = lane >> 4;
    uint32_t offA[4], offB[4];
    #pragma unroll
    for (int mi = 0; mi < 4; mi++) {
        int r = mBase + mi * 16 + rl + qh * 8;
        offA[mi] = (uint32_t)(r * 64 + ((qc ^ ((r >> 1) & 3)) << 4));
    }
    int qb = (lane >> 3) & 1;
    #pragma unroll
    for (int ni = 0; ni < 4; ni++) {
        int r = nBase + ni * 8 + rl;
        offB[ni] = (uint32_t)(r * 64 + ((qb ^ ((r >> 1) & 3)) << 4));
    }

    float acc[4][4][4] = {};
    int st = 0, par = 0, st2 = STG - 1;
    int ep0 = 0, ep1 = 0, ep2 = 0;

    for (int kt = 0; kt < nk; kt++) {
        if (tid == 0 && kt + STG - 1 < nk) {
            int tk = kt + STG - 1;
            if (tk >= STG) {
                int p2 = (st2 == 0) ? ep0 : (st2 == 1) ? ep1 : ep2;
                mbar_wait(mbE + st2 * 8, (uint32_t)p2);
                if (st2 == 0) ep0 ^= 1; else if (st2 == 1) ep1 ^= 1; else ep2 ^= 1;
            }
            uint32_t mb = mbF + st2 * 8;
            uint32_t sb = sbase + st2 * STAGE_BYTES;
            mbar_expect(mb, STAGE_BYTES);
            tma2d(sb,         &tmA, tk * 64,      row0, mb);
            tma2d(sb + 8192,  &tmA, tk * 64 + 32, row0, mb);
            tma2d(sb + 16384, &tmB, tk * 64,      col0, mb);
            tma2d(sb + 24576, &tmB, tk * 64 + 32, col0, mb);
        }
        mbar_wait(mbF + st * 8, (uint32_t)par);
        uint32_t stA = sbase + st * STAGE_BYTES;
        uint32_t stB = stA + 16384;
        #pragma unroll
        for (int sub = 0; sub < 2; sub++) {
            uint32_t baseA = stA + sub * 8192;
            uint32_t baseB = stB + sub * 8192;
            #pragma unroll
            for (int kk2 = 0; kk2 < 2; kk2++) {
                uint32_t xv = kk2 * 32;
                uint32_t a[4][4], b[4][2];
                #pragma unroll
                for (int mi = 0; mi < 4; mi++) ldmx4(a[mi], baseA + (offA[mi] ^ xv));
                #pragma unroll
                for (int ni = 0; ni < 4; ni++) ldmx2(b[ni][0], b[ni][1], baseB + (offB[ni] ^ xv));
                #pragma unroll
                for (int mi = 0; mi < 4; mi++)
                    #pragma unroll
                    for (int ni = 0; ni < 4; ni++)
                        mma_f16(acc[mi][ni], a[mi], b[ni]);
            }
        }
        if (lane == 0) mbar_arrive(mbE + st * 8);
        st++; if (st == STG) { st = 0; par ^= 1; }
        st2++; if (st2 == STG) st2 = 0;
    }

    // ---- epilogue ----
    float thv = 0.f;
    if (EPI == 1) thv = thr2[0];
    #pragma unroll
    for (int mi = 0; mi < 4; mi++) {
        #pragma unroll
        for (int half = 0; half < 2; half++) {
            int ig = row0 + mBase + mi * 16 + g + half * 8;
            float mrow = 0.f;
            if (EPI == 1) {
                mrow = (mask[ig] >= thv) ? am2[ig] : 0.f;   // mask param = imp
                if (blockIdx.x == 0 && warpN == 0 && tg == 0)
                    omask[ig] = mrow;
            }
            #pragma unroll
            for (int ni = 0; ni < 4; ni++) {
                float v0 = acc[mi][ni][2 * half + 0];
                float v1 = acc[mi][ni][2 * half + 1];
                int jg = col0 + nBase + ni * 8 + tg * 2;
                if (EPI == 0) {
                    int bq = ig >> 10, t = ig & 1023;
                    int part = jg >> 10;
                    int c = jg & 1023;
                    int h = c >> 6, d = c & 63;
                    __half2 hv;
                    hv.x = __float2half_rn(v0 + bias[jg]);
                    hv.y = __float2half_rn(v1 + bias[jg + 1]);
                    __half* dst = (part == 0) ? g_q16 : (part == 1) ? g_k16 : g_v16;
                    *(__half2*)&dst[((size_t)(bq * H_ + h) * T_ + t) * D_ + d] = hv;
                } else if (EPI == 1) {
                    Cout[(size_t)ig * N + jg]     = (res[(size_t)ig * N + jg]     + v0 + bias[jg])     * mrow;
                    Cout[(size_t)ig * N + jg + 1] = (res[(size_t)ig * N + jg + 1] + v1 + bias[jg + 1]) * mrow;
                } else if (EPI == 2) {
                    float a0 = v0 + bias[jg], a1 = v1 + bias[jg + 1];
                    float g0 = 0.5f * a0 * (1.f + erff(a0 * 0.70710678118654752f));
                    float g1 = 0.5f * a1 * (1.f + erff(a1 * 0.70710678118654752f));
                    __half2 hv; hv.x = __float2half_rn(g0); hv.y = __float2half_rn(g1);
                    *(__half2*)&g_f16[(size_t)ig * N + jg] = hv;
                } else {
                    Cout[(size_t)ig * N + jg]     = res[(size_t)ig * N + jg]     + v0 + bias[jg];
                    Cout[(size_t)ig * N + jg + 1] = res[(size_t)ig * N + jg + 1] + v1 + bias[jg + 1];
                }
            }
        }
    }
}

// ======= FUSED FLASH ATTENTION (fp16, 2 CTA/SM, prefetched chunks) ==========
#define QT 32
#define SHSTR 524
#define QSTR 36
#define KVSTR 36
#define KVBYTES (128*KVSTR*4)
#define OFF_Q    67072
#define OFF_KV0  71680
#define OFF_KV1  (OFF_KV0 + KVBYTES)
#define OFF_AM   (OFF_KV1 + KVBYTES)
#define OFF_INV  (OFF_AM + 4096)
#define OFF_PART (OFF_INV + 128)
#define FA_SMEM  (OFF_PART + 1088)

__global__ void __launch_bounds__(512, 2) fattn_kernel(
    const __half* __restrict__ q, const __half* __restrict__ k,
    const __half* __restrict__ v, const float* __restrict__ am,
    __half* __restrict__ y16, float* __restrict__ imp)
{
    extern __shared__ char smc[];
    uint32_t* Shw = (uint32_t*)smc;
    uint32_t* Qs  = (uint32_t*)(smc + OFF_Q);
    uint32_t* KV0 = (uint32_t*)(smc + OFF_KV0);
    uint32_t* KV1 = (uint32_t*)(smc + OFF_KV1);
    float*    amS = (float*)(smc + OFF_AM);
    float*    invlS = (float*)(smc + OFF_INV);
    float*    part  = (float*)(smc + OFF_PART);

    int qt = gridDim.x - 1 - blockIdx.x;
    int bh = blockIdx.y;
    int b  = bh >> 4, h = bh & 15;
    int tid  = threadIdx.x;
    int lane = tid & 31;
    int wid  = tid >> 5;
    int g = lane >> 2, tg = lane & 3;

    int q0   = qt * QT;
    int kend = q0 + QT;
    int jmax = ((kend + 63) >> 6) << 6;
    int nch  = (jmax + 127) >> 7;

    const __half* qb = q + (size_t)bh * T_ * D_;
    const __half* kb = k + (size_t)bh * T_ * D_;
    const __half* vb = v + (size_t)bh * T_ * D_;

    {
        int rows_here = min(128, jmax);
        for (int idx = tid; idx < rows_here * 8; idx += 512) {
            int r = idx >> 3, cs = idx & 7;
            cp16(KV0 + r * KVSTR + cs * 4, kb + (size_t)r * D_ + cs * 8);
        }
        cp_commit();
    }

    if (tid < 256) {
        int row = tid >> 3, cs = tid & 7;
        uint4 val = *(const uint4*)(qb + (size_t)(q0 + row) * D_ + cs * 8);
        *(uint4*)&Qs[row * QSTR + cs * 4] = val;
    }
    for (int j = tid; j < T_; j += 512)
        amS[j] = (am[b * T_ + j] != 0.f) ? 1.f : 0.f;
    __syncthreads();

    int warpRow = wid >> 3;
    int warpCol = wid & 7;
    int m0 = warpRow * 16;

    uint32_t aq[4][4];
    #pragma unroll
    for (int ks = 0; ks < 4; ks++) {
        aq[ks][0] = Qs[(m0 + g    ) * QSTR + ks * 8 + tg    ];
        aq[ks][1] = Qs[(m0 + g + 8) * QSTR + ks * 8 + tg    ];
        aq[ks][2] = Qs[(m0 + g    ) * QSTR + ks * 8 + 4 + tg];
        aq[ks][3] = Qs[(m0 + g + 8) * QSTR + ks * 8 + 4 + tg];
    }

    int qg0 = q0 + m0 + g;
    int qg1 = qg0 + 8;
    float rs0 = 0.f, rs1 = 0.f;
    uint32_t kvb0 = smem_u32(KV0);
    uint32_t kvb1 = smem_u32(KV1);
    uint32_t shbase = smem_u32(Shw);
    int rl = lane & 7, qb2 = (lane >> 3) & 1;
    int qh = (lane >> 3) & 1, qc = lane >> 4;
    uint32_t offK[2];
    #pragma unroll
    for (int f = 0; f < 2; f++)
        offK[f] = (uint32_t)((warpCol * 16 + f * 8 + rl) * 144 + qb2 * 16);
    uint32_t offS = (uint32_t)((m0 + rl + qh * 8) * (SHSTR * 4) + qc * 16);

    // ---- phase 1 ----
    for (int ic = 0; ic < nch; ic++) {
        int kc0 = ic * 128;
        int rows_here = min(128, jmax - kc0);
        bool interior = (kc0 + 127 <= q0);
        cp_wait<0>();
        __syncthreads();
        if (ic + 1 < nch) {
            int nk0 = (ic + 1) * 128;
            int nrows = min(128, jmax - nk0);
            uint32_t* dst = ((ic + 1) & 1) ? KV1 : KV0;
            for (int idx = tid; idx < nrows * 8; idx += 512) {
                int r = idx >> 3, cs = idx & 7;
                cp16(dst + r * KVSTR + cs * 4, kb + (size_t)(nk0 + r) * D_ + cs * 8);
            }
        }
        cp_commit();
        uint32_t kvbase = (ic & 1) ? kvb1 : kvb0;
        if (warpCol * 16 < rows_here) {
            float acc[2][4] = {};
            #pragma unroll
            for (int ks = 0; ks < 4; ks++) {
                #pragma unroll
                for (int f = 0; f < 2; f++) {
                    uint32_t bb0, bb1;
                    ldmx2(bb0, bb1, kvbase + offK[f] + ks * 32);
                    uint32_t bb[2] = {bb0, bb1};
                    mma_f16(acc[f], aq[ks], bb);
                }
            }
            if (interior) {
                #pragma unroll
                for (int f = 0; f < 2; f++) {
                    int j0 = kc0 + warpCol * 16 + f * 8 + tg * 2;
                    float m0v = amS[j0], m1v = amS[j0 + 1];
                    float e00 = fexp8(acc[f][0]) * m0v;
                    float e01 = fexp8(acc[f][1]) * m1v;
                    float e10 = fexp8(acc[f][2]) * m0v;
                    float e11 = fexp8(acc[f][3]) * m1v;
                    rs0 += e00 + e01;
                    rs1 += e10 + e11;
                    __half2 p01 = __floats2half2_rn(e00, e01);
                    __half2 p23 = __floats2half2_rn(e10, e11);
                    int w0 = (j0 >> 1);
                    int r0 = m0 + g;
                    Shw[r0 * SHSTR + w0]       = *(uint32_t*)&p01;
                    Shw[(r0 + 8) * SHSTR + w0] = *(uint32_t*)&p23;
                }
            } else {
                #pragma unroll
                for (int f = 0; f < 2; f++) {
                    int j0 = kc0 + warpCol * 16 + f * 8 + tg * 2;
                    float m0v = amS[j0], m1v = amS[j0 + 1];
                    float e00 = (j0     <= qg0) ? fexp8(acc[f][0]) * m0v : 0.f;
                    float e01 = (j0 + 1 <= qg0) ? fexp8(acc[f][1]) * m1v : 0.f;
                    float e10 = (j0     <= qg1) ? fexp8(acc[f][2]) * m0v : 0.f;
                    float e11 = (j0 + 1 <= qg1) ? fexp8(acc[f][3]) * m1v : 0.f;
                    rs0 += e00 + e01;
                    rs1 += e10 + e11;
                    __half2 p01 = __floats2half2_rn(e00, e01);
                    __half2 p23 = __floats2half2_rn(e10, e11);
                    int w0 = (j0 >> 1);
                    int r0 = m0 + g;
                    Shw[r0 * SHSTR + w0]       = *(uint32_t*)&p01;
                    Shw[(r0 + 8) * SHSTR + w0] = *(uint32_t*)&p23;
                }
            }
        }
    }
    rs0 += __shfl_xor_sync(~0u, rs0, 1); rs0 += __shfl_xor_sync(~0u, rs0, 2);
    rs1 += __shfl_xor_sync(~0u, rs1, 1); rs1 += __shfl_xor_sync(~0u, rs1, 2);
    if (tg == 0) {
        part[wid * 17 + g]     = rs0;
        part[wid * 17 + g + 8] = rs1;
    }
    __syncthreads();
    if (tid < 32) {
        int wr = tid >> 4, lr = tid & 15;
        float s = 0.f;
        #pragma unroll
        for (int w = 0; w < 8; w++) s += part[(wr * 8 + w) * 17 + lr];
        invlS[tid] = 1.f / s;
    }
    __syncthreads();

    {
        int rows_here = min(128, jmax);
        for (int idx = tid; idx < rows_here * 8; idx += 512) {
            int r = idx >> 3, cs = idx & 7;
            cp16(KV0 + r * KVSTR + cs * 4, vb + (size_t)r * D_ + cs * 8);
        }
        cp_commit();
    }

    if (2 * tid < kend) {
        float cs0 = 0.f, cs1 = 0.f;
        #pragma unroll
        for (int r = 0; r < QT; r++) {
            uint32_t pw = Shw[r * SHSTR + tid];
            __half2 ph = *(__half2*)&pw;
            float wgt = invlS[r];
            cs0 += __half2float(ph.x) * wgt;
            cs1 += __half2float(ph.y) * wgt;
        }
        atomicAdd(&imp[b * T_ + 2 * tid],     cs0 * (1.f / (H_ * T_)));
        atomicAdd(&imp[b * T_ + 2 * tid + 1], cs1 * (1.f / (H_ * T_)));
    }

    // ---- phase 3 ----
    int col0 = warpCol * 8;
    float acc[4] = {};
    for (int ic = 0; ic < nch; ic++) {
        int kc0 = ic * 128;
        int rows_here = min(128, jmax - kc0);
        cp_wait<0>();
        __syncthreads();
        if (ic + 1 < nch) {
            int nk0 = (ic + 1) * 128;
            int nrows = min(128, jmax - nk0);
            uint32_t* dst = ((ic + 1) & 1) ? KV1 : KV0;
            for (int idx = tid; idx < nrows * 8; idx += 512) {
                int r = idx >> 3, cs = idx & 7;
                cp16(dst + r * KVSTR + cs * 4, vb + (size_t)(nk0 + r) * D_ + cs * 8);
            }
        }
        cp_commit();
        uint32_t kvbase = (ic & 1) ? kvb1 : kvb0;
        int ksteps = rows_here >> 4;
        for (int ks = 0; ks < ksteps; ks++) {
            uint32_t a[4], bb[2];
            ldmx4(a, shbase + offS + (uint32_t)((kc0 + ks * 16) * 2));
            uint32_t addr = kvbase + ((ks * 16 + (lane & 15)) * 72 + col0) * 2;
            ldmx2t(bb[0], bb[1], addr);
            mma_f16(acc, a, bb);
        }
    }
    float sc0 = invlS[m0 + g], sc1 = invlS[m0 + g + 8];
    #pragma unroll
    for (int half = 0; half < 2; half++) {
        int t = q0 + m0 + g + half * 8;
        int d = h * 64 + col0 + tg * 2;
        float s = half ? sc1 : sc0;
        __half2 hv;
        hv.x = __float2half_rn(acc[2 * half] * s);
        hv.y = __float2half_rn(acc[2 * half + 1] * s);
        *(__half2*)&y16[(size_t)(b * T_ + t) * C_ + d] = hv;
    }
}

// ---------------- launch ----------------------------------------------------
typedef CUresult (*EncodeFn)(CUtensorMap*, CUtensorMapDataType, cuuint32_t, void*,
                             const cuuint64_t*, const cuuint64_t*, const cuuint32_t*,
                             const cuuint32_t*, CUtensorMapInterleave, CUtensorMapSwizzle,
                             CUtensorMapL2promotion, CUtensorMapFloatOOBfill);

static void make_map(EncodeFn fn, CUtensorMap* m, void* addr, uint64_t K, uint64_t rows) {
    cuuint64_t dims[2]    = {K, rows};
    cuuint64_t strides[1] = {K * 2};
    cuuint32_t box[2]     = {32, 128};
    cuuint32_t estr[2]    = {1, 1};
    fn(m, CU_TENSOR_MAP_DATA_TYPE_UINT16, 2, addr, dims, strides, box, estr,
       CU_TENSOR_MAP_INTERLEAVE_NONE, CU_TENSOR_MAP_SWIZZLE_64B,
       CU_TENSOR_MAP_L2_PROMOTION_L2_128B, CU_TENSOR_MAP_FLOAT_OOB_FILL_NONE);
}

extern "C" void kernel_launch(void* const* d_in, const int* in_sizes, int n_in,
                              void* d_out, int out_size) {
    const float* x     = (const float*)d_in[0];
    const float* am    = (const float*)d_in[1];
    const float* ln1w  = (const float*)d_in[2];
    const float* ln1b  = (const float*)d_in[3];
    const float* wattn = (const float*)d_in[4];
    const float* battn = (const float*)d_in[5];
    const float* wproj = (const float*)d_in[6];
    const float* bproj = (const float*)d_in[7];
    const float* thr   = (const float*)d_in[8];
    const float* ln2w  = (const float*)d_in[9];
    const float* ln2b  = (const float*)d_in[10];
    const float* wfc   = (const float*)d_in[11];
    const float* bfc   = (const float*)d_in[12];
    const float* wfc2  = (const float*)d_in[13];
    const float* bfc2  = (const float*)d_in[14];

    float* out      = (float*)d_out;
    float* out_x    = out;
    float* out_mask = out + out_size - 1 - M_;
    float* out_loss = out + out_size - 1;

    float *px2, *pimp;
    cudaGetSymbolAddress((void**)&px2,  g_x2);
    cudaGetSymbolAddress((void**)&pimp, g_imp);
    __half *pq16, *pk16, *pv16, *ph16, *py16, *pf16, *pwat, *pwpr, *pwfc, *pwf2;
    cudaGetSymbolAddress((void**)&pq16, g_q16);
    cudaGetSymbolAddress((void**)&pk16, g_k16);
    cudaGetSymbolAddress((void**)&pv16, g_v16);
    cudaGetSymbolAddress((void**)&ph16, g_h16);
    cudaGetSymbolAddress((void**)&py16, g_y16);
    cudaGetSymbolAddress((void**)&pf16, g_f16);
    cudaGetSymbolAddress((void**)&pwat, g_wat);
    cudaGetSymbolAddress((void**)&pwpr, g_wpr);
    cudaGetSymbolAddress((void**)&pwfc, g_wfc);
    cudaGetSymbolAddress((void**)&pwf2, g_wf2);

    static cudaStream_t sB = nullptr;
    static cudaEvent_t evFork = nullptr, evJoinA = nullptr, evJoin = nullptr;
    static CUtensorMap tmA_h, tmA_y, tmA_f, tmB_at, tmB_pr, tmB_fc, tmB_f2;
    static int init_done = 0;
    if (!init_done) {
        cudaFuncSetAttribute(fattn_kernel,
                             cudaFuncAttributeMaxDynamicSharedMemorySize, FA_SMEM);
        cudaFuncSetAttribute(tcgemm_kernel<0>,
                             cudaFuncAttributeMaxDynamicSharedMemorySize, GEMM_SMEM);
        cudaFuncSetAttribute(tcgemm_kernel<1>,
                             cudaFuncAttributeMaxDynamicSharedMemorySize, GEMM_SMEM);
        cudaFuncSetAttribute(tcgemm_kernel<2>,
                             cudaFuncAttributeMaxDynamicSharedMemorySize, GEMM_SMEM);
        cudaFuncSetAttribute(tcgemm_kernel<3>,
                             cudaFuncAttributeMaxDynamicSharedMemorySize, GEMM_SMEM);
        cudaStreamCreateWithFlags(&sB, cudaStreamNonBlocking);
        cudaEventCreateWithFlags(&evFork, cudaEventDisableTiming);
        cudaEventCreateWithFlags(&evJoinA, cudaEventDisableTiming);
        cudaEventCreateWithFlags(&evJoin, cudaEventDisableTiming);

        EncodeFn fn = nullptr;
        cudaDriverEntryPointQueryResult qres;
        cudaGetDriverEntryPoint("cuTensorMapEncodeTiled", (void**)&fn,
                                cudaEnableDefault, &qres);
        make_map(fn, &tmA_h,  ph16, 1024, 4096);
        make_map(fn, &tmA_y,  py16, 1024, 4096);
        make_map(fn, &tmA_f,  pf16, 4096, 4096);
        make_map(fn, &tmB_at, pwat, 1024, 3072);
        make_map(fn, &tmB_pr, pwpr, 1024, 1024);
        make_map(fn, &tmB_fc, pwfc, 1024, 4096);
        make_map(fn, &tmB_f2, pwf2, 4096, 1024);
        init_done = 1;
    }

    // fork: side stream runs prepA (qkv weights) then prepB (later weights)
    cudaEventRecord(evFork, 0);
    cudaStreamWaitEvent(sB, evFork, 0);
    prepA_kernel<<<3072, 256, 0, sB>>>(wattn, pwat, pimp);
    cudaEventRecord(evJoinA, sB);
    prepB_kernel<<<9216, 256, 0, sB>>>(wproj, pwpr, wfc, pwfc, wfc2, pwf2);
    cudaEventRecord(evJoin, sB);

    // main: LN1 runs concurrently with prepA
    ln_kernel<<<M_, 256>>>(x, ln1w, ln1b, ph16);
    cudaStreamWaitEvent(0, evJoinA, 0);
    tcgemm_kernel<0><<<dim3(NQKV/128, M_/128), 256, GEMM_SMEM>>>(
        tmA_h, tmB_at, battn, nullptr, nullptr, nullptr, M_, NQKV, C_,
        nullptr, nullptr, nullptr, nullptr);
    fattn_kernel<<<dim3(T_/QT, B_*H_), 512, FA_SMEM>>>(pq16, pk16, pv16, am, py16, pimp);

    cudaStreamWaitEvent(0, evJoin, 0);
    tcgemm_kernel<1><<<dim3(C_/128, M_/128), 256, GEMM_SMEM>>>(
        tmA_y, tmB_pr, bproj, x, pimp, px2, M_, C_, C_,
        am, thr, out_mask, out_loss);
    ln_kernel<<<M_, 256>>>(px2, ln2w, ln2b, ph16);
    tcgemm_kernel<2><<<dim3(NFC/128, M_/128), 256, GEMM_SMEM>>>(
        tmA_h, tmB_fc, bfc, nullptr, nullptr, nullptr, M_, NFC, C_,
        nullptr, nullptr, nullptr, nullptr);
    tcgemm_kernel<3><<<dim3(C_/128, M_/128), 256, GEMM_SMEM>>>(
        tmA_f, tmB_f2, bfc2, px2, nullptr, out_x, M_, C_, NFC,
        nullptr, nullptr, nullptr, nullptr);
}